// round 9
// baseline (speedup 1.0000x reference)
#include <cuda_runtime.h>
#include <math.h>
#include <cstdint>

#define NA 20000
#define NP 50000
#define EMAX 300000
#define DD 256
#define NH 8
#define DKH 32

// k-permutation within each 8-group: stored order [k0,k4,k1,k5,k2,k6,k3,k7]
__device__ __forceinline__ int kperm(int k) {
    return (k & ~7) | (((k & 3) << 1) | ((k >> 2) & 1));
}

// ---------------- scratch ----------------
__device__ float g_Har[NA * DD];
__device__ float g_Hpr[NP * DD];
__device__ float g_K0[NA * DD];
__device__ float g_V0[NA * DD];
__device__ float g_Qa[NA * DD];
__device__ float g_Kp[NP * DD];
__device__ float g_Vp[NP * DD];
__device__ float g_Qp[NP * DD];
__device__ float g_Qpc[NP * DD];
__device__ float g_aggPw[NP * DD];
__device__ float g_aggPc[NP * DD];
__device__ float g_aggP[NP * DD];
__device__ float g_aggAc[NA * DD];
__device__ float g_aggA[NA * DD];
__device__ float g_fW[3 * DD * DD];
__device__ float g_fB[3 * DD];
__device__ float g_rw[5 * DD * DD];
__device__ int g_deg0[NP];
__device__ int g_deg1[NP];
__device__ int g_deg2[NA];
__device__ int g_rp0[NP + 1];
__device__ int g_rp1[NP + 1];
__device__ int g_rp2[NA + 1];
__device__ int g_cur0[NP];
__device__ int g_cur1[NP];
__device__ int g_cur2[NA];
__device__ int g_col0[EMAX];
__device__ int g_col1[EMAX];
__device__ int g_col2[EMAX];

__device__ __forceinline__ float tf32r(float v) {
    uint32_t r;
    asm("cvt.rna.tf32.f32 %0, %1;" : "=r"(r) : "f"(v));
    return __uint_as_float(r);
}

// ---------------- round + k-permute copy (8 floats per thread) ----------------
__global__ void roundcopy8(const float* __restrict__ in, float* __restrict__ out, int n8) {
    int i = blockIdx.x * blockDim.x + threadIdx.x;
    if (i < n8) {
        const float4* ip = (const float4*)(in + (size_t)i * 8);
        float4 v0 = ip[0], v1 = ip[1];
        float4 o0 = make_float4(tf32r(v0.x), tf32r(v1.x), tf32r(v0.y), tf32r(v1.y));
        float4 o1 = make_float4(tf32r(v0.z), tf32r(v1.z), tf32r(v0.w), tf32r(v1.w));
        float4* op = (float4*)(out + (size_t)i * 8);
        op[0] = o0; op[1] = o1;
    }
}

// ---------------- weight folds (store k-permuted rows) ----------------
__global__ void fold_k(const float* __restrict__ W, const float* __restrict__ rel,
                       const float* __restrict__ b,
                       float* __restrict__ Wout, float* __restrict__ bout) {
    int c = blockIdx.x, d = threadIdx.x;
    int h = c >> 5, j = c & 31;
    float s = 0.f;
#pragma unroll
    for (int i = 0; i < 32; i++)
        s += rel[(h * 32 + i) * 32 + j] * W[(h * 32 + i) * DD + d];
    Wout[c * DD + kperm(d)] = tf32r(s);
    if (d == 0) {
        float sb = 0.f;
#pragma unroll
        for (int i = 0; i < 32; i++)
            sb += rel[(h * 32 + i) * 32 + j] * b[h * 32 + i];
        bout[c] = sb;
    }
}

__global__ void fold_q(const float* __restrict__ W, const float* __restrict__ rel,
                       const float* __restrict__ b,
                       float* __restrict__ Wout, float* __restrict__ bout) {
    int c = blockIdx.x, d = threadIdx.x;
    int h = c >> 5, i = c & 31;
    float s = 0.f;
#pragma unroll
    for (int j = 0; j < 32; j++)
        s += rel[(h * 32 + i) * 32 + j] * W[(h * 32 + j) * DD + d];
    Wout[c * DD + kperm(d)] = tf32r(s);
    if (d == 0) {
        float sb = 0.f;
#pragma unroll
        for (int j = 0; j < 32; j++)
            sb += rel[(h * 32 + i) * 32 + j] * b[h * 32 + j];
        bout[c] = sb;
    }
}

// ---------------- block-diagonal per-head transform ----------------
// roundit=1 also applies the k-permute on the store (output feeds a GEMM A).
__global__ void bdtrans(const float* __restrict__ in, const float* __restrict__ base,
                        const float* __restrict__ R, float* __restrict__ out,
                        int N, int transp, int roundit) {
    __shared__ float Rs[32 * 33];
    __shared__ float As[64 * 33];
    const int h = blockIdx.y;
    const int n0 = blockIdx.x * 64;
    const int t = threadIdx.x;
#pragma unroll
    for (int k = 0; k < 4; k++) {
        int idx = t * 4 + k;
        int i0 = idx >> 5, j0 = idx & 31;
        float v = R[h * 1024 + idx];
        if (transp) Rs[i0 * 33 + j0] = v;
        else        Rs[j0 * 33 + i0] = v;
    }
    const int rows = (N - n0 < 64) ? (N - n0) : 64;
#pragma unroll
    for (int it = 0; it < 8; it++) {
        int r = (t >> 5) + it * 8;
        int j = t & 31;
        if (r < rows) As[r * 33 + j] = in[(size_t)(n0 + r) * DD + h * 32 + j];
    }
    __syncthreads();
    const int i = t & 31;
#pragma unroll
    for (int it = 0; it < 8; it++) {
        int r = (t >> 5) + it * 8;
        if (r >= rows) break;
        float v = 0.f;
#pragma unroll
        for (int j = 0; j < 32; j++) v += As[r * 33 + j] * Rs[j * 33 + i];
        int col = h * 32 + i;
        if (base) v += base[(size_t)(n0 + r) * DD + col];
        if (roundit)
            out[(size_t)(n0 + r) * DD + kperm(col)] = tf32r(v);
        else
            out[(size_t)(n0 + r) * DD + col] = v;
    }
}

// ---------------- tf32 mma GEMM, LDS.64 fragments, pitch 40 ----------------
#define SLAB_F (128 * 40)
#define GSMEM (4 * SLAB_F * 4)
#define GS3 (8 * SLAB_F * 4)

__device__ __forceinline__ void mma1688(float c[4], uint32_t a0, uint32_t a1, uint32_t a2,
                                        uint32_t a3, uint32_t b0, uint32_t b1) {
    asm volatile(
        "mma.sync.aligned.m16n8k8.row.col.f32.tf32.tf32.f32 "
        "{%0,%1,%2,%3}, {%4,%5,%6,%7}, {%8,%9}, {%0,%1,%2,%3};"
        : "+f"(c[0]), "+f"(c[1]), "+f"(c[2]), "+f"(c[3])
        : "r"(a0), "r"(a1), "r"(a2), "r"(a3), "r"(b0), "r"(b1));
}

__global__ __launch_bounds__(256) void gemm_mma(
    const float* __restrict__ A, const float* __restrict__ B,
    const float* __restrict__ bias, const float* __restrict__ resid,
    const float* __restrict__ skipv, int nid,
    float* __restrict__ C, int M) {
    extern __shared__ float sm[];
    const int tid = threadIdx.x;
    const int m0 = blockIdx.x * 128;
    const int col0 = blockIdx.y * 128;
    const int w = tid >> 5, ln = tid & 31;
    const int rowb = (w >> 2) * 64, colb = (w & 3) * 32;
    const int lg = ln >> 2, lt = ln & 3;

    float* const Ab[2] = {sm, sm + SLAB_F};
    float* const Bb[2] = {sm + 2 * SLAB_F, sm + 3 * SLAB_F};

    float c[4][4][4];
#pragma unroll
    for (int mi = 0; mi < 4; mi++)
#pragma unroll
        for (int ni = 0; ni < 4; ni++)
#pragma unroll
            for (int r = 0; r < 4; r++) c[mi][ni][r] = 0.f;

    auto load_slab = [&](int s, int b) {
        const int k0 = s * 32;
        float* As = Ab[b];
        float* Bs = Bb[b];
#pragma unroll
        for (int i = 0; i < 4; i++) {
            int idx = tid + i * 256;
            int row = idx >> 3, kg = idx & 7;
            uint32_t da = (uint32_t)__cvta_generic_to_shared(As + row * 40 + kg * 4);
            const float* ga = A + (size_t)(m0 + row) * DD + k0 + kg * 4;
            int sz = ((m0 + row) < M) ? 16 : 0;
            asm volatile("cp.async.cg.shared.global [%0], [%1], 16, %2;\n" ::"r"(da), "l"(ga), "r"(sz));
            uint32_t db = (uint32_t)__cvta_generic_to_shared(Bs + row * 40 + kg * 4);
            const float* gb = B + (size_t)(col0 + row) * DD + k0 + kg * 4;
            asm volatile("cp.async.cg.shared.global [%0], [%1], 16;\n" ::"r"(db), "l"(gb));
        }
        asm volatile("cp.async.commit_group;\n");
    };

    load_slab(0, 0);
    for (int s = 0; s < 8; s++) {
        int b = s & 1;
        if (s < 7) {
            load_slab(s + 1, b ^ 1);
            asm volatile("cp.async.wait_group 1;\n");
        } else {
            asm volatile("cp.async.wait_group 0;\n");
        }
        __syncthreads();
        const float* As = Ab[b];
        const float* Bs = Bb[b];
#pragma unroll
        for (int ks = 0; ks < 4; ks++) {
            const int ko = ks * 8 + lt * 2;
            float2 a02[4], a13[4], bp[4];
#pragma unroll
            for (int mi = 0; mi < 4; mi++) {
                const float* p = As + (rowb + mi * 16 + lg) * 40 + ko;
                a02[mi] = *(const float2*)p;
                a13[mi] = *(const float2*)(p + 8 * 40);
            }
#pragma unroll
            for (int ni = 0; ni < 4; ni++)
                bp[ni] = *(const float2*)(Bs + (colb + ni * 8 + lg) * 40 + ko);
#pragma unroll
            for (int mi = 0; mi < 4; mi++)
#pragma unroll
                for (int ni = 0; ni < 4; ni++)
                    mma1688(c[mi][ni], __float_as_uint(a02[mi].x), __float_as_uint(a13[mi].x),
                            __float_as_uint(a02[mi].y), __float_as_uint(a13[mi].y),
                            __float_as_uint(bp[ni].x), __float_as_uint(bp[ni].y));
        }
        __syncthreads();
    }

    float alpha = 1.f, beta = 0.f;
    if (resid) {
        float sv = skipv[nid];
        alpha = 1.f / (1.f + __expf(-sv));
        beta = 1.f - alpha;
    }
#pragma unroll
    for (int mi = 0; mi < 4; mi++) {
#pragma unroll
        for (int half = 0; half < 2; half++) {
            int row = m0 + rowb + mi * 16 + lg + half * 8;
            if (row >= M) continue;
#pragma unroll
            for (int ni = 0; ni < 4; ni++) {
                int cc = col0 + colb + ni * 8 + lt * 2;
                float2 o;
                o.x = c[mi][ni][half * 2 + 0] + bias[cc];
                o.y = c[mi][ni][half * 2 + 1] + bias[cc + 1];
                if (resid) {
                    float2 rv = *(const float2*)(resid + (size_t)row * DD + cc);
                    o.x = o.x * alpha + rv.x * beta;
                    o.y = o.y * alpha + rv.y * beta;
                }
                *(float2*)(C + (size_t)row * DD + cc) = o;
            }
        }
    }
}

// ---------------- fused 3-B projection GEMM ----------------
__global__ __launch_bounds__(256, 1) void gemm3(
    const float* __restrict__ A,
    const float* __restrict__ B0, const float* __restrict__ B1, const float* __restrict__ B2,
    const float* __restrict__ bi0, const float* __restrict__ bi1, const float* __restrict__ bi2,
    float* __restrict__ C0, float* __restrict__ C1, float* __restrict__ C2, int M) {
    extern __shared__ float sm[];
    const int tid = threadIdx.x;
    const int m0 = blockIdx.x * 128;
    const int col0 = blockIdx.y * 128;
    const int w = tid >> 5, ln = tid & 31;
    const int rowb = (w >> 2) * 64, colb = (w & 3) * 32;
    const int lg = ln >> 2, lt = ln & 3;

    const float* const Bv[3] = {B0, B1, B2};
    const float* const biv[3] = {bi0, bi1, bi2};
    float* const Cv[3] = {C0, C1, C2};

    float c[3][4][4][4];
#pragma unroll
    for (int b = 0; b < 3; b++)
#pragma unroll
        for (int mi = 0; mi < 4; mi++)
#pragma unroll
            for (int ni = 0; ni < 4; ni++)
#pragma unroll
                for (int r = 0; r < 4; r++) c[b][mi][ni][r] = 0.f;

    auto load_slab = [&](int s, int buf) {
        const int k0 = s * 32;
        float* As = sm + buf * SLAB_F;
#pragma unroll
        for (int i = 0; i < 4; i++) {
            int idx = tid + i * 256;
            int row = idx >> 3, kg = idx & 7;
            uint32_t da = (uint32_t)__cvta_generic_to_shared(As + row * 40 + kg * 4);
            const float* ga = A + (size_t)(m0 + row) * DD + k0 + kg * 4;
            int sz = ((m0 + row) < M) ? 16 : 0;
            asm volatile("cp.async.cg.shared.global [%0], [%1], 16, %2;\n" ::"r"(da), "l"(ga), "r"(sz));
        }
#pragma unroll
        for (int b = 0; b < 3; b++) {
            float* Bs = sm + (2 + b * 2 + buf) * SLAB_F;
#pragma unroll
            for (int i = 0; i < 4; i++) {
                int idx = tid + i * 256;
                int row = idx >> 3, kg = idx & 7;
                uint32_t db = (uint32_t)__cvta_generic_to_shared(Bs + row * 40 + kg * 4);
                const float* gb = Bv[b] + (size_t)(col0 + row) * DD + k0 + kg * 4;
                asm volatile("cp.async.cg.shared.global [%0], [%1], 16;\n" ::"r"(db), "l"(gb));
            }
        }
        asm volatile("cp.async.commit_group;\n");
    };

    load_slab(0, 0);
    for (int s = 0; s < 8; s++) {
        int buf = s & 1;
        if (s < 7) {
            load_slab(s + 1, buf ^ 1);
            asm volatile("cp.async.wait_group 1;\n");
        } else {
            asm volatile("cp.async.wait_group 0;\n");
        }
        __syncthreads();
        const float* As = sm + buf * SLAB_F;
#pragma unroll
        for (int ks = 0; ks < 4; ks++) {
            const int ko = ks * 8 + lt * 2;
            float2 a02[4], a13[4];
#pragma unroll
            for (int mi = 0; mi < 4; mi++) {
                const float* p = As + (rowb + mi * 16 + lg) * 40 + ko;
                a02[mi] = *(const float2*)p;
                a13[mi] = *(const float2*)(p + 8 * 40);
            }
#pragma unroll
            for (int b = 0; b < 3; b++) {
                const float* Bs = sm + (2 + b * 2 + buf) * SLAB_F;
                float2 bp[4];
#pragma unroll
                for (int ni = 0; ni < 4; ni++)
                    bp[ni] = *(const float2*)(Bs + (colb + ni * 8 + lg) * 40 + ko);
#pragma unroll
                for (int mi = 0; mi < 4; mi++)
#pragma unroll
                    for (int ni = 0; ni < 4; ni++)
                        mma1688(c[b][mi][ni], __float_as_uint(a02[mi].x), __float_as_uint(a13[mi].x),
                                __float_as_uint(a02[mi].y), __float_as_uint(a13[mi].y),
                                __float_as_uint(bp[ni].x), __float_as_uint(bp[ni].y));
            }
        }
        __syncthreads();
    }

#pragma unroll
    for (int b = 0; b < 3; b++) {
#pragma unroll
        for (int mi = 0; mi < 4; mi++) {
#pragma unroll
            for (int half = 0; half < 2; half++) {
                int row = m0 + rowb + mi * 16 + lg + half * 8;
                if (row >= M) continue;
#pragma unroll
                for (int ni = 0; ni < 4; ni++) {
                    int cc = col0 + colb + ni * 8 + lt * 2;
                    float2 o;
                    o.x = c[b][mi][ni][half * 2 + 0] + biv[b][cc];
                    o.y = c[b][mi][ni][half * 2 + 1] + biv[b][cc + 1];
                    *(float2*)(Cv[b] + (size_t)row * DD + cc) = o;
                }
            }
        }
    }
}

// ---------------- CSR build ----------------
__global__ void zero3(int* d0, int* d1, int* d2) {
    int i = blockIdx.x * blockDim.x + threadIdx.x;
    if (i < NP) { d0[i] = 0; d1[i] = 0; }
    if (i < NA) d2[i] = 0;
}

__global__ void hist3(const int* __restrict__ dw, const int* __restrict__ dc,
                      const int* __restrict__ db, int E,
                      int* d0, int* d1, int* d2) {
    int i = blockIdx.x * blockDim.x + threadIdx.x;
    if (i < E) atomicAdd(&d0[dw[i]], 1);
    else if (i < 2 * E) atomicAdd(&d1[dc[i - E]], 1);
    else if (i < 3 * E) atomicAdd(&d2[db[i - 2 * E]], 1);
}

__global__ void scan3(const int* __restrict__ deg0, const int* __restrict__ deg1,
                      const int* __restrict__ deg2,
                      int* rp0, int* rp1, int* rp2, int* c0, int* c1, int* c2) {
    __shared__ int sh[1024];
    __shared__ int carry_s;
    const int* deg; int* rp; int* cur; int n;
    if (blockIdx.x == 0) { deg = deg0; rp = rp0; cur = c0; n = NP; }
    else if (blockIdx.x == 1) { deg = deg1; rp = rp1; cur = c1; n = NP; }
    else { deg = deg2; rp = rp2; cur = c2; n = NA; }
    int tid = threadIdx.x;
    if (tid == 0) carry_s = 0;
    __syncthreads();
    for (int base = 0; base < n; base += 1024) {
        int i = base + tid;
        int v = (i < n) ? deg[i] : 0;
        sh[tid] = v;
        __syncthreads();
        for (int off = 1; off < 1024; off <<= 1) {
            int t = (tid >= off) ? sh[tid - off] : 0;
            __syncthreads();
            sh[tid] += t;
            __syncthreads();
        }
        int incl = sh[tid] + carry_s;
        if (i < n) { rp[i + 1] = incl; cur[i] = incl - v; }
        __syncthreads();
        if (tid == 1023) carry_s = incl;
        __syncthreads();
    }
    if (tid == 0) rp[0] = 0;
}

__global__ void scatter3(const int* __restrict__ sw, const int* __restrict__ dw,
                         const int* __restrict__ sc, const int* __restrict__ dc,
                         const int* __restrict__ sb, const int* __restrict__ db, int E,
                         int* c0, int* c1, int* c2,
                         int* col0, int* col1, int* col2) {
    int i = blockIdx.x * blockDim.x + threadIdx.x;
    if (i < E) { int p = atomicAdd(&c0[dw[i]], 1); col0[p] = sw[i]; }
    else if (i < 2 * E) { int j = i - E; int p = atomicAdd(&c1[dc[j]], 1); col1[p] = sc[j]; }
    else if (i < 3 * E) { int j = i - 2 * E; int p = atomicAdd(&c2[db[j]], 1); col2[p] = sb[j]; }
}

// ---------------- aggregation (R8-proven) ----------------
__device__ __forceinline__ void csr_attend8(
    int node, int lane, const int* __restrict__ rp, const int* __restrict__ colv,
    const float* __restrict__ K, const float* __restrict__ V,
    const float4 qa, const float4 qb, const float prih, float acc[8]) {
    float s = 0.f;
    float a[8];
#pragma unroll
    for (int j = 0; j < 8; j++) a[j] = 0.f;
    const int off = (lane >> 2) * DKH + (lane & 3) * 8;
    const int beg = rp[node], end = rp[node + 1];
    for (int e = beg; e < end; e++) {
        const int src = colv[e];
        const float* kr = K + (size_t)src * DD + off;
        float4 k0 = *(const float4*)kr;
        float4 k1 = *(const float4*)(kr + 4);
        float p = qa.x * k0.x + qa.y * k0.y + qa.z * k0.z + qa.w * k0.w +
                  qb.x * k1.x + qb.y * k1.y + qb.z * k1.z + qb.w * k1.w;
        p += __shfl_xor_sync(0xffffffffu, p, 1);
        p += __shfl_xor_sync(0xffffffffu, p, 2);
        float wgt = __expf(p * prih);
        const float* vr = V + (size_t)src * DD + off;
        float4 v0 = *(const float4*)vr;
        float4 v1 = *(const float4*)(vr + 4);
        s += wgt;
        a[0] += wgt * v0.x; a[1] += wgt * v0.y; a[2] += wgt * v0.z; a[3] += wgt * v0.w;
        a[4] += wgt * v1.x; a[5] += wgt * v1.y; a[6] += wgt * v1.z; a[7] += wgt * v1.w;
    }
    if (s > 0.f) {
        float inv = 1.f / s;
#pragma unroll
        for (int j = 0; j < 8; j++) acc[j] += a[j] * inv;
    }
}

__global__ void agg_paper_kernel(const float* __restrict__ Qp, const float* __restrict__ Qpc,
                                 const float* __restrict__ K0, const float* __restrict__ V0,
                                 const float* __restrict__ Kp, const float* __restrict__ Vp,
                                 const int* __restrict__ rp0, const int* __restrict__ col0,
                                 const int* __restrict__ rp1, const int* __restrict__ col1,
                                 const float* __restrict__ rel_pri,
                                 float* __restrict__ aggw, float* __restrict__ aggc) {
    int w = (blockIdx.x * blockDim.x + threadIdx.x) >> 5;
    int lane = threadIdx.x & 31;
    if (w >= NP) return;
    const float sc = 0.17677669529663687f;
    const int h = lane >> 2;
    const int off = h * DKH + (lane & 3) * 8;
    const size_t qoff = (size_t)w * DD + off;
    {
        float4 qa = *(const float4*)(Qp + qoff);
        float4 qb = *(const float4*)(Qp + qoff + 4);
        float acc[8];
#pragma unroll
        for (int j = 0; j < 8; j++) acc[j] = 0.f;
        csr_attend8(w, lane, rp0, col0, K0, V0, qa, qb, rel_pri[h] * sc, acc);
        float* o = aggw + qoff;
        *(float4*)o = make_float4(acc[0], acc[1], acc[2], acc[3]);
        *(float4*)(o + 4) = make_float4(acc[4], acc[5], acc[6], acc[7]);
    }
    {
        float4 qa = *(const float4*)(Qpc + qoff);
        float4 qb = *(const float4*)(Qpc + qoff + 4);
        float acc[8];
#pragma unroll
        for (int j = 0; j < 8; j++) acc[j] = 0.f;
        csr_attend8(w, lane, rp1, col1, Kp, Vp, qa, qb, rel_pri[NH + h] * sc, acc);
        float* o = aggc + qoff;
        *(float4*)o = make_float4(acc[0], acc[1], acc[2], acc[3]);
        *(float4*)(o + 4) = make_float4(acc[4], acc[5], acc[6], acc[7]);
    }
}

__global__ void agg_author_kernel(const float* __restrict__ Qa,
                                  const float* __restrict__ Kp, const float* __restrict__ Vp,
                                  const int* __restrict__ rp2, const int* __restrict__ col2,
                                  const float* __restrict__ rel_pri,
                                  float* __restrict__ agg) {
    int w = (blockIdx.x * blockDim.x + threadIdx.x) >> 5;
    int lane = threadIdx.x & 31;
    if (w >= NA) return;
    const float sc = 0.17677669529663687f;
    const int h = lane >> 2;
    const int off = h * DKH + (lane & 3) * 8;
    const size_t qoff = (size_t)w * DD + off;
    float4 qa = *(const float4*)(Qa + qoff);
    float4 qb = *(const float4*)(Qa + qoff + 4);
    float acc[8];
#pragma unroll
    for (int j = 0; j < 8; j++) acc[j] = 0.f;
    csr_attend8(w, lane, rp2, col2, Kp, Vp, qa, qb, rel_pri[2 * NH + h] * sc, acc);
    float* o = agg + qoff;
    *(float4*)o = make_float4(acc[0], acc[1], acc[2], acc[3]);
    *(float4*)(o + 4) = make_float4(acc[4], acc[5], acc[6], acc[7]);
}

// ---------------- host launch ----------------
extern "C" void kernel_launch(void* const* d_in, const int* in_sizes, int n_in,
                              void* d_out, int out_size) {
    const float* h_author = (const float*)d_in[0];
    const float* h_paper  = (const float*)d_in[1];
    const float* k_w  = (const float*)d_in[2];
    const float* k_b  = (const float*)d_in[3];
    const float* q_w  = (const float*)d_in[4];
    const float* q_b  = (const float*)d_in[5];
    const float* v_w  = (const float*)d_in[6];
    const float* v_b  = (const float*)d_in[7];
    const float* a_w  = (const float*)d_in[8];
    const float* a_b  = (const float*)d_in[9];
    const float* rel_att = (const float*)d_in[10];
    const float* rel_msg = (const float*)d_in[11];
    const float* rel_pri = (const float*)d_in[12];
    const float* skipv   = (const float*)d_in[13];
    const int* src_writes = (const int*)d_in[14];
    const int* dst_writes = (const int*)d_in[15];
    const int* src_cites  = (const int*)d_in[16];
    const int* dst_cites  = (const int*)d_in[17];
    const int* src_wb     = (const int*)d_in[18];
    const int* dst_wb     = (const int*)d_in[19];

    int E = in_sizes[14];
    if (E > EMAX) E = EMAX;

    float *Har, *Hpr, *K0, *V0, *Qa, *Kp, *Vp, *Qp, *Qpc;
    float *aggPw, *aggPc, *aggP, *aggAc, *aggA, *fW, *fB, *rw;
    int *deg0, *deg1, *deg2, *rp0, *rp1, *rp2, *cur0, *cur1, *cur2, *col0, *col1, *col2;
    cudaGetSymbolAddress((void**)&Har, g_Har);
    cudaGetSymbolAddress((void**)&Hpr, g_Hpr);
    cudaGetSymbolAddress((void**)&K0, g_K0);
    cudaGetSymbolAddress((void**)&V0, g_V0);
    cudaGetSymbolAddress((void**)&Qa, g_Qa);
    cudaGetSymbolAddress((void**)&Kp, g_Kp);
    cudaGetSymbolAddress((void**)&Vp, g_Vp);
    cudaGetSymbolAddress((void**)&Qp, g_Qp);
    cudaGetSymbolAddress((void**)&Qpc, g_Qpc);
    cudaGetSymbolAddress((void**)&aggPw, g_aggPw);
    cudaGetSymbolAddress((void**)&aggPc, g_aggPc);
    cudaGetSymbolAddress((void**)&aggP, g_aggP);
    cudaGetSymbolAddress((void**)&aggAc, g_aggAc);
    cudaGetSymbolAddress((void**)&aggA, g_aggA);
    cudaGetSymbolAddress((void**)&fW, g_fW);
    cudaGetSymbolAddress((void**)&fB, g_fB);
    cudaGetSymbolAddress((void**)&rw, g_rw);
    cudaGetSymbolAddress((void**)&deg0, g_deg0);
    cudaGetSymbolAddress((void**)&deg1, g_deg1);
    cudaGetSymbolAddress((void**)&deg2, g_deg2);
    cudaGetSymbolAddress((void**)&rp0, g_rp0);
    cudaGetSymbolAddress((void**)&rp1, g_rp1);
    cudaGetSymbolAddress((void**)&rp2, g_rp2);
    cudaGetSymbolAddress((void**)&cur0, g_cur0);
    cudaGetSymbolAddress((void**)&cur1, g_cur1);
    cudaGetSymbolAddress((void**)&cur2, g_cur2);
    cudaGetSymbolAddress((void**)&col0, g_col0);
    cudaGetSymbolAddress((void**)&col1, g_col1);
    cudaGetSymbolAddress((void**)&col2, g_col2);

    cudaFuncSetAttribute(gemm_mma, cudaFuncAttributeMaxDynamicSharedMemorySize, GSMEM);
    cudaFuncSetAttribute(gemm3, cudaFuncAttributeMaxDynamicSharedMemorySize, GS3);

    float* kwr1 = rw + 0 * 65536;
    float* vwr1 = rw + 1 * 65536;
    float* qwr1 = rw + 2 * 65536;
    float* awr  = rw + 3 * 65536;
    float* fWk0 = fW + 0 * 65536;
    float* fWv0 = fW + 1 * 65536;
    float* fWqa = fW + 2 * 65536;
    float* fBk0 = fB + 0 * 256;
    float* fBv0 = fB + 1 * 256;
    float* fBqa = fB + 2 * 256;

    // 1) pre-round + k-permute GEMM inputs
    roundcopy8<<<(NA * DD / 8 + 255) / 256, 256>>>(h_author, Har, NA * DD / 8);
    roundcopy8<<<(NP * DD / 8 + 255) / 256, 256>>>(h_paper, Hpr, NP * DD / 8);
    roundcopy8<<<(65536 / 8 + 255) / 256, 256>>>(k_w + 65536, kwr1, 65536 / 8);
    roundcopy8<<<(65536 / 8 + 255) / 256, 256>>>(v_w + 65536, vwr1, 65536 / 8);
    roundcopy8<<<(65536 / 8 + 255) / 256, 256>>>(q_w + 65536, qwr1, 65536 / 8);
    roundcopy8<<<(131072 / 8 + 255) / 256, 256>>>(a_w, awr, 131072 / 8);

    // 2) weight folds (permuted stores)
    fold_k<<<256, 256>>>(k_w, rel_att, k_b, fWk0, fBk0);
    fold_k<<<256, 256>>>(v_w, rel_msg, v_b, fWv0, fBv0);
    fold_q<<<256, 256>>>(q_w, rel_att + 2 * 8192, q_b, fWqa, fBqa);

    // 3) projection GEMMs
    {
        dim3 ga((NA + 127) / 128, 2), gp((NP + 127) / 128, 2);
        gemm3<<<ga, 256, GS3>>>(Har, fWk0, fWv0, fWqa, fBk0, fBv0, fBqa, K0, V0, Qa, NA);
        gemm3<<<gp, 256, GS3>>>(Hpr, kwr1, vwr1, qwr1, k_b + 256, v_b + 256, q_b + 256,
                                Kp, Vp, Qp, NP);
    }

    // 4) Q transform for cites (unpermuted output — feeds agg, not a GEMM)
    {
        dim3 g((NP + 63) / 64, NH);
        bdtrans<<<g, 256>>>(Qp, nullptr, rel_att + 8192, Qpc, NP, 0, 0);
    }

    // 5) CSR builds
    zero3<<<(NP + 255) / 256, 256>>>(deg0, deg1, deg2);
    hist3<<<(3 * E + 255) / 256, 256>>>(dst_writes, dst_cites, dst_wb, E, deg0, deg1, deg2);
    scan3<<<3, 1024>>>(deg0, deg1, deg2, rp0, rp1, rp2, cur0, cur1, cur2);
    scatter3<<<(3 * E + 255) / 256, 256>>>(src_writes, dst_writes, src_cites, dst_cites,
                                           src_wb, dst_wb, E, cur0, cur1, cur2, col0, col1, col2);

    // 6) attention aggregation
    agg_paper_kernel<<<(NP * 32 + 255) / 256, 256>>>(Qp, Qpc, K0, V0, Kp, Vp,
                                                     rp0, col0, rp1, col1, rel_pri, aggPw, aggPc);
    agg_author_kernel<<<(NA * 32 + 255) / 256, 256>>>(Qa, Kp, Vp, rp2, col2, rel_pri, aggAc);

    // 7) post-agg message transforms (roundit=1 → permuted for out-GEMM)
    {
        dim3 gp((NP + 63) / 64, NH), ga((NA + 63) / 64, NH);
        bdtrans<<<gp, 256>>>(aggPc, aggPw, rel_msg + 8192, aggP, NP, 1, 1);
        bdtrans<<<ga, 256>>>(aggAc, nullptr, rel_msg + 2 * 8192, aggA, NA, 1, 1);
    }

    // 8) output GEMMs
    float* out = (float*)d_out;
    {
        dim3 ga((NA + 127) / 128, 2), gp((NP + 127) / 128, 2);
        gemm_mma<<<ga, 256, GSMEM>>>(aggA, awr, a_b, h_author, skipv, 0, out, NA);
        gemm_mma<<<gp, 256, GSMEM>>>(aggP, awr + 65536, a_b + 256, h_paper, skipv, 1,
                                     out + (size_t)NA * DD, NP);
    }
}

// round 10
// speedup vs baseline: 1.1275x; 1.1275x over previous
#include <cuda_runtime.h>
#include <math.h>
#include <cstdint>

#define NA 20000
#define NP 50000
#define EMAX 300000
#define DD 256
#define NH 8
#define DKH 32

// ---------------- scratch ----------------
__device__ float g_Har[NA * DD];
__device__ float g_Hpr[NP * DD];
__device__ float g_K0[NA * DD];
__device__ float g_V0[NA * DD];
__device__ float g_Qa[NA * DD];
__device__ float g_Kp[NP * DD];
__device__ float g_Vp[NP * DD];
__device__ float g_Qp[NP * DD];
__device__ float g_Qpc[NP * DD];
__device__ float g_aggPw[NP * DD];
__device__ float g_aggPc[NP * DD];
__device__ float g_aggP[NP * DD];
__device__ float g_aggAc[NA * DD];
__device__ float g_aggA[NA * DD];
__device__ float g_fW[3 * DD * DD];
__device__ float g_fB[3 * DD];
__device__ float g_rw[5 * DD * DD];
__device__ int g_deg0[NP];
__device__ int g_deg1[NP];
__device__ int g_deg2[NA];
__device__ int g_rp0[NP + 1];
__device__ int g_rp1[NP + 1];
__device__ int g_rp2[NA + 1];
__device__ int g_cur0[NP];
__device__ int g_cur1[NP];
__device__ int g_cur2[NA];
__device__ int g_col0[EMAX];
__device__ int g_col1[EMAX];
__device__ int g_col2[EMAX];

__device__ __forceinline__ float tf32r(float v) {
    uint32_t r;
    asm("cvt.rna.tf32.f32 %0, %1;" : "=r"(r) : "f"(v));
    return __uint_as_float(r);
}

// ---------------- fused round-copy over 6 regions ----------------
__global__ void roundcopy_all(
    const float* __restrict__ s0, float* __restrict__ d0, int n0,
    const float* __restrict__ s1, float* __restrict__ d1, int n1,
    const float* __restrict__ s2, float* __restrict__ d2, int n2,
    const float* __restrict__ s3, float* __restrict__ d3, int n3,
    const float* __restrict__ s4, float* __restrict__ d4, int n4,
    const float* __restrict__ s5, float* __restrict__ d5, int n5) {
    int i = blockIdx.x * blockDim.x + threadIdx.x;
    const float* s;
    float* d;
    if (i < n0) { s = s0; d = d0; }
    else if ((i -= n0) < n1) { s = s1; d = d1; }
    else if ((i -= n1) < n2) { s = s2; d = d2; }
    else if ((i -= n2) < n3) { s = s3; d = d3; }
    else if ((i -= n3) < n4) { s = s4; d = d4; }
    else if ((i -= n4) < n5) { s = s5; d = d5; }
    else return;
    float4 v = ((const float4*)s)[i];
    v.x = tf32r(v.x); v.y = tf32r(v.y); v.z = tf32r(v.z); v.w = tf32r(v.w);
    ((float4*)d)[i] = v;
}

// ---------------- weight folds ----------------
__global__ void fold_k(const float* __restrict__ W, const float* __restrict__ rel,
                       const float* __restrict__ b,
                       float* __restrict__ Wout, float* __restrict__ bout) {
    int c = blockIdx.x, d = threadIdx.x;
    int h = c >> 5, j = c & 31;
    float s = 0.f;
#pragma unroll
    for (int i = 0; i < 32; i++)
        s += rel[(h * 32 + i) * 32 + j] * W[(h * 32 + i) * DD + d];
    Wout[c * DD + d] = tf32r(s);
    if (d == 0) {
        float sb = 0.f;
#pragma unroll
        for (int i = 0; i < 32; i++)
            sb += rel[(h * 32 + i) * 32 + j] * b[h * 32 + i];
        bout[c] = sb;
    }
}

__global__ void fold_q(const float* __restrict__ W, const float* __restrict__ rel,
                       const float* __restrict__ b,
                       float* __restrict__ Wout, float* __restrict__ bout) {
    int c = blockIdx.x, d = threadIdx.x;
    int h = c >> 5, i = c & 31;
    float s = 0.f;
#pragma unroll
    for (int j = 0; j < 32; j++)
        s += rel[(h * 32 + i) * 32 + j] * W[(h * 32 + j) * DD + d];
    Wout[c * DD + d] = tf32r(s);
    if (d == 0) {
        float sb = 0.f;
#pragma unroll
        for (int j = 0; j < 32; j++)
            sb += rel[(h * 32 + i) * 32 + j] * b[h * 32 + j];
        bout[c] = sb;
    }
}

// ---------------- block-diagonal per-head transform ----------------
__global__ void bdtrans(const float* __restrict__ in, const float* __restrict__ base,
                        const float* __restrict__ R, float* __restrict__ out,
                        int N, int transp, int roundit) {
    __shared__ float Rs[32 * 33];
    __shared__ float As[64 * 33];
    const int h = blockIdx.y;
    const int n0 = blockIdx.x * 64;
    const int t = threadIdx.x;
#pragma unroll
    for (int k = 0; k < 4; k++) {
        int idx = t * 4 + k;
        int i0 = idx >> 5, j0 = idx & 31;
        float v = R[h * 1024 + idx];
        if (transp) Rs[i0 * 33 + j0] = v;
        else        Rs[j0 * 33 + i0] = v;
    }
    const int rows = (N - n0 < 64) ? (N - n0) : 64;
#pragma unroll
    for (int it = 0; it < 8; it++) {
        int r = (t >> 5) + it * 8;
        int j = t & 31;
        if (r < rows) As[r * 33 + j] = in[(size_t)(n0 + r) * DD + h * 32 + j];
    }
    __syncthreads();
    const int i = t & 31;
#pragma unroll
    for (int it = 0; it < 8; it++) {
        int r = (t >> 5) + it * 8;
        if (r >= rows) break;
        float v = 0.f;
#pragma unroll
        for (int j = 0; j < 32; j++) v += As[r * 33 + j] * Rs[j * 33 + i];
        size_t o = (size_t)(n0 + r) * DD + h * 32 + i;
        if (base) v += base[o];
        out[o] = roundit ? tf32r(v) : v;
    }
}

// ---------------- tf32 mma GEMM pieces (R8-proven inner loop) ----------------
#define SLAB_F (128 * 36)
#define GSMEM (4 * SLAB_F * 4)
#define GS3 (8 * SLAB_F * 4)

__device__ __forceinline__ void mma1688(float c[4], const uint32_t a[4], const uint32_t b[2]) {
    asm volatile(
        "mma.sync.aligned.m16n8k8.row.col.f32.tf32.tf32.f32 "
        "{%0,%1,%2,%3}, {%4,%5,%6,%7}, {%8,%9}, {%0,%1,%2,%3};"
        : "+f"(c[0]), "+f"(c[1]), "+f"(c[2]), "+f"(c[3])
        : "r"(a[0]), "r"(a[1]), "r"(a[2]), "r"(a[3]), "r"(b[0]), "r"(b[1]));
}

// ---------------- fused out-GEMM (authors + papers in one launch) ----------------
__global__ __launch_bounds__(256) void gemm_out(
    int gaBlocks,
    const float* __restrict__ Aa, const float* __restrict__ Ap,
    const float* __restrict__ Ba, const float* __restrict__ Bp,
    const float* __restrict__ biasa, const float* __restrict__ biasp,
    const float* __restrict__ resida, const float* __restrict__ residp,
    const float* __restrict__ skipv,
    float* __restrict__ Ca, float* __restrict__ Cp, int Ma, int Mp) {
    extern __shared__ float sm[];
    const int tid = threadIdx.x;
    const bool pp = (int)blockIdx.x >= gaBlocks;
    const int m0 = ((int)blockIdx.x - (pp ? gaBlocks : 0)) * 128;
    const int col0 = blockIdx.y * 128;
    const float* A = pp ? Ap : Aa;
    const float* B = pp ? Bp : Ba;
    const float* bias = pp ? biasp : biasa;
    const float* resid = pp ? residp : resida;
    float* C = pp ? Cp : Ca;
    const int M = pp ? Mp : Ma;
    const int nid = pp ? 1 : 0;

    const int w = tid >> 5, ln = tid & 31;
    const int rowb = (w >> 2) * 64, colb = (w & 3) * 32;
    const int lg = ln >> 2, lt = ln & 3;

    float* const Ab[2] = {sm, sm + SLAB_F};
    float* const Bb[2] = {sm + 2 * SLAB_F, sm + 3 * SLAB_F};

    float c[4][4][4];
#pragma unroll
    for (int mi = 0; mi < 4; mi++)
#pragma unroll
        for (int ni = 0; ni < 4; ni++)
#pragma unroll
            for (int r = 0; r < 4; r++) c[mi][ni][r] = 0.f;

    auto load_slab = [&](int s, int b) {
        const int k0 = s * 32;
        float* As = Ab[b];
        float* Bs = Bb[b];
#pragma unroll
        for (int i = 0; i < 4; i++) {
            int idx = tid + i * 256;
            int row = idx >> 3, kg = idx & 7;
            uint32_t da = (uint32_t)__cvta_generic_to_shared(As + row * 36 + kg * 4);
            const float* ga = A + (size_t)(m0 + row) * DD + k0 + kg * 4;
            int sz = ((m0 + row) < M) ? 16 : 0;
            asm volatile("cp.async.cg.shared.global [%0], [%1], 16, %2;\n" ::"r"(da), "l"(ga), "r"(sz));
            uint32_t db = (uint32_t)__cvta_generic_to_shared(Bs + row * 36 + kg * 4);
            const float* gb = B + (size_t)(col0 + row) * DD + k0 + kg * 4;
            asm volatile("cp.async.cg.shared.global [%0], [%1], 16;\n" ::"r"(db), "l"(gb));
        }
        asm volatile("cp.async.commit_group;\n");
    };

    load_slab(0, 0);
    for (int s = 0; s < 8; s++) {
        int b = s & 1;
        if (s < 7) {
            load_slab(s + 1, b ^ 1);
            asm volatile("cp.async.wait_group 1;\n");
        } else {
            asm volatile("cp.async.wait_group 0;\n");
        }
        __syncthreads();
        const float* As = Ab[b];
        const float* Bs = Bb[b];
#pragma unroll
        for (int ks = 0; ks < 4; ks++) {
            const int kk = ks * 8 + lt;
            uint32_t af[4][4], bf[4][2];
#pragma unroll
            for (int mi = 0; mi < 4; mi++) {
                const float* p = As + (rowb + mi * 16 + lg) * 36 + kk;
                af[mi][0] = __float_as_uint(p[0]);
                af[mi][1] = __float_as_uint(p[8 * 36]);
                af[mi][2] = __float_as_uint(p[4]);
                af[mi][3] = __float_as_uint(p[8 * 36 + 4]);
            }
#pragma unroll
            for (int ni = 0; ni < 4; ni++) {
                const float* p = Bs + (colb + ni * 8 + lg) * 36 + kk;
                bf[ni][0] = __float_as_uint(p[0]);
                bf[ni][1] = __float_as_uint(p[4]);
            }
#pragma unroll
            for (int mi = 0; mi < 4; mi++)
#pragma unroll
                for (int ni = 0; ni < 4; ni++) mma1688(c[mi][ni], af[mi], bf[ni]);
        }
        __syncthreads();
    }

    float sv = skipv[nid];
    float alpha = 1.f / (1.f + __expf(-sv));
    float beta = 1.f - alpha;
#pragma unroll
    for (int mi = 0; mi < 4; mi++) {
#pragma unroll
        for (int half = 0; half < 2; half++) {
            int row = m0 + rowb + mi * 16 + lg + half * 8;
            if (row >= M) continue;
#pragma unroll
            for (int ni = 0; ni < 4; ni++) {
                int cc = col0 + colb + ni * 8 + lt * 2;
                float2 o;
                o.x = c[mi][ni][half * 2 + 0] + bias[cc];
                o.y = c[mi][ni][half * 2 + 1] + bias[cc + 1];
                float2 rv = *(const float2*)(resid + (size_t)row * DD + cc);
                o.x = o.x * alpha + rv.x * beta;
                o.y = o.y * alpha + rv.y * beta;
                *(float2*)(C + (size_t)row * DD + cc) = o;
            }
        }
    }
}

// ---------------- fused 3-B projection GEMM, both node types ----------------
__global__ __launch_bounds__(256, 1) void gemm3f(
    int gaBlocks,
    const float* __restrict__ Aa, const float* __restrict__ Ap,
    const float* __restrict__ Ba0, const float* __restrict__ Ba1, const float* __restrict__ Ba2,
    const float* __restrict__ Bp0, const float* __restrict__ Bp1, const float* __restrict__ Bp2,
    const float* __restrict__ ba0, const float* __restrict__ ba1, const float* __restrict__ ba2,
    const float* __restrict__ bp0, const float* __restrict__ bp1, const float* __restrict__ bp2,
    float* __restrict__ Ca0, float* __restrict__ Ca1, float* __restrict__ Ca2,
    float* __restrict__ Cp0, float* __restrict__ Cp1, float* __restrict__ Cp2,
    int Ma, int Mp) {
    extern __shared__ float sm[];
    const int tid = threadIdx.x;
    const bool pp = (int)blockIdx.x >= gaBlocks;
    const int m0 = ((int)blockIdx.x - (pp ? gaBlocks : 0)) * 128;
    const int col0 = blockIdx.y * 128;
    const float* A = pp ? Ap : Aa;
    const int M = pp ? Mp : Ma;
    const float* const Bv[3] = {pp ? Bp0 : Ba0, pp ? Bp1 : Ba1, pp ? Bp2 : Ba2};
    const float* const biv[3] = {pp ? bp0 : ba0, pp ? bp1 : ba1, pp ? bp2 : ba2};
    float* const Cv[3] = {pp ? Cp0 : Ca0, pp ? Cp1 : Ca1, pp ? Cp2 : Ca2};

    const int w = tid >> 5, ln = tid & 31;
    const int rowb = (w >> 2) * 64, colb = (w & 3) * 32;
    const int lg = ln >> 2, lt = ln & 3;

    float c[3][4][4][4];
#pragma unroll
    for (int b = 0; b < 3; b++)
#pragma unroll
        for (int mi = 0; mi < 4; mi++)
#pragma unroll
            for (int ni = 0; ni < 4; ni++)
#pragma unroll
                for (int r = 0; r < 4; r++) c[b][mi][ni][r] = 0.f;

    auto load_slab = [&](int s, int buf) {
        const int k0 = s * 32;
        float* As = sm + buf * SLAB_F;
#pragma unroll
        for (int i = 0; i < 4; i++) {
            int idx = tid + i * 256;
            int row = idx >> 3, kg = idx & 7;
            uint32_t da = (uint32_t)__cvta_generic_to_shared(As + row * 36 + kg * 4);
            const float* ga = A + (size_t)(m0 + row) * DD + k0 + kg * 4;
            int sz = ((m0 + row) < M) ? 16 : 0;
            asm volatile("cp.async.cg.shared.global [%0], [%1], 16, %2;\n" ::"r"(da), "l"(ga), "r"(sz));
        }
#pragma unroll
        for (int b = 0; b < 3; b++) {
            float* Bs = sm + (2 + b * 2 + buf) * SLAB_F;
#pragma unroll
            for (int i = 0; i < 4; i++) {
                int idx = tid + i * 256;
                int row = idx >> 3, kg = idx & 7;
                uint32_t db = (uint32_t)__cvta_generic_to_shared(Bs + row * 36 + kg * 4);
                const float* gb = Bv[b] + (size_t)(col0 + row) * DD + k0 + kg * 4;
                asm volatile("cp.async.cg.shared.global [%0], [%1], 16;\n" ::"r"(db), "l"(gb));
            }
        }
        asm volatile("cp.async.commit_group;\n");
    };

    load_slab(0, 0);
    for (int s = 0; s < 8; s++) {
        int buf = s & 1;
        if (s < 7) {
            load_slab(s + 1, buf ^ 1);
            asm volatile("cp.async.wait_group 1;\n");
        } else {
            asm volatile("cp.async.wait_group 0;\n");
        }
        __syncthreads();
        const float* As = sm + buf * SLAB_F;
#pragma unroll
        for (int ks = 0; ks < 4; ks++) {
            const int kk = ks * 8 + lt;
            uint32_t af[4][4];
#pragma unroll
            for (int mi = 0; mi < 4; mi++) {
                const float* p = As + (rowb + mi * 16 + lg) * 36 + kk;
                af[mi][0] = __float_as_uint(p[0]);
                af[mi][1] = __float_as_uint(p[8 * 36]);
                af[mi][2] = __float_as_uint(p[4]);
                af[mi][3] = __float_as_uint(p[8 * 36 + 4]);
            }
#pragma unroll
            for (int b = 0; b < 3; b++) {
                const float* Bs = sm + (2 + b * 2 + buf) * SLAB_F;
                uint32_t bf[4][2];
#pragma unroll
                for (int ni = 0; ni < 4; ni++) {
                    const float* p = Bs + (colb + ni * 8 + lg) * 36 + kk;
                    bf[ni][0] = __float_as_uint(p[0]);
                    bf[ni][1] = __float_as_uint(p[4]);
                }
#pragma unroll
                for (int mi = 0; mi < 4; mi++)
#pragma unroll
                    for (int ni = 0; ni < 4; ni++) mma1688(c[b][mi][ni], af[mi], bf[ni]);
            }
        }
        __syncthreads();
    }

#pragma unroll
    for (int b = 0; b < 3; b++) {
#pragma unroll
        for (int mi = 0; mi < 4; mi++) {
#pragma unroll
            for (int half = 0; half < 2; half++) {
                int row = m0 + rowb + mi * 16 + lg + half * 8;
                if (row >= M) continue;
#pragma unroll
                for (int ni = 0; ni < 4; ni++) {
                    int cc = col0 + colb + ni * 8 + lt * 2;
                    float2 o;
                    o.x = c[b][mi][ni][half * 2 + 0] + biv[b][cc];
                    o.y = c[b][mi][ni][half * 2 + 1] + biv[b][cc + 1];
                    *(float2*)(Cv[b] + (size_t)row * DD + cc) = o;
                }
            }
        }
    }
}

// ---------------- CSR build ----------------
__global__ void zero3(int* d0, int* d1, int* d2) {
    int i = blockIdx.x * blockDim.x + threadIdx.x;
    if (i < NP) { d0[i] = 0; d1[i] = 0; }
    if (i < NA) d2[i] = 0;
}

__global__ void hist3(const int* __restrict__ dw, const int* __restrict__ dc,
                      const int* __restrict__ db, int E,
                      int* d0, int* d1, int* d2) {
    int i = blockIdx.x * blockDim.x + threadIdx.x;
    if (i < E) atomicAdd(&d0[dw[i]], 1);
    else if (i < 2 * E) atomicAdd(&d1[dc[i - E]], 1);
    else if (i < 3 * E) atomicAdd(&d2[db[i - 2 * E]], 1);
}

__global__ void scan3(const int* __restrict__ deg0, const int* __restrict__ deg1,
                      const int* __restrict__ deg2,
                      int* rp0, int* rp1, int* rp2, int* c0, int* c1, int* c2) {
    __shared__ int sh[1024];
    __shared__ int carry_s;
    const int* deg; int* rp; int* cur; int n;
    if (blockIdx.x == 0) { deg = deg0; rp = rp0; cur = c0; n = NP; }
    else if (blockIdx.x == 1) { deg = deg1; rp = rp1; cur = c1; n = NP; }
    else { deg = deg2; rp = rp2; cur = c2; n = NA; }
    int tid = threadIdx.x;
    if (tid == 0) carry_s = 0;
    __syncthreads();
    for (int base = 0; base < n; base += 1024) {
        int i = base + tid;
        int v = (i < n) ? deg[i] : 0;
        sh[tid] = v;
        __syncthreads();
        for (int off = 1; off < 1024; off <<= 1) {
            int t = (tid >= off) ? sh[tid - off] : 0;
            __syncthreads();
            sh[tid] += t;
            __syncthreads();
        }
        int incl = sh[tid] + carry_s;
        if (i < n) { rp[i + 1] = incl; cur[i] = incl - v; }
        __syncthreads();
        if (tid == 1023) carry_s = incl;
        __syncthreads();
    }
    if (tid == 0) rp[0] = 0;
}

__global__ void scatter3(const int* __restrict__ sw, const int* __restrict__ dw,
                         const int* __restrict__ sc, const int* __restrict__ dc,
                         const int* __restrict__ sb, const int* __restrict__ db, int E,
                         int* c0, int* c1, int* c2,
                         int* col0, int* col1, int* col2) {
    int i = blockIdx.x * blockDim.x + threadIdx.x;
    if (i < E) { int p = atomicAdd(&c0[dw[i]], 1); col0[p] = sw[i]; }
    else if (i < 2 * E) { int j = i - E; int p = atomicAdd(&c1[dc[j]], 1); col1[p] = sc[j]; }
    else if (i < 3 * E) { int j = i - 2 * E; int p = atomicAdd(&c2[db[j]], 1); col2[p] = sb[j]; }
}

// ---------------- aggregation (R8-proven), fused over papers+authors ----------------
__device__ __forceinline__ void csr_attend8(
    int node, int lane, const int* __restrict__ rp, const int* __restrict__ colv,
    const float* __restrict__ K, const float* __restrict__ V,
    const float4 qa, const float4 qb, const float prih, float acc[8]) {
    float s = 0.f;
    float a[8];
#pragma unroll
    for (int j = 0; j < 8; j++) a[j] = 0.f;
    const int off = (lane >> 2) * DKH + (lane & 3) * 8;
    const int beg = rp[node], end = rp[node + 1];
    for (int e = beg; e < end; e++) {
        const int src = colv[e];
        const float* kr = K + (size_t)src * DD + off;
        float4 k0 = *(const float4*)kr;
        float4 k1 = *(const float4*)(kr + 4);
        float p = qa.x * k0.x + qa.y * k0.y + qa.z * k0.z + qa.w * k0.w +
                  qb.x * k1.x + qb.y * k1.y + qb.z * k1.z + qb.w * k1.w;
        p += __shfl_xor_sync(0xffffffffu, p, 1);
        p += __shfl_xor_sync(0xffffffffu, p, 2);
        float wgt = __expf(p * prih);
        const float* vr = V + (size_t)src * DD + off;
        float4 v0 = *(const float4*)vr;
        float4 v1 = *(const float4*)(vr + 4);
        s += wgt;
        a[0] += wgt * v0.x; a[1] += wgt * v0.y; a[2] += wgt * v0.z; a[3] += wgt * v0.w;
        a[4] += wgt * v1.x; a[5] += wgt * v1.y; a[6] += wgt * v1.z; a[7] += wgt * v1.w;
    }
    if (s > 0.f) {
        float inv = 1.f / s;
#pragma unroll
        for (int j = 0; j < 8; j++) acc[j] += a[j] * inv;
    }
}

__global__ void agg_all(const float* __restrict__ Qp, const float* __restrict__ Qpc,
                        const float* __restrict__ Qa,
                        const float* __restrict__ K0, const float* __restrict__ V0,
                        const float* __restrict__ Kp, const float* __restrict__ Vp,
                        const int* __restrict__ rp0, const int* __restrict__ col0,
                        const int* __restrict__ rp1, const int* __restrict__ col1,
                        const int* __restrict__ rp2, const int* __restrict__ col2,
                        const float* __restrict__ rel_pri,
                        float* __restrict__ aggw, float* __restrict__ aggc,
                        float* __restrict__ agga) {
    int w = (blockIdx.x * blockDim.x + threadIdx.x) >> 5;
    int lane = threadIdx.x & 31;
    const float sc = 0.17677669529663687f;
    const int h = lane >> 2;
    const int off = h * DKH + (lane & 3) * 8;
    if (w < NP) {
        const size_t qoff = (size_t)w * DD + off;
        {
            float4 qa = *(const float4*)(Qp + qoff);
            float4 qb = *(const float4*)(Qp + qoff + 4);
            float acc[8];
#pragma unroll
            for (int j = 0; j < 8; j++) acc[j] = 0.f;
            csr_attend8(w, lane, rp0, col0, K0, V0, qa, qb, rel_pri[h] * sc, acc);
            float* o = aggw + qoff;
            *(float4*)o = make_float4(acc[0], acc[1], acc[2], acc[3]);
            *(float4*)(o + 4) = make_float4(acc[4], acc[5], acc[6], acc[7]);
        }
        {
            float4 qa = *(const float4*)(Qpc + qoff);
            float4 qb = *(const float4*)(Qpc + qoff + 4);
            float acc[8];
#pragma unroll
            for (int j = 0; j < 8; j++) acc[j] = 0.f;
            csr_attend8(w, lane, rp1, col1, Kp, Vp, qa, qb, rel_pri[NH + h] * sc, acc);
            float* o = aggc + qoff;
            *(float4*)o = make_float4(acc[0], acc[1], acc[2], acc[3]);
            *(float4*)(o + 4) = make_float4(acc[4], acc[5], acc[6], acc[7]);
        }
    } else if (w < NP + NA) {
        int n = w - NP;
        const size_t qoff = (size_t)n * DD + off;
        float4 qa = *(const float4*)(Qa + qoff);
        float4 qb = *(const float4*)(Qa + qoff + 4);
        float acc[8];
#pragma unroll
        for (int j = 0; j < 8; j++) acc[j] = 0.f;
        csr_attend8(n, lane, rp2, col2, Kp, Vp, qa, qb, rel_pri[2 * NH + h] * sc, acc);
        float* o = agga + qoff;
        *(float4*)o = make_float4(acc[0], acc[1], acc[2], acc[3]);
        *(float4*)(o + 4) = make_float4(acc[4], acc[5], acc[6], acc[7]);
    }
}

// ---------------- host launch ----------------
extern "C" void kernel_launch(void* const* d_in, const int* in_sizes, int n_in,
                              void* d_out, int out_size) {
    const float* h_author = (const float*)d_in[0];
    const float* h_paper  = (const float*)d_in[1];
    const float* k_w  = (const float*)d_in[2];
    const float* k_b  = (const float*)d_in[3];
    const float* q_w  = (const float*)d_in[4];
    const float* q_b  = (const float*)d_in[5];
    const float* v_w  = (const float*)d_in[6];
    const float* v_b  = (const float*)d_in[7];
    const float* a_w  = (const float*)d_in[8];
    const float* a_b  = (const float*)d_in[9];
    const float* rel_att = (const float*)d_in[10];
    const float* rel_msg = (const float*)d_in[11];
    const float* rel_pri = (const float*)d_in[12];
    const float* skipv   = (const float*)d_in[13];
    const int* src_writes = (const int*)d_in[14];
    const int* dst_writes = (const int*)d_in[15];
    const int* src_cites  = (const int*)d_in[16];
    const int* dst_cites  = (const int*)d_in[17];
    const int* src_wb     = (const int*)d_in[18];
    const int* dst_wb     = (const int*)d_in[19];

    int E = in_sizes[14];
    if (E > EMAX) E = EMAX;

    float *Har, *Hpr, *K0, *V0, *Qa, *Kp, *Vp, *Qp, *Qpc;
    float *aggPw, *aggPc, *aggP, *aggAc, *aggA, *fW, *fB, *rw;
    int *deg0, *deg1, *deg2, *rp0, *rp1, *rp2, *cur0, *cur1, *cur2, *col0, *col1, *col2;
    cudaGetSymbolAddress((void**)&Har, g_Har);
    cudaGetSymbolAddress((void**)&Hpr, g_Hpr);
    cudaGetSymbolAddress((void**)&K0, g_K0);
    cudaGetSymbolAddress((void**)&V0, g_V0);
    cudaGetSymbolAddress((void**)&Qa, g_Qa);
    cudaGetSymbolAddress((void**)&Kp, g_Kp);
    cudaGetSymbolAddress((void**)&Vp, g_Vp);
    cudaGetSymbolAddress((void**)&Qp, g_Qp);
    cudaGetSymbolAddress((void**)&Qpc, g_Qpc);
    cudaGetSymbolAddress((void**)&aggPw, g_aggPw);
    cudaGetSymbolAddress((void**)&aggPc, g_aggPc);
    cudaGetSymbolAddress((void**)&aggP, g_aggP);
    cudaGetSymbolAddress((void**)&aggAc, g_aggAc);
    cudaGetSymbolAddress((void**)&aggA, g_aggA);
    cudaGetSymbolAddress((void**)&fW, g_fW);
    cudaGetSymbolAddress((void**)&fB, g_fB);
    cudaGetSymbolAddress((void**)&rw, g_rw);
    cudaGetSymbolAddress((void**)&deg0, g_deg0);
    cudaGetSymbolAddress((void**)&deg1, g_deg1);
    cudaGetSymbolAddress((void**)&deg2, g_deg2);
    cudaGetSymbolAddress((void**)&rp0, g_rp0);
    cudaGetSymbolAddress((void**)&rp1, g_rp1);
    cudaGetSymbolAddress((void**)&rp2, g_rp2);
    cudaGetSymbolAddress((void**)&cur0, g_cur0);
    cudaGetSymbolAddress((void**)&cur1, g_cur1);
    cudaGetSymbolAddress((void**)&cur2, g_cur2);
    cudaGetSymbolAddress((void**)&col0, g_col0);
    cudaGetSymbolAddress((void**)&col1, g_col1);
    cudaGetSymbolAddress((void**)&col2, g_col2);

    cudaFuncSetAttribute(gemm_out, cudaFuncAttributeMaxDynamicSharedMemorySize, GSMEM);
    cudaFuncSetAttribute(gemm3f, cudaFuncAttributeMaxDynamicSharedMemorySize, GS3);

    float* kwr1 = rw + 0 * 65536;
    float* vwr1 = rw + 1 * 65536;
    float* qwr1 = rw + 2 * 65536;
    float* awr  = rw + 3 * 65536;
    float* fWk0 = fW + 0 * 65536;
    float* fWv0 = fW + 1 * 65536;
    float* fWqa = fW + 2 * 65536;
    float* fBk0 = fB + 0 * 256;
    float* fBv0 = fB + 1 * 256;
    float* fBqa = fB + 2 * 256;

    // 1) fused pre-round (6 regions, counts in float4s)
    {
        int n0 = NA * DD / 4, n1 = NP * DD / 4, n2 = 65536 / 4, n3 = 65536 / 4,
            n4 = 65536 / 4, n5 = 131072 / 4;
        int total = n0 + n1 + n2 + n3 + n4 + n5;
        roundcopy_all<<<(total + 255) / 256, 256>>>(
            h_author, Har, n0, h_paper, Hpr, n1,
            k_w + 65536, kwr1, n2, v_w + 65536, vwr1, n3,
            q_w + 65536, qwr1, n4, a_w, awr, n5);
    }

    // 2) weight folds
    fold_k<<<256, 256>>>(k_w, rel_att, k_b, fWk0, fBk0);
    fold_k<<<256, 256>>>(v_w, rel_msg, v_b, fWv0, fBv0);
    fold_q<<<256, 256>>>(q_w, rel_att + 2 * 8192, q_b, fWqa, fBqa);

    // 3) fused projection GEMM (authors + papers)
    const int gaB = (NA + 127) / 128, gpB = (NP + 127) / 128;
    {
        dim3 g(gaB + gpB, 2);
        gemm3f<<<g, 256, GS3>>>(gaB, Har, Hpr,
                                fWk0, fWv0, fWqa, kwr1, vwr1, qwr1,
                                fBk0, fBv0, fBqa, k_b + 256, v_b + 256, q_b + 256,
                                K0, V0, Qa, Kp, Vp, Qp, NA, NP);
    }

    // 4) Q transform for cites
    {
        dim3 g((NP + 63) / 64, NH);
        bdtrans<<<g, 256>>>(Qp, nullptr, rel_att + 8192, Qpc, NP, 0, 0);
    }

    // 5) CSR builds
    zero3<<<(NP + 255) / 256, 256>>>(deg0, deg1, deg2);
    hist3<<<(3 * E + 255) / 256, 256>>>(dst_writes, dst_cites, dst_wb, E, deg0, deg1, deg2);
    scan3<<<3, 1024>>>(deg0, deg1, deg2, rp0, rp1, rp2, cur0, cur1, cur2);
    scatter3<<<(3 * E + 255) / 256, 256>>>(src_writes, dst_writes, src_cites, dst_cites,
                                           src_wb, dst_wb, E, cur0, cur1, cur2, col0, col1, col2);

    // 6) fused attention aggregation (papers + authors)
    agg_all<<<((NP + NA) * 32 + 255) / 256, 256>>>(Qp, Qpc, Qa, K0, V0, Kp, Vp,
                                                   rp0, col0, rp1, col1, rp2, col2,
                                                   rel_pri, aggPw, aggPc, aggAc);

    // 7) post-agg message transforms
    {
        dim3 gp((NP + 63) / 64, NH), ga((NA + 63) / 64, NH);
        bdtrans<<<gp, 256>>>(aggPc, aggPw, rel_msg + 8192, aggP, NP, 1, 1);
        bdtrans<<<ga, 256>>>(aggAc, nullptr, rel_msg + 2 * 8192, aggA, NA, 1, 1);
    }

    // 8) fused output GEMM (authors + papers)
    float* out = (float*)d_out;
    {
        dim3 g(gaB + gpB, 2);
        gemm_out<<<g, 256, GSMEM>>>(gaB, aggA, aggP, awr, awr + 65536, a_b, a_b + 256,
                                    h_author, h_paper, skipv, out, out + (size_t)NA * DD,
                                    NA, NP);
    }
}

// round 11
// speedup vs baseline: 1.3859x; 1.2292x over previous
#include <cuda_runtime.h>
#include <cuda_fp16.h>
#include <math.h>
#include <cstdint>

#define NA 20000
#define NP 50000
#define EMAX 300000
#define DD 256
#define NH 8
#define DKH 32

// ---------------- scratch ----------------
__device__ float g_Har[NA * DD];
__device__ float g_Hpr[NP * DD];
__device__ __half g_K0[NA * DD];
__device__ __half g_V0[NA * DD];
__device__ float g_Qa[NA * DD];
__device__ __half g_Kp[NP * DD];
__device__ __half g_Vp[NP * DD];
__device__ float g_Qp[NP * DD];
__device__ float g_Qpc[NP * DD];
__device__ float g_aggPw[NP * DD];
__device__ float g_aggPc[NP * DD];
__device__ float g_aggP[NP * DD];
__device__ float g_aggAc[NA * DD];
__device__ float g_aggA[NA * DD];
__device__ float g_fW[3 * DD * DD];
__device__ float g_fB[3 * DD];
__device__ float g_rw[5 * DD * DD];
__device__ int g_deg0[NP];
__device__ int g_deg1[NP];
__device__ int g_deg2[NA];
__device__ int g_rp0[NP + 1];
__device__ int g_rp1[NP + 1];
__device__ int g_rp2[NA + 1];
__device__ int g_cur0[NP];
__device__ int g_cur1[NP];
__device__ int g_cur2[NA];
__device__ int g_col0[EMAX];
__device__ int g_col1[EMAX];
__device__ int g_col2[EMAX];
__device__ int g_psum[64];
__device__ int g_pbase[64];

__device__ __forceinline__ float tf32r(float v) {
    uint32_t r;
    asm("cvt.rna.tf32.f32 %0, %1;" : "=r"(r) : "f"(v));
    return __uint_as_float(r);
}

// ---------------- fused round-copy over 6 regions ----------------
__global__ void roundcopy_all(
    const float* __restrict__ s0, float* __restrict__ d0, int n0,
    const float* __restrict__ s1, float* __restrict__ d1, int n1,
    const float* __restrict__ s2, float* __restrict__ d2, int n2,
    const float* __restrict__ s3, float* __restrict__ d3, int n3,
    const float* __restrict__ s4, float* __restrict__ d4, int n4,
    const float* __restrict__ s5, float* __restrict__ d5, int n5) {
    int i = blockIdx.x * blockDim.x + threadIdx.x;
    const float* s;
    float* d;
    if (i < n0) { s = s0; d = d0; }
    else if ((i -= n0) < n1) { s = s1; d = d1; }
    else if ((i -= n1) < n2) { s = s2; d = d2; }
    else if ((i -= n2) < n3) { s = s3; d = d3; }
    else if ((i -= n3) < n4) { s = s4; d = d4; }
    else if ((i -= n4) < n5) { s = s5; d = d5; }
    else return;
    float4 v = ((const float4*)s)[i];
    v.x = tf32r(v.x); v.y = tf32r(v.y); v.z = tf32r(v.z); v.w = tf32r(v.w);
    ((float4*)d)[i] = v;
}

// ---------------- fused weight folds (3 in one launch) ----------------
__global__ void fold_all(const float* __restrict__ k_w, const float* __restrict__ v_w,
                         const float* __restrict__ q_w,
                         const float* __restrict__ k_b, const float* __restrict__ v_b,
                         const float* __restrict__ q_b,
                         const float* __restrict__ rel_att, const float* __restrict__ rel_msg,
                         float* __restrict__ fWk0, float* __restrict__ fWv0,
                         float* __restrict__ fWqa,
                         float* __restrict__ fBk0, float* __restrict__ fBv0,
                         float* __restrict__ fBqa) {
    const int which = blockIdx.y;
    const float *W, *rel, *b;
    float *Wout, *bout;
    if (which == 0) { W = k_w; rel = rel_att; b = k_b; Wout = fWk0; bout = fBk0; }
    else if (which == 1) { W = v_w; rel = rel_msg; b = v_b; Wout = fWv0; bout = fBv0; }
    else { W = q_w; rel = rel_att + 2 * 8192; b = q_b; Wout = fWqa; bout = fBqa; }
    int c = blockIdx.x, d = threadIdx.x;
    int h = c >> 5, x = c & 31;
    float s = 0.f;
    if (which < 2) {
#pragma unroll
        for (int i = 0; i < 32; i++)
            s += rel[(h * 32 + i) * 32 + x] * W[(h * 32 + i) * DD + d];
    } else {
#pragma unroll
        for (int j = 0; j < 32; j++)
            s += rel[(h * 32 + x) * 32 + j] * W[(h * 32 + j) * DD + d];
    }
    Wout[c * DD + d] = tf32r(s);
    if (d == 0) {
        float sb = 0.f;
        if (which < 2) {
#pragma unroll
            for (int i = 0; i < 32; i++)
                sb += rel[(h * 32 + i) * 32 + x] * b[h * 32 + i];
        } else {
#pragma unroll
            for (int j = 0; j < 32; j++)
                sb += rel[(h * 32 + x) * 32 + j] * b[h * 32 + j];
        }
        bout[c] = sb;
    }
}

// ---------------- block-diagonal per-head transform ----------------
__global__ void bdtrans(const float* __restrict__ in, const float* __restrict__ base,
                        const float* __restrict__ R, float* __restrict__ out,
                        int N, int transp, int roundit) {
    __shared__ float Rs[32 * 33];
    __shared__ float As[64 * 33];
    const int h = blockIdx.y;
    const int n0 = blockIdx.x * 64;
    const int t = threadIdx.x;
#pragma unroll
    for (int k = 0; k < 4; k++) {
        int idx = t * 4 + k;
        int i0 = idx >> 5, j0 = idx & 31;
        float v = R[h * 1024 + idx];
        if (transp) Rs[i0 * 33 + j0] = v;
        else        Rs[j0 * 33 + i0] = v;
    }
    const int rows = (N - n0 < 64) ? (N - n0) : 64;
#pragma unroll
    for (int it = 0; it < 8; it++) {
        int r = (t >> 5) + it * 8;
        int j = t & 31;
        if (r < rows) As[r * 33 + j] = in[(size_t)(n0 + r) * DD + h * 32 + j];
    }
    __syncthreads();
    const int i = t & 31;
#pragma unroll
    for (int it = 0; it < 8; it++) {
        int r = (t >> 5) + it * 8;
        if (r >= rows) break;
        float v = 0.f;
#pragma unroll
        for (int j = 0; j < 32; j++) v += As[r * 33 + j] * Rs[j * 33 + i];
        size_t o = (size_t)(n0 + r) * DD + h * 32 + i;
        if (base) v += base[o];
        out[o] = roundit ? tf32r(v) : v;
    }
}

// ---------------- tf32 mma helpers ----------------
#define SLAB_F (128 * 36)
#define GSMEM (4 * SLAB_F * 4)
#define GS3 (8 * SLAB_F * 4)

__device__ __forceinline__ void mma1688(float c[4], const uint32_t a[4], const uint32_t b[2]) {
    asm volatile(
        "mma.sync.aligned.m16n8k8.row.col.f32.tf32.tf32.f32 "
        "{%0,%1,%2,%3}, {%4,%5,%6,%7}, {%8,%9}, {%0,%1,%2,%3};"
        : "+f"(c[0]), "+f"(c[1]), "+f"(c[2]), "+f"(c[3])
        : "r"(a[0]), "r"(a[1]), "r"(a[2]), "r"(a[3]), "r"(b[0]), "r"(b[1]));
}

// ---------------- fused out-GEMM (authors + papers) ----------------
__global__ __launch_bounds__(256) void gemm_out(
    int gaBlocks,
    const float* __restrict__ Aa, const float* __restrict__ Ap,
    const float* __restrict__ Ba, const float* __restrict__ Bp,
    const float* __restrict__ biasa, const float* __restrict__ biasp,
    const float* __restrict__ resida, const float* __restrict__ residp,
    const float* __restrict__ skipv,
    float* __restrict__ Ca, float* __restrict__ Cp, int Ma, int Mp) {
    extern __shared__ float sm[];
    const int tid = threadIdx.x;
    const bool pp = (int)blockIdx.x >= gaBlocks;
    const int m0 = ((int)blockIdx.x - (pp ? gaBlocks : 0)) * 128;
    const int col0 = blockIdx.y * 128;
    const float* A = pp ? Ap : Aa;
    const float* B = pp ? Bp : Ba;
    const float* bias = pp ? biasp : biasa;
    const float* resid = pp ? residp : resida;
    float* C = pp ? Cp : Ca;
    const int M = pp ? Mp : Ma;
    const int nid = pp ? 1 : 0;

    const int w = tid >> 5, ln = tid & 31;
    const int rowb = (w >> 2) * 64, colb = (w & 3) * 32;
    const int lg = ln >> 2, lt = ln & 3;

    float* const Ab[2] = {sm, sm + SLAB_F};
    float* const Bb[2] = {sm + 2 * SLAB_F, sm + 3 * SLAB_F};

    float c[4][4][4];
#pragma unroll
    for (int mi = 0; mi < 4; mi++)
#pragma unroll
        for (int ni = 0; ni < 4; ni++)
#pragma unroll
            for (int r = 0; r < 4; r++) c[mi][ni][r] = 0.f;

    auto load_slab = [&](int s, int b) {
        const int k0 = s * 32;
        float* As = Ab[b];
        float* Bs = Bb[b];
#pragma unroll
        for (int i = 0; i < 4; i++) {
            int idx = tid + i * 256;
            int row = idx >> 3, kg = idx & 7;
            uint32_t da = (uint32_t)__cvta_generic_to_shared(As + row * 36 + kg * 4);
            const float* ga = A + (size_t)(m0 + row) * DD + k0 + kg * 4;
            int sz = ((m0 + row) < M) ? 16 : 0;
            asm volatile("cp.async.cg.shared.global [%0], [%1], 16, %2;\n" ::"r"(da), "l"(ga), "r"(sz));
            uint32_t db = (uint32_t)__cvta_generic_to_shared(Bs + row * 36 + kg * 4);
            const float* gb = B + (size_t)(col0 + row) * DD + k0 + kg * 4;
            asm volatile("cp.async.cg.shared.global [%0], [%1], 16;\n" ::"r"(db), "l"(gb));
        }
        asm volatile("cp.async.commit_group;\n");
    };

    load_slab(0, 0);
    for (int s = 0; s < 8; s++) {
        int b = s & 1;
        if (s < 7) {
            load_slab(s + 1, b ^ 1);
            asm volatile("cp.async.wait_group 1;\n");
        } else {
            asm volatile("cp.async.wait_group 0;\n");
        }
        __syncthreads();
        const float* As = Ab[b];
        const float* Bs = Bb[b];
#pragma unroll
        for (int ks = 0; ks < 4; ks++) {
            const int kk = ks * 8 + lt;
            uint32_t af[4][4], bf[4][2];
#pragma unroll
            for (int mi = 0; mi < 4; mi++) {
                const float* p = As + (rowb + mi * 16 + lg) * 36 + kk;
                af[mi][0] = __float_as_uint(p[0]);
                af[mi][1] = __float_as_uint(p[8 * 36]);
                af[mi][2] = __float_as_uint(p[4]);
                af[mi][3] = __float_as_uint(p[8 * 36 + 4]);
            }
#pragma unroll
            for (int ni = 0; ni < 4; ni++) {
                const float* p = Bs + (colb + ni * 8 + lg) * 36 + kk;
                bf[ni][0] = __float_as_uint(p[0]);
                bf[ni][1] = __float_as_uint(p[4]);
            }
#pragma unroll
            for (int mi = 0; mi < 4; mi++)
#pragma unroll
                for (int ni = 0; ni < 4; ni++) mma1688(c[mi][ni], af[mi], bf[ni]);
        }
        __syncthreads();
    }

    float sv = skipv[nid];
    float alpha = 1.f / (1.f + __expf(-sv));
    float beta = 1.f - alpha;
#pragma unroll
    for (int mi = 0; mi < 4; mi++) {
#pragma unroll
        for (int half = 0; half < 2; half++) {
            int row = m0 + rowb + mi * 16 + lg + half * 8;
            if (row >= M) continue;
#pragma unroll
            for (int ni = 0; ni < 4; ni++) {
                int cc = col0 + colb + ni * 8 + lt * 2;
                float2 o;
                o.x = c[mi][ni][half * 2 + 0] + bias[cc];
                o.y = c[mi][ni][half * 2 + 1] + bias[cc + 1];
                float2 rv = *(const float2*)(resid + (size_t)row * DD + cc);
                o.x = o.x * alpha + rv.x * beta;
                o.y = o.y * alpha + rv.y * beta;
                *(float2*)(C + (size_t)row * DD + cc) = o;
            }
        }
    }
}

// ---------------- fused 3-B projection GEMM; K/V outputs stored fp16 ----------------
__global__ __launch_bounds__(256, 1) void gemm3f(
    int gaBlocks,
    const float* __restrict__ Aa, const float* __restrict__ Ap,
    const float* __restrict__ Ba0, const float* __restrict__ Ba1, const float* __restrict__ Ba2,
    const float* __restrict__ Bp0, const float* __restrict__ Bp1, const float* __restrict__ Bp2,
    const float* __restrict__ ba0, const float* __restrict__ ba1, const float* __restrict__ ba2,
    const float* __restrict__ bp0, const float* __restrict__ bp1, const float* __restrict__ bp2,
    __half* __restrict__ CaK, __half* __restrict__ CaV, float* __restrict__ CaQ,
    __half* __restrict__ CpK, __half* __restrict__ CpV, float* __restrict__ CpQ,
    int Ma, int Mp) {
    extern __shared__ float sm[];
    const int tid = threadIdx.x;
    const bool pp = (int)blockIdx.x >= gaBlocks;
    const int m0 = ((int)blockIdx.x - (pp ? gaBlocks : 0)) * 128;
    const int col0 = blockIdx.y * 128;
    const float* A = pp ? Ap : Aa;
    const int M = pp ? Mp : Ma;
    const float* const Bv[3] = {pp ? Bp0 : Ba0, pp ? Bp1 : Ba1, pp ? Bp2 : Ba2};
    const float* const biv[3] = {pp ? bp0 : ba0, pp ? bp1 : ba1, pp ? bp2 : ba2};
    __half* const Chv[2] = {pp ? CpK : CaK, pp ? CpV : CaV};
    float* const Cq = pp ? CpQ : CaQ;

    const int w = tid >> 5, ln = tid & 31;
    const int rowb = (w >> 2) * 64, colb = (w & 3) * 32;
    const int lg = ln >> 2, lt = ln & 3;

    float c[3][4][4][4];
#pragma unroll
    for (int b = 0; b < 3; b++)
#pragma unroll
        for (int mi = 0; mi < 4; mi++)
#pragma unroll
            for (int ni = 0; ni < 4; ni++)
#pragma unroll
                for (int r = 0; r < 4; r++) c[b][mi][ni][r] = 0.f;

    auto load_slab = [&](int s, int buf) {
        const int k0 = s * 32;
        float* As = sm + buf * SLAB_F;
#pragma unroll
        for (int i = 0; i < 4; i++) {
            int idx = tid + i * 256;
            int row = idx >> 3, kg = idx & 7;
            uint32_t da = (uint32_t)__cvta_generic_to_shared(As + row * 36 + kg * 4);
            const float* ga = A + (size_t)(m0 + row) * DD + k0 + kg * 4;
            int sz = ((m0 + row) < M) ? 16 : 0;
            asm volatile("cp.async.cg.shared.global [%0], [%1], 16, %2;\n" ::"r"(da), "l"(ga), "r"(sz));
        }
#pragma unroll
        for (int b = 0; b < 3; b++) {
            float* Bs = sm + (2 + b * 2 + buf) * SLAB_F;
#pragma unroll
            for (int i = 0; i < 4; i++) {
                int idx = tid + i * 256;
                int row = idx >> 3, kg = idx & 7;
                uint32_t db = (uint32_t)__cvta_generic_to_shared(Bs + row * 36 + kg * 4);
                const float* gb = Bv[b] + (size_t)(col0 + row) * DD + k0 + kg * 4;
                asm volatile("cp.async.cg.shared.global [%0], [%1], 16;\n" ::"r"(db), "l"(gb));
            }
        }
        asm volatile("cp.async.commit_group;\n");
    };

    load_slab(0, 0);
    for (int s = 0; s < 8; s++) {
        int buf = s & 1;
        if (s < 7) {
            load_slab(s + 1, buf ^ 1);
            asm volatile("cp.async.wait_group 1;\n");
        } else {
            asm volatile("cp.async.wait_group 0;\n");
        }
        __syncthreads();
        const float* As = sm + buf * SLAB_F;
#pragma unroll
        for (int ks = 0; ks < 4; ks++) {
            const int kk = ks * 8 + lt;
            uint32_t af[4][4];
#pragma unroll
            for (int mi = 0; mi < 4; mi++) {
                const float* p = As + (rowb + mi * 16 + lg) * 36 + kk;
                af[mi][0] = __float_as_uint(p[0]);
                af[mi][1] = __float_as_uint(p[8 * 36]);
                af[mi][2] = __float_as_uint(p[4]);
                af[mi][3] = __float_as_uint(p[8 * 36 + 4]);
            }
#pragma unroll
            for (int b = 0; b < 3; b++) {
                const float* Bs = sm + (2 + b * 2 + buf) * SLAB_F;
                uint32_t bf[4][2];
#pragma unroll
                for (int ni = 0; ni < 4; ni++) {
                    const float* p = Bs + (colb + ni * 8 + lg) * 36 + kk;
                    bf[ni][0] = __float_as_uint(p[0]);
                    bf[ni][1] = __float_as_uint(p[4]);
                }
#pragma unroll
                for (int mi = 0; mi < 4; mi++)
#pragma unroll
                    for (int ni = 0; ni < 4; ni++) mma1688(c[b][mi][ni], af[mi], bf[ni]);
            }
        }
        __syncthreads();
    }

#pragma unroll
    for (int b = 0; b < 3; b++) {
#pragma unroll
        for (int mi = 0; mi < 4; mi++) {
#pragma unroll
            for (int half = 0; half < 2; half++) {
                int row = m0 + rowb + mi * 16 + lg + half * 8;
                if (row >= M) continue;
#pragma unroll
                for (int ni = 0; ni < 4; ni++) {
                    int cc = col0 + colb + ni * 8 + lt * 2;
                    float ox = c[b][mi][ni][half * 2 + 0] + biv[b][cc];
                    float oy = c[b][mi][ni][half * 2 + 1] + biv[b][cc + 1];
                    if (b < 2) {
                        *(__half2*)(Chv[b] + (size_t)row * DD + cc) = __floats2half2_rn(ox, oy);
                    } else {
                        *(float2*)(Cq + (size_t)row * DD + cc) = make_float2(ox, oy);
                    }
                }
            }
        }
    }
}

// ---------------- CSR build ----------------
__global__ void zero3(int* d0, int* d1, int* d2) {
    int i = blockIdx.x * blockDim.x + threadIdx.x;
    if (i < NP) { d0[i] = 0; d1[i] = 0; }
    if (i < NA) d2[i] = 0;
}

__global__ void hist3(const int* __restrict__ dw, const int* __restrict__ dc,
                      const int* __restrict__ db, int E,
                      int* d0, int* d1, int* d2) {
    int i = blockIdx.x * blockDim.x + threadIdx.x;
    if (i < E) atomicAdd(&d0[dw[i]], 1);
    else if (i < 2 * E) atomicAdd(&d1[dc[i - E]], 1);
    else if (i < 3 * E) atomicAdd(&d2[db[i - 2 * E]], 1);
}

// wide 3-phase scan: BLKE=2048 per block; seg0:25 blocks, seg1:25, seg2:10
#define BLKE 2048
#define NB0 25
#define NB1 25
#define NB2 10

__device__ __forceinline__ void seg_of(int b, const int** deg, int* base, int* n, int* lb,
                                       const int* d0, const int* d1, const int* d2) {
    if (b < NB0) { *deg = d0; *lb = b; *n = NP; }
    else if (b < NB0 + NB1) { *deg = d1; *lb = b - NB0; *n = NP; }
    else { *deg = d2; *lb = b - NB0 - NB1; *n = NA; }
    *base = *lb * BLKE;
}

__global__ void scanA(const int* __restrict__ d0, const int* __restrict__ d1,
                      const int* __restrict__ d2, int* __restrict__ psum) {
    __shared__ int sh[512];
    const int* deg; int base, n, lb;
    seg_of(blockIdx.x, &deg, &base, &n, &lb, d0, d1, d2);
    int t = threadIdx.x;
    int s = 0;
#pragma unroll
    for (int k = 0; k < 4; k++) {
        int i = base + t * 4 + k;
        if (i < n && t * 4 + k < BLKE) s += deg[i];
    }
    sh[t] = s;
    __syncthreads();
    for (int off = 256; off; off >>= 1) {
        if (t < off) sh[t] += sh[t + off];
        __syncthreads();
    }
    if (t == 0) psum[blockIdx.x] = sh[0];
}

__global__ void scanB(const int* __restrict__ psum, int* __restrict__ pbase) {
    if (threadIdx.x == 0) {
        int run = 0;
        for (int b = 0; b < NB0 + NB1 + NB2; b++) {
            if (b == 0 || b == NB0 || b == NB0 + NB1) run = 0;
            pbase[b] = run;
            run += psum[b];
        }
    }
}

__global__ void scanC(const int* __restrict__ d0, const int* __restrict__ d1,
                      const int* __restrict__ d2, const int* __restrict__ pbase,
                      int* __restrict__ rp0, int* __restrict__ rp1, int* __restrict__ rp2,
                      int* __restrict__ c0, int* __restrict__ c1, int* __restrict__ c2) {
    __shared__ int sh[512];
    const int* deg; int base, n, lb;
    seg_of(blockIdx.x, &deg, &base, &n, &lb, d0, d1, d2);
    int* rp; int* cur;
    if (blockIdx.x < NB0) { rp = rp0; cur = c0; }
    else if (blockIdx.x < NB0 + NB1) { rp = rp1; cur = c1; }
    else { rp = rp2; cur = c2; }
    int t = threadIdx.x;
    int v[4];
    int loc = 0;
#pragma unroll
    for (int k = 0; k < 4; k++) {
        int i = base + t * 4 + k;
        v[k] = (i < n) ? deg[i] : 0;
        loc += v[k];
    }
    sh[t] = loc;
    __syncthreads();
    // inclusive Hillis-Steele over 512 thread-sums
    for (int off = 1; off < 512; off <<= 1) {
        int x = (t >= off) ? sh[t - off] : 0;
        __syncthreads();
        sh[t] += x;
        __syncthreads();
    }
    int pre = (t ? sh[t - 1] : 0) + pbase[blockIdx.x];
#pragma unroll
    for (int k = 0; k < 4; k++) {
        int i = base + t * 4 + k;
        if (i < n) {
            cur[i] = pre;
            pre += v[k];
            rp[i + 1] = pre;
        }
    }
    if (lb == 0 && t == 0) rp[0] = 0;
}

__global__ void scatter3(const int* __restrict__ sw, const int* __restrict__ dw,
                         const int* __restrict__ sc, const int* __restrict__ dc,
                         const int* __restrict__ sb, const int* __restrict__ db, int E,
                         int* c0, int* c1, int* c2,
                         int* col0, int* col1, int* col2) {
    int i = blockIdx.x * blockDim.x + threadIdx.x;
    if (i < E) { int p = atomicAdd(&c0[dw[i]], 1); col0[p] = sw[i]; }
    else if (i < 2 * E) { int j = i - E; int p = atomicAdd(&c1[dc[j]], 1); col1[p] = sc[j]; }
    else if (i < 3 * E) { int j = i - 2 * E; int p = atomicAdd(&c2[db[j]], 1); col2[p] = sb[j]; }
}

// ---------------- aggregation with fp16 K/V gathers ----------------
__device__ __forceinline__ void csr_attend8h(
    int node, int lane, const int* __restrict__ rp, const int* __restrict__ colv,
    const __half* __restrict__ K, const __half* __restrict__ V,
    const float4 qa, const float4 qb, const float prih, float acc[8]) {
    float s = 0.f;
    float a[8];
#pragma unroll
    for (int j = 0; j < 8; j++) a[j] = 0.f;
    const int off = (lane >> 2) * DKH + (lane & 3) * 8;
    const int beg = rp[node], end = rp[node + 1];
    for (int e = beg; e < end; e++) {
        const int src = colv[e];
        uint4 kq = *(const uint4*)(K + (size_t)src * DD + off);
        const __half2* kh = (const __half2*)&kq;
        float2 k0 = __half22float2(kh[0]);
        float2 k1 = __half22float2(kh[1]);
        float2 k2 = __half22float2(kh[2]);
        float2 k3 = __half22float2(kh[3]);
        float p = qa.x * k0.x + qa.y * k0.y + qa.z * k1.x + qa.w * k1.y +
                  qb.x * k2.x + qb.y * k2.y + qb.z * k3.x + qb.w * k3.y;
        p += __shfl_xor_sync(0xffffffffu, p, 1);
        p += __shfl_xor_sync(0xffffffffu, p, 2);
        float wgt = __expf(p * prih);
        uint4 vq = *(const uint4*)(V + (size_t)src * DD + off);
        const __half2* vh = (const __half2*)&vq;
        float2 v0 = __half22float2(vh[0]);
        float2 v1 = __half22float2(vh[1]);
        float2 v2 = __half22float2(vh[2]);
        float2 v3 = __half22float2(vh[3]);
        s += wgt;
        a[0] += wgt * v0.x; a[1] += wgt * v0.y; a[2] += wgt * v1.x; a[3] += wgt * v1.y;
        a[4] += wgt * v2.x; a[5] += wgt * v2.y; a[6] += wgt * v3.x; a[7] += wgt * v3.y;
    }
    if (s > 0.f) {
        float inv = 1.f / s;
#pragma unroll
        for (int j = 0; j < 8; j++) acc[j] += a[j] * inv;
    }
}

__global__ void agg_all(const float* __restrict__ Qp, const float* __restrict__ Qpc,
                        const float* __restrict__ Qa,
                        const __half* __restrict__ K0, const __half* __restrict__ V0,
                        const __half* __restrict__ Kp, const __half* __restrict__ Vp,
                        const int* __restrict__ rp0, const int* __restrict__ col0,
                        const int* __restrict__ rp1, const int* __restrict__ col1,
                        const int* __restrict__ rp2, const int* __restrict__ col2,
                        const float* __restrict__ rel_pri,
                        float* __restrict__ aggw, float* __restrict__ aggc,
                        float* __restrict__ agga) {
    int w = (blockIdx.x * blockDim.x + threadIdx.x) >> 5;
    int lane = threadIdx.x & 31;
    const float sc = 0.17677669529663687f;
    const int h = lane >> 2;
    const int off = h * DKH + (lane & 3) * 8;
    if (w < NP) {
        const size_t qoff = (size_t)w * DD + off;
        {
            float4 qa = *(const float4*)(Qp + qoff);
            float4 qb = *(const float4*)(Qp + qoff + 4);
            float acc[8];
#pragma unroll
            for (int j = 0; j < 8; j++) acc[j] = 0.f;
            csr_attend8h(w, lane, rp0, col0, K0, V0, qa, qb, rel_pri[h] * sc, acc);
            float* o = aggw + qoff;
            *(float4*)o = make_float4(acc[0], acc[1], acc[2], acc[3]);
            *(float4*)(o + 4) = make_float4(acc[4], acc[5], acc[6], acc[7]);
        }
        {
            float4 qa = *(const float4*)(Qpc + qoff);
            float4 qb = *(const float4*)(Qpc + qoff + 4);
            float acc[8];
#pragma unroll
            for (int j = 0; j < 8; j++) acc[j] = 0.f;
            csr_attend8h(w, lane, rp1, col1, Kp, Vp, qa, qb, rel_pri[NH + h] * sc, acc);
            float* o = aggc + qoff;
            *(float4*)o = make_float4(acc[0], acc[1], acc[2], acc[3]);
            *(float4*)(o + 4) = make_float4(acc[4], acc[5], acc[6], acc[7]);
        }
    } else if (w < NP + NA) {
        int n = w - NP;
        const size_t qoff = (size_t)n * DD + off;
        float4 qa = *(const float4*)(Qa + qoff);
        float4 qb = *(const float4*)(Qa + qoff + 4);
        float acc[8];
#pragma unroll
        for (int j = 0; j < 8; j++) acc[j] = 0.f;
        csr_attend8h(n, lane, rp2, col2, Kp, Vp, qa, qb, rel_pri[2 * NH + h] * sc, acc);
        float* o = agga + qoff;
        *(float4*)o = make_float4(acc[0], acc[1], acc[2], acc[3]);
        *(float4*)(o + 4) = make_float4(acc[4], acc[5], acc[6], acc[7]);
    }
}

// ---------------- host launch ----------------
extern "C" void kernel_launch(void* const* d_in, const int* in_sizes, int n_in,
                              void* d_out, int out_size) {
    const float* h_author = (const float*)d_in[0];
    const float* h_paper  = (const float*)d_in[1];
    const float* k_w  = (const float*)d_in[2];
    const float* k_b  = (const float*)d_in[3];
    const float* q_w  = (const float*)d_in[4];
    const float* q_b  = (const float*)d_in[5];
    const float* v_w  = (const float*)d_in[6];
    const float* v_b  = (const float*)d_in[7];
    const float* a_w  = (const float*)d_in[8];
    const float* a_b  = (const float*)d_in[9];
    const float* rel_att = (const float*)d_in[10];
    const float* rel_msg = (const float*)d_in[11];
    const float* rel_pri = (const float*)d_in[12];
    const float* skipv   = (const float*)d_in[13];
    const int* src_writes = (const int*)d_in[14];
    const int* dst_writes = (const int*)d_in[15];
    const int* src_cites  = (const int*)d_in[16];
    const int* dst_cites  = (const int*)d_in[17];
    const int* src_wb     = (const int*)d_in[18];
    const int* dst_wb     = (const int*)d_in[19];

    int E = in_sizes[14];
    if (E > EMAX) E = EMAX;

    float *Har, *Hpr, *Qa, *Qp, *Qpc;
    __half *K0, *V0, *Kp, *Vp;
    float *aggPw, *aggPc, *aggP, *aggAc, *aggA, *fW, *fB, *rw;
    int *deg0, *deg1, *deg2, *rp0, *rp1, *rp2, *cur0, *cur1, *cur2, *col0, *col1, *col2;
    int *psum, *pbase;
    cudaGetSymbolAddress((void**)&Har, g_Har);
    cudaGetSymbolAddress((void**)&Hpr, g_Hpr);
    cudaGetSymbolAddress((void**)&K0, g_K0);
    cudaGetSymbolAddress((void**)&V0, g_V0);
    cudaGetSymbolAddress((void**)&Qa, g_Qa);
    cudaGetSymbolAddress((void**)&Kp, g_Kp);
    cudaGetSymbolAddress((void**)&Vp, g_Vp);
    cudaGetSymbolAddress((void**)&Qp, g_Qp);
    cudaGetSymbolAddress((void**)&Qpc, g_Qpc);
    cudaGetSymbolAddress((void**)&aggPw, g_aggPw);
    cudaGetSymbolAddress((void**)&aggPc, g_aggPc);
    cudaGetSymbolAddress((void**)&aggP, g_aggP);
    cudaGetSymbolAddress((void**)&aggAc, g_aggAc);
    cudaGetSymbolAddress((void**)&aggA, g_aggA);
    cudaGetSymbolAddress((void**)&fW, g_fW);
    cudaGetSymbolAddress((void**)&fB, g_fB);
    cudaGetSymbolAddress((void**)&rw, g_rw);
    cudaGetSymbolAddress((void**)&deg0, g_deg0);
    cudaGetSymbolAddress((void**)&deg1, g_deg1);
    cudaGetSymbolAddress((void**)&deg2, g_deg2);
    cudaGetSymbolAddress((void**)&rp0, g_rp0);
    cudaGetSymbolAddress((void**)&rp1, g_rp1);
    cudaGetSymbolAddress((void**)&rp2, g_rp2);
    cudaGetSymbolAddress((void**)&cur0, g_cur0);
    cudaGetSymbolAddress((void**)&cur1, g_cur1);
    cudaGetSymbolAddress((void**)&cur2, g_cur2);
    cudaGetSymbolAddress((void**)&col0, g_col0);
    cudaGetSymbolAddress((void**)&col1, g_col1);
    cudaGetSymbolAddress((void**)&col2, g_col2);
    cudaGetSymbolAddress((void**)&psum, g_psum);
    cudaGetSymbolAddress((void**)&pbase, g_pbase);

    cudaFuncSetAttribute(gemm_out, cudaFuncAttributeMaxDynamicSharedMemorySize, GSMEM);
    cudaFuncSetAttribute(gemm3f, cudaFuncAttributeMaxDynamicSharedMemorySize, GS3);

    float* kwr1 = rw + 0 * 65536;
    float* vwr1 = rw + 1 * 65536;
    float* qwr1 = rw + 2 * 65536;
    float* awr  = rw + 3 * 65536;
    float* fWk0 = fW + 0 * 65536;
    float* fWv0 = fW + 1 * 65536;
    float* fWqa = fW + 2 * 65536;
    float* fBk0 = fB + 0 * 256;
    float* fBv0 = fB + 1 * 256;
    float* fBqa = fB + 2 * 256;

    // 1) fused pre-round (6 regions)
    {
        int n0 = NA * DD / 4, n1 = NP * DD / 4, n2 = 65536 / 4, n3 = 65536 / 4,
            n4 = 65536 / 4, n5 = 131072 / 4;
        int total = n0 + n1 + n2 + n3 + n4 + n5;
        roundcopy_all<<<(total + 255) / 256, 256>>>(
            h_author, Har, n0, h_paper, Hpr, n1,
            k_w + 65536, kwr1, n2, v_w + 65536, vwr1, n3,
            q_w + 65536, qwr1, n4, a_w, awr, n5);
    }

    // 2) fused weight folds
    {
        dim3 g(256, 3);
        fold_all<<<g, 256>>>(k_w, v_w, q_w, k_b, v_b, q_b, rel_att, rel_msg,
                             fWk0, fWv0, fWqa, fBk0, fBv0, fBqa);
    }

    // 3) fused projection GEMM (K/V emitted fp16)
    const int gaB = (NA + 127) / 128, gpB = (NP + 127) / 128;
    {
        dim3 g(gaB + gpB, 2);
        gemm3f<<<g, 256, GS3>>>(gaB, Har, Hpr,
                                fWk0, fWv0, fWqa, kwr1, vwr1, qwr1,
                                fBk0, fBv0, fBqa, k_b + 256, v_b + 256, q_b + 256,
                                K0, V0, Qa, Kp, Vp, Qp, NA, NP);
    }

    // 4) Q transform for cites
    {
        dim3 g((NP + 63) / 64, NH);
        bdtrans<<<g, 256>>>(Qp, nullptr, rel_att + 8192, Qpc, NP, 0, 0);
    }

    // 5) CSR builds with wide scan
    zero3<<<(NP + 255) / 256, 256>>>(deg0, deg1, deg2);
    hist3<<<(3 * E + 255) / 256, 256>>>(dst_writes, dst_cites, dst_wb, E, deg0, deg1, deg2);
    scanA<<<NB0 + NB1 + NB2, 512>>>(deg0, deg1, deg2, psum);
    scanB<<<1, 32>>>(psum, pbase);
    scanC<<<NB0 + NB1 + NB2, 512>>>(deg0, deg1, deg2, pbase, rp0, rp1, rp2, cur0, cur1, cur2);
    scatter3<<<(3 * E + 255) / 256, 256>>>(src_writes, dst_writes, src_cites, dst_cites,
                                           src_wb, dst_wb, E, cur0, cur1, cur2, col0, col1, col2);

    // 6) fused attention aggregation (fp16 gathers)
    agg_all<<<((NP + NA) * 32 + 255) / 256, 256>>>(Qp, Qpc, Qa, K0, V0, Kp, Vp,
                                                   rp0, col0, rp1, col1, rp2, col2,
                                                   rel_pri, aggPw, aggPc, aggAc);

    // 7) post-agg message transforms
    {
        dim3 gp((NP + 63) / 64, NH), ga((NA + 63) / 64, NH);
        bdtrans<<<gp, 256>>>(aggPc, aggPw, rel_msg + 8192, aggP, NP, 1, 1);
        bdtrans<<<ga, 256>>>(aggAc, nullptr, rel_msg + 2 * 8192, aggA, NA, 1, 1);
    }

    // 8) fused output GEMM
    float* out = (float*)d_out;
    {
        dim3 g(gaB + gpB, 2);
        gemm_out<<<g, 256, GSMEM>>>(gaB, aggA, aggP, awr, awr + 65536, a_b, a_b + 256,
                                    h_author, h_paper, skipv, out, out + (size_t)NA * DD,
                                    NA, NP);
    }
}

// round 12
// speedup vs baseline: 1.4220x; 1.0260x over previous
#include <cuda_runtime.h>
#include <cuda_fp16.h>
#include <math.h>
#include <cstdint>

#define NA 20000
#define NP 50000
#define EMAX 300000
#define DD 256
#define NH 8
#define DKH 32

// ---------------- scratch ----------------
__device__ float g_Har[NA * DD];
__device__ float g_Hpr[NP * DD];
__device__ __half g_K0[NA * DD];
__device__ __half g_V0[NA * DD];
__device__ float g_Qa[NA * DD];
__device__ __half g_Kp[NP * DD];
__device__ __half g_Vp[NP * DD];
__device__ float g_Qp[NP * DD];
__device__ float g_Qpc[NP * DD];
__device__ float g_aggPw[NP * DD];
__device__ float g_aggPc[NP * DD];
__device__ float g_aggP[NP * DD];
__device__ float g_aggAc[NA * DD];
__device__ float g_aggA[NA * DD];
__device__ float g_fW[3 * DD * DD];
__device__ float g_fB[3 * DD];
__device__ float g_rw[5 * DD * DD];
__device__ int g_deg0[NP];
__device__ int g_deg1[NP];
__device__ int g_deg2[NA];
__device__ int g_rp0[NP + 1];
__device__ int g_rp1[NP + 1];
__device__ int g_rp2[NA + 1];
__device__ int g_cur0[NP];
__device__ int g_cur1[NP];
__device__ int g_cur2[NA];
__device__ int g_col0[EMAX];
__device__ int g_col1[EMAX];
__device__ int g_col2[EMAX];
__device__ int g_psum[64];
__device__ int g_pbase[64];

__device__ __forceinline__ float tf32r(float v) {
    uint32_t r;
    asm("cvt.rna.tf32.f32 %0, %1;" : "=r"(r) : "f"(v));
    return __uint_as_float(r);
}

// ---------------- fused round-copy over 6 regions ----------------
__global__ void roundcopy_all(
    const float* __restrict__ s0, float* __restrict__ d0, int n0,
    const float* __restrict__ s1, float* __restrict__ d1, int n1,
    const float* __restrict__ s2, float* __restrict__ d2, int n2,
    const float* __restrict__ s3, float* __restrict__ d3, int n3,
    const float* __restrict__ s4, float* __restrict__ d4, int n4,
    const float* __restrict__ s5, float* __restrict__ d5, int n5) {
    int i = blockIdx.x * blockDim.x + threadIdx.x;
    const float* s;
    float* d;
    if (i < n0) { s = s0; d = d0; }
    else if ((i -= n0) < n1) { s = s1; d = d1; }
    else if ((i -= n1) < n2) { s = s2; d = d2; }
    else if ((i -= n2) < n3) { s = s3; d = d3; }
    else if ((i -= n3) < n4) { s = s4; d = d4; }
    else if ((i -= n4) < n5) { s = s5; d = d5; }
    else return;
    float4 v = ((const float4*)s)[i];
    v.x = tf32r(v.x); v.y = tf32r(v.y); v.z = tf32r(v.z); v.w = tf32r(v.w);
    ((float4*)d)[i] = v;
}

// ---------------- fused weight folds (3 in one launch) ----------------
__global__ void fold_all(const float* __restrict__ k_w, const float* __restrict__ v_w,
                         const float* __restrict__ q_w,
                         const float* __restrict__ k_b, const float* __restrict__ v_b,
                         const float* __restrict__ q_b,
                         const float* __restrict__ rel_att, const float* __restrict__ rel_msg,
                         float* __restrict__ fWk0, float* __restrict__ fWv0,
                         float* __restrict__ fWqa,
                         float* __restrict__ fBk0, float* __restrict__ fBv0,
                         float* __restrict__ fBqa) {
    const int which = blockIdx.y;
    const float *W, *rel, *b;
    float *Wout, *bout;
    if (which == 0) { W = k_w; rel = rel_att; b = k_b; Wout = fWk0; bout = fBk0; }
    else if (which == 1) { W = v_w; rel = rel_msg; b = v_b; Wout = fWv0; bout = fBv0; }
    else { W = q_w; rel = rel_att + 2 * 8192; b = q_b; Wout = fWqa; bout = fBqa; }
    int c = blockIdx.x, d = threadIdx.x;
    int h = c >> 5, x = c & 31;
    float s = 0.f;
    if (which < 2) {
#pragma unroll
        for (int i = 0; i < 32; i++)
            s += rel[(h * 32 + i) * 32 + x] * W[(h * 32 + i) * DD + d];
    } else {
#pragma unroll
        for (int j = 0; j < 32; j++)
            s += rel[(h * 32 + x) * 32 + j] * W[(h * 32 + j) * DD + d];
    }
    Wout[c * DD + d] = tf32r(s);
    if (d == 0) {
        float sb = 0.f;
        if (which < 2) {
#pragma unroll
            for (int i = 0; i < 32; i++)
                sb += rel[(h * 32 + i) * 32 + x] * b[h * 32 + i];
        } else {
#pragma unroll
            for (int j = 0; j < 32; j++)
                sb += rel[(h * 32 + x) * 32 + j] * b[h * 32 + j];
        }
        bout[c] = sb;
    }
}

// ---------------- fast block-diagonal per-head transform ----------------
// One (node, head) per thread; warp shares a head so Ms reads are broadcast.
__device__ __forceinline__ void bdt_body(const float* __restrict__ in,
                                         const float* __restrict__ base,
                                         const float* __restrict__ Rh,
                                         float* __restrict__ out,
                                         int N, int h, int transp, int roundit) {
    __shared__ float Ms[1024];
    const int t = threadIdx.x;
    for (int k = t; k < 1024; k += 256) {
        int j = k >> 5, i = k & 31;
        Ms[k] = transp ? Rh[j * 32 + i] : Rh[i * 32 + j];
    }
    __syncthreads();
    int n = blockIdx.x * 256 + t;
    if (n >= N) return;
    const float* ip = in + (size_t)n * DD + h * 32;
    float iv[32];
#pragma unroll
    for (int k = 0; k < 8; k++) {
        float4 v = *(const float4*)(ip + k * 4);
        iv[4 * k] = v.x; iv[4 * k + 1] = v.y; iv[4 * k + 2] = v.z; iv[4 * k + 3] = v.w;
    }
    float ov[32];
#pragma unroll
    for (int i = 0; i < 32; i++) ov[i] = 0.f;
#pragma unroll
    for (int j = 0; j < 32; j++) {
#pragma unroll
        for (int i4 = 0; i4 < 8; i4++) {
            float4 m = *(const float4*)&Ms[j * 32 + i4 * 4];
            ov[i4 * 4 + 0] += iv[j] * m.x;
            ov[i4 * 4 + 1] += iv[j] * m.y;
            ov[i4 * 4 + 2] += iv[j] * m.z;
            ov[i4 * 4 + 3] += iv[j] * m.w;
        }
    }
    float* op = out + (size_t)n * DD + h * 32;
    const float* bp = base ? base + (size_t)n * DD + h * 32 : nullptr;
#pragma unroll
    for (int k = 0; k < 8; k++) {
        float4 v = make_float4(ov[4 * k], ov[4 * k + 1], ov[4 * k + 2], ov[4 * k + 3]);
        if (bp) {
            float4 b = *(const float4*)(bp + 4 * k);
            v.x += b.x; v.y += b.y; v.z += b.z; v.w += b.w;
        }
        if (roundit) { v.x = tf32r(v.x); v.y = tf32r(v.y); v.z = tf32r(v.z); v.w = tf32r(v.w); }
        *(float4*)(op + 4 * k) = v;
    }
}

// Qpc = per-head ratt1 * Qp (Q-side, transp=0, no round)
__global__ void bdtrans_q(const float* __restrict__ in, const float* __restrict__ R,
                          float* __restrict__ out, int N) {
    bdt_body(in, nullptr, R + blockIdx.y * 1024, out, N, blockIdx.y, 0, 0);
}

// fused post-agg transforms: y<8 papers (base=aggPw), y>=8 authors
__global__ void bdtrans_post(const float* __restrict__ inP, const float* __restrict__ baseP,
                             const float* __restrict__ RP, float* __restrict__ outP, int NPn,
                             const float* __restrict__ inA, const float* __restrict__ RA,
                             float* __restrict__ outA, int NAn) {
    int y = blockIdx.y;
    if (y < 8)
        bdt_body(inP, baseP, RP + y * 1024, outP, NPn, y, 1, 1);
    else
        bdt_body(inA, nullptr, RA + (y - 8) * 1024, outA, NAn, y - 8, 1, 1);
}

// ---------------- tf32 mma helpers ----------------
#define SLAB_F (128 * 36)
#define GSMEM (4 * SLAB_F * 4)
#define GS3 (8 * SLAB_F * 4)

__device__ __forceinline__ void mma1688(float c[4], const uint32_t a[4], const uint32_t b[2]) {
    asm volatile(
        "mma.sync.aligned.m16n8k8.row.col.f32.tf32.tf32.f32 "
        "{%0,%1,%2,%3}, {%4,%5,%6,%7}, {%8,%9}, {%0,%1,%2,%3};"
        : "+f"(c[0]), "+f"(c[1]), "+f"(c[2]), "+f"(c[3])
        : "r"(a[0]), "r"(a[1]), "r"(a[2]), "r"(a[3]), "r"(b[0]), "r"(b[1]));
}

// ---------------- fused out-GEMM (authors + papers) ----------------
__global__ __launch_bounds__(256) void gemm_out(
    int gaBlocks,
    const float* __restrict__ Aa, const float* __restrict__ Ap,
    const float* __restrict__ Ba, const float* __restrict__ Bp,
    const float* __restrict__ biasa, const float* __restrict__ biasp,
    const float* __restrict__ resida, const float* __restrict__ residp,
    const float* __restrict__ skipv,
    float* __restrict__ Ca, float* __restrict__ Cp, int Ma, int Mp) {
    extern __shared__ float sm[];
    const int tid = threadIdx.x;
    const bool pp = (int)blockIdx.x >= gaBlocks;
    const int m0 = ((int)blockIdx.x - (pp ? gaBlocks : 0)) * 128;
    const int col0 = blockIdx.y * 128;
    const float* A = pp ? Ap : Aa;
    const float* B = pp ? Bp : Ba;
    const float* bias = pp ? biasp : biasa;
    const float* resid = pp ? residp : resida;
    float* C = pp ? Cp : Ca;
    const int M = pp ? Mp : Ma;
    const int nid = pp ? 1 : 0;

    const int w = tid >> 5, ln = tid & 31;
    const int rowb = (w >> 2) * 64, colb = (w & 3) * 32;
    const int lg = ln >> 2, lt = ln & 3;

    float* const Ab[2] = {sm, sm + SLAB_F};
    float* const Bb[2] = {sm + 2 * SLAB_F, sm + 3 * SLAB_F};

    float c[4][4][4];
#pragma unroll
    for (int mi = 0; mi < 4; mi++)
#pragma unroll
        for (int ni = 0; ni < 4; ni++)
#pragma unroll
            for (int r = 0; r < 4; r++) c[mi][ni][r] = 0.f;

    auto load_slab = [&](int s, int b) {
        const int k0 = s * 32;
        float* As = Ab[b];
        float* Bs = Bb[b];
#pragma unroll
        for (int i = 0; i < 4; i++) {
            int idx = tid + i * 256;
            int row = idx >> 3, kg = idx & 7;
            uint32_t da = (uint32_t)__cvta_generic_to_shared(As + row * 36 + kg * 4);
            const float* ga = A + (size_t)(m0 + row) * DD + k0 + kg * 4;
            int sz = ((m0 + row) < M) ? 16 : 0;
            asm volatile("cp.async.cg.shared.global [%0], [%1], 16, %2;\n" ::"r"(da), "l"(ga), "r"(sz));
            uint32_t db = (uint32_t)__cvta_generic_to_shared(Bs + row * 36 + kg * 4);
            const float* gb = B + (size_t)(col0 + row) * DD + k0 + kg * 4;
            asm volatile("cp.async.cg.shared.global [%0], [%1], 16;\n" ::"r"(db), "l"(gb));
        }
        asm volatile("cp.async.commit_group;\n");
    };

    load_slab(0, 0);
    for (int s = 0; s < 8; s++) {
        int b = s & 1;
        if (s < 7) {
            load_slab(s + 1, b ^ 1);
            asm volatile("cp.async.wait_group 1;\n");
        } else {
            asm volatile("cp.async.wait_group 0;\n");
        }
        __syncthreads();
        const float* As = Ab[b];
        const float* Bs = Bb[b];
#pragma unroll
        for (int ks = 0; ks < 4; ks++) {
            const int kk = ks * 8 + lt;
            uint32_t af[4][4], bf[4][2];
#pragma unroll
            for (int mi = 0; mi < 4; mi++) {
                const float* p = As + (rowb + mi * 16 + lg) * 36 + kk;
                af[mi][0] = __float_as_uint(p[0]);
                af[mi][1] = __float_as_uint(p[8 * 36]);
                af[mi][2] = __float_as_uint(p[4]);
                af[mi][3] = __float_as_uint(p[8 * 36 + 4]);
            }
#pragma unroll
            for (int ni = 0; ni < 4; ni++) {
                const float* p = Bs + (colb + ni * 8 + lg) * 36 + kk;
                bf[ni][0] = __float_as_uint(p[0]);
                bf[ni][1] = __float_as_uint(p[4]);
            }
#pragma unroll
            for (int mi = 0; mi < 4; mi++)
#pragma unroll
                for (int ni = 0; ni < 4; ni++) mma1688(c[mi][ni], af[mi], bf[ni]);
        }
        __syncthreads();
    }

    float sv = skipv[nid];
    float alpha = 1.f / (1.f + __expf(-sv));
    float beta = 1.f - alpha;
#pragma unroll
    for (int mi = 0; mi < 4; mi++) {
#pragma unroll
        for (int half = 0; half < 2; half++) {
            int row = m0 + rowb + mi * 16 + lg + half * 8;
            if (row >= M) continue;
#pragma unroll
            for (int ni = 0; ni < 4; ni++) {
                int cc = col0 + colb + ni * 8 + lt * 2;
                float2 o;
                o.x = c[mi][ni][half * 2 + 0] + bias[cc];
                o.y = c[mi][ni][half * 2 + 1] + bias[cc + 1];
                float2 rv = *(const float2*)(resid + (size_t)row * DD + cc);
                o.x = o.x * alpha + rv.x * beta;
                o.y = o.y * alpha + rv.y * beta;
                *(float2*)(C + (size_t)row * DD + cc) = o;
            }
        }
    }
}

// ---------------- fused 3-B projection GEMM; K/V outputs stored fp16 ----------------
__global__ __launch_bounds__(256, 1) void gemm3f(
    int gaBlocks,
    const float* __restrict__ Aa, const float* __restrict__ Ap,
    const float* __restrict__ Ba0, const float* __restrict__ Ba1, const float* __restrict__ Ba2,
    const float* __restrict__ Bp0, const float* __restrict__ Bp1, const float* __restrict__ Bp2,
    const float* __restrict__ ba0, const float* __restrict__ ba1, const float* __restrict__ ba2,
    const float* __restrict__ bp0, const float* __restrict__ bp1, const float* __restrict__ bp2,
    __half* __restrict__ CaK, __half* __restrict__ CaV, float* __restrict__ CaQ,
    __half* __restrict__ CpK, __half* __restrict__ CpV, float* __restrict__ CpQ,
    int Ma, int Mp) {
    extern __shared__ float sm[];
    const int tid = threadIdx.x;
    const bool pp = (int)blockIdx.x >= gaBlocks;
    const int m0 = ((int)blockIdx.x - (pp ? gaBlocks : 0)) * 128;
    const int col0 = blockIdx.y * 128;
    const float* A = pp ? Ap : Aa;
    const int M = pp ? Mp : Ma;
    const float* const Bv[3] = {pp ? Bp0 : Ba0, pp ? Bp1 : Ba1, pp ? Bp2 : Ba2};
    const float* const biv[3] = {pp ? bp0 : ba0, pp ? bp1 : ba1, pp ? bp2 : ba2};
    __half* const Chv[2] = {pp ? CpK : CaK, pp ? CpV : CaV};
    float* const Cq = pp ? CpQ : CaQ;

    const int w = tid >> 5, ln = tid & 31;
    const int rowb = (w >> 2) * 64, colb = (w & 3) * 32;
    const int lg = ln >> 2, lt = ln & 3;

    float c[3][4][4][4];
#pragma unroll
    for (int b = 0; b < 3; b++)
#pragma unroll
        for (int mi = 0; mi < 4; mi++)
#pragma unroll
            for (int ni = 0; ni < 4; ni++)
#pragma unroll
                for (int r = 0; r < 4; r++) c[b][mi][ni][r] = 0.f;

    auto load_slab = [&](int s, int buf) {
        const int k0 = s * 32;
        float* As = sm + buf * SLAB_F;
#pragma unroll
        for (int i = 0; i < 4; i++) {
            int idx = tid + i * 256;
            int row = idx >> 3, kg = idx & 7;
            uint32_t da = (uint32_t)__cvta_generic_to_shared(As + row * 36 + kg * 4);
            const float* ga = A + (size_t)(m0 + row) * DD + k0 + kg * 4;
            int sz = ((m0 + row) < M) ? 16 : 0;
            asm volatile("cp.async.cg.shared.global [%0], [%1], 16, %2;\n" ::"r"(da), "l"(ga), "r"(sz));
        }
#pragma unroll
        for (int b = 0; b < 3; b++) {
            float* Bs = sm + (2 + b * 2 + buf) * SLAB_F;
#pragma unroll
            for (int i = 0; i < 4; i++) {
                int idx = tid + i * 256;
                int row = idx >> 3, kg = idx & 7;
                uint32_t db = (uint32_t)__cvta_generic_to_shared(Bs + row * 36 + kg * 4);
                const float* gb = Bv[b] + (size_t)(col0 + row) * DD + k0 + kg * 4;
                asm volatile("cp.async.cg.shared.global [%0], [%1], 16;\n" ::"r"(db), "l"(gb));
            }
        }
        asm volatile("cp.async.commit_group;\n");
    };

    load_slab(0, 0);
    for (int s = 0; s < 8; s++) {
        int buf = s & 1;
        if (s < 7) {
            load_slab(s + 1, buf ^ 1);
            asm volatile("cp.async.wait_group 1;\n");
        } else {
            asm volatile("cp.async.wait_group 0;\n");
        }
        __syncthreads();
        const float* As = sm + buf * SLAB_F;
#pragma unroll
        for (int ks = 0; ks < 4; ks++) {
            const int kk = ks * 8 + lt;
            uint32_t af[4][4];
#pragma unroll
            for (int mi = 0; mi < 4; mi++) {
                const float* p = As + (rowb + mi * 16 + lg) * 36 + kk;
                af[mi][0] = __float_as_uint(p[0]);
                af[mi][1] = __float_as_uint(p[8 * 36]);
                af[mi][2] = __float_as_uint(p[4]);
                af[mi][3] = __float_as_uint(p[8 * 36 + 4]);
            }
#pragma unroll
            for (int b = 0; b < 3; b++) {
                const float* Bs = sm + (2 + b * 2 + buf) * SLAB_F;
                uint32_t bf[4][2];
#pragma unroll
                for (int ni = 0; ni < 4; ni++) {
                    const float* p = Bs + (colb + ni * 8 + lg) * 36 + kk;
                    bf[ni][0] = __float_as_uint(p[0]);
                    bf[ni][1] = __float_as_uint(p[4]);
                }
#pragma unroll
                for (int mi = 0; mi < 4; mi++)
#pragma unroll
                    for (int ni = 0; ni < 4; ni++) mma1688(c[b][mi][ni], af[mi], bf[ni]);
            }
        }
        __syncthreads();
    }

#pragma unroll
    for (int b = 0; b < 3; b++) {
#pragma unroll
        for (int mi = 0; mi < 4; mi++) {
#pragma unroll
            for (int half = 0; half < 2; half++) {
                int row = m0 + rowb + mi * 16 + lg + half * 8;
                if (row >= M) continue;
#pragma unroll
                for (int ni = 0; ni < 4; ni++) {
                    int cc = col0 + colb + ni * 8 + lt * 2;
                    float ox = c[b][mi][ni][half * 2 + 0] + biv[b][cc];
                    float oy = c[b][mi][ni][half * 2 + 1] + biv[b][cc + 1];
                    if (b < 2) {
                        *(__half2*)(Chv[b] + (size_t)row * DD + cc) = __floats2half2_rn(ox, oy);
                    } else {
                        *(float2*)(Cq + (size_t)row * DD + cc) = make_float2(ox, oy);
                    }
                }
            }
        }
    }
}

// ---------------- CSR build ----------------
__global__ void zero3(int* d0, int* d1, int* d2) {
    int i = blockIdx.x * blockDim.x + threadIdx.x;
    if (i < NP) { d0[i] = 0; d1[i] = 0; }
    if (i < NA) d2[i] = 0;
}

__global__ void hist3(const int* __restrict__ dw, const int* __restrict__ dc,
                      const int* __restrict__ db, int E,
                      int* d0, int* d1, int* d2) {
    int i = blockIdx.x * blockDim.x + threadIdx.x;
    if (i < E) atomicAdd(&d0[dw[i]], 1);
    else if (i < 2 * E) atomicAdd(&d1[dc[i - E]], 1);
    else if (i < 3 * E) atomicAdd(&d2[db[i - 2 * E]], 1);
}

#define BLKE 2048
#define NB0 25
#define NB1 25
#define NB2 10

__device__ __forceinline__ void seg_of(int b, const int** deg, int* base, int* n, int* lb,
                                       const int* d0, const int* d1, const int* d2) {
    if (b < NB0) { *deg = d0; *lb = b; *n = NP; }
    else if (b < NB0 + NB1) { *deg = d1; *lb = b - NB0; *n = NP; }
    else { *deg = d2; *lb = b - NB0 - NB1; *n = NA; }
    *base = *lb * BLKE;
}

__global__ void scanA(const int* __restrict__ d0, const int* __restrict__ d1,
                      const int* __restrict__ d2, int* __restrict__ psum) {
    __shared__ int sh[512];
    const int* deg; int base, n, lb;
    seg_of(blockIdx.x, &deg, &base, &n, &lb, d0, d1, d2);
    int t = threadIdx.x;
    int s = 0;
#pragma unroll
    for (int k = 0; k < 4; k++) {
        int i = base + t * 4 + k;
        if (i < n && t * 4 + k < BLKE) s += deg[i];
    }
    sh[t] = s;
    __syncthreads();
    for (int off = 256; off; off >>= 1) {
        if (t < off) sh[t] += sh[t + off];
        __syncthreads();
    }
    if (t == 0) psum[blockIdx.x] = sh[0];
}

__global__ void scanB(const int* __restrict__ psum, int* __restrict__ pbase) {
    if (threadIdx.x == 0) {
        int run = 0;
        for (int b = 0; b < NB0 + NB1 + NB2; b++) {
            if (b == 0 || b == NB0 || b == NB0 + NB1) run = 0;
            pbase[b] = run;
            run += psum[b];
        }
    }
}

__global__ void scanC(const int* __restrict__ d0, const int* __restrict__ d1,
                      const int* __restrict__ d2, const int* __restrict__ pbase,
                      int* __restrict__ rp0, int* __restrict__ rp1, int* __restrict__ rp2,
                      int* __restrict__ c0, int* __restrict__ c1, int* __restrict__ c2) {
    __shared__ int sh[512];
    const int* deg; int base, n, lb;
    seg_of(blockIdx.x, &deg, &base, &n, &lb, d0, d1, d2);
    int* rp; int* cur;
    if (blockIdx.x < NB0) { rp = rp0; cur = c0; }
    else if (blockIdx.x < NB0 + NB1) { rp = rp1; cur = c1; }
    else { rp = rp2; cur = c2; }
    int t = threadIdx.x;
    int v[4];
    int loc = 0;
#pragma unroll
    for (int k = 0; k < 4; k++) {
        int i = base + t * 4 + k;
        v[k] = (i < n) ? deg[i] : 0;
        loc += v[k];
    }
    sh[t] = loc;
    __syncthreads();
    for (int off = 1; off < 512; off <<= 1) {
        int x = (t >= off) ? sh[t - off] : 0;
        __syncthreads();
        sh[t] += x;
        __syncthreads();
    }
    int pre = (t ? sh[t - 1] : 0) + pbase[blockIdx.x];
#pragma unroll
    for (int k = 0; k < 4; k++) {
        int i = base + t * 4 + k;
        if (i < n) {
            cur[i] = pre;
            pre += v[k];
            rp[i + 1] = pre;
        }
    }
    if (lb == 0 && t == 0) rp[0] = 0;
}

__global__ void scatter3(const int* __restrict__ sw, const int* __restrict__ dw,
                         const int* __restrict__ sc, const int* __restrict__ dc,
                         const int* __restrict__ sb, const int* __restrict__ db, int E,
                         int* c0, int* c1, int* c2,
                         int* col0, int* col1, int* col2) {
    int i = blockIdx.x * blockDim.x + threadIdx.x;
    if (i < E) { int p = atomicAdd(&c0[dw[i]], 1); col0[p] = sw[i]; }
    else if (i < 2 * E) { int j = i - E; int p = atomicAdd(&c1[dc[j]], 1); col1[p] = sc[j]; }
    else if (i < 3 * E) { int j = i - 2 * E; int p = atomicAdd(&c2[db[j]], 1); col2[p] = sb[j]; }
}

// ---------------- aggregation with fp16 K/V gathers ----------------
__device__ __forceinline__ void csr_attend8h(
    int node, int lane, const int* __restrict__ rp, const int* __restrict__ colv,
    const __half* __restrict__ K, const __half* __restrict__ V,
    const float4 qa, const float4 qb, const float prih, float acc[8]) {
    float s = 0.f;
    float a[8];
#pragma unroll
    for (int j = 0; j < 8; j++) a[j] = 0.f;
    const int off = (lane >> 2) * DKH + (lane & 3) * 8;
    const int beg = rp[node], end = rp[node + 1];
    for (int e = beg; e < end; e++) {
        const int src = colv[e];
        uint4 kq = *(const uint4*)(K + (size_t)src * DD + off);
        const __half2* kh = (const __half2*)&kq;
        float2 k0 = __half22float2(kh[0]);
        float2 k1 = __half22float2(kh[1]);
        float2 k2 = __half22float2(kh[2]);
        float2 k3 = __half22float2(kh[3]);
        float p = qa.x * k0.x + qa.y * k0.y + qa.z * k1.x + qa.w * k1.y +
                  qb.x * k2.x + qb.y * k2.y + qb.z * k3.x + qb.w * k3.y;
        p += __shfl_xor_sync(0xffffffffu, p, 1);
        p += __shfl_xor_sync(0xffffffffu, p, 2);
        float wgt = __expf(p * prih);
        uint4 vq = *(const uint4*)(V + (size_t)src * DD + off);
        const __half2* vh = (const __half2*)&vq;
        float2 v0 = __half22float2(vh[0]);
        float2 v1 = __half22float2(vh[1]);
        float2 v2 = __half22float2(vh[2]);
        float2 v3 = __half22float2(vh[3]);
        s += wgt;
        a[0] += wgt * v0.x; a[1] += wgt * v0.y; a[2] += wgt * v1.x; a[3] += wgt * v1.y;
        a[4] += wgt * v2.x; a[5] += wgt * v2.y; a[6] += wgt * v3.x; a[7] += wgt * v3.y;
    }
    if (s > 0.f) {
        float inv = 1.f / s;
#pragma unroll
        for (int j = 0; j < 8; j++) acc[j] += a[j] * inv;
    }
}

__global__ void agg_all(const float* __restrict__ Qp, const float* __restrict__ Qpc,
                        const float* __restrict__ Qa,
                        const __half* __restrict__ K0, const __half* __restrict__ V0,
                        const __half* __restrict__ Kp, const __half* __restrict__ Vp,
                        const int* __restrict__ rp0, const int* __restrict__ col0,
                        const int* __restrict__ rp1, const int* __restrict__ col1,
                        const int* __restrict__ rp2, const int* __restrict__ col2,
                        const float* __restrict__ rel_pri,
                        float* __restrict__ aggw, float* __restrict__ aggc,
                        float* __restrict__ agga) {
    int w = (blockIdx.x * blockDim.x + threadIdx.x) >> 5;
    int lane = threadIdx.x & 31;
    const float sc = 0.17677669529663687f;
    const int h = lane >> 2;
    const int off = h * DKH + (lane & 3) * 8;
    if (w < NP) {
        const size_t qoff = (size_t)w * DD + off;
        {
            float4 qa = *(const float4*)(Qp + qoff);
            float4 qb = *(const float4*)(Qp + qoff + 4);
            float acc[8];
#pragma unroll
            for (int j = 0; j < 8; j++) acc[j] = 0.f;
            csr_attend8h(w, lane, rp0, col0, K0, V0, qa, qb, rel_pri[h] * sc, acc);
            float* o = aggw + qoff;
            *(float4*)o = make_float4(acc[0], acc[1], acc[2], acc[3]);
            *(float4*)(o + 4) = make_float4(acc[4], acc[5], acc[6], acc[7]);
        }
        {
            float4 qa = *(const float4*)(Qpc + qoff);
            float4 qb = *(const float4*)(Qpc + qoff + 4);
            float acc[8];
#pragma unroll
            for (int j = 0; j < 8; j++) acc[j] = 0.f;
            csr_attend8h(w, lane, rp1, col1, Kp, Vp, qa, qb, rel_pri[NH + h] * sc, acc);
            float* o = aggc + qoff;
            *(float4*)o = make_float4(acc[0], acc[1], acc[2], acc[3]);
            *(float4*)(o + 4) = make_float4(acc[4], acc[5], acc[6], acc[7]);
        }
    } else if (w < NP + NA) {
        int n = w - NP;
        const size_t qoff = (size_t)n * DD + off;
        float4 qa = *(const float4*)(Qa + qoff);
        float4 qb = *(const float4*)(Qa + qoff + 4);
        float acc[8];
#pragma unroll
        for (int j = 0; j < 8; j++) acc[j] = 0.f;
        csr_attend8h(n, lane, rp2, col2, Kp, Vp, qa, qb, rel_pri[2 * NH + h] * sc, acc);
        float* o = agga + qoff;
        *(float4*)o = make_float4(acc[0], acc[1], acc[2], acc[3]);
        *(float4*)(o + 4) = make_float4(acc[4], acc[5], acc[6], acc[7]);
    }
}

// ---------------- host launch ----------------
extern "C" void kernel_launch(void* const* d_in, const int* in_sizes, int n_in,
                              void* d_out, int out_size) {
    const float* h_author = (const float*)d_in[0];
    const float* h_paper  = (const float*)d_in[1];
    const float* k_w  = (const float*)d_in[2];
    const float* k_b  = (const float*)d_in[3];
    const float* q_w  = (const float*)d_in[4];
    const float* q_b  = (const float*)d_in[5];
    const float* v_w  = (const float*)d_in[6];
    const float* v_b  = (const float*)d_in[7];
    const float* a_w  = (const float*)d_in[8];
    const float* a_b  = (const float*)d_in[9];
    const float* rel_att = (const float*)d_in[10];
    const float* rel_msg = (const float*)d_in[11];
    const float* rel_pri = (const float*)d_in[12];
    const float* skipv   = (const float*)d_in[13];
    const int* src_writes = (const int*)d_in[14];
    const int* dst_writes = (const int*)d_in[15];
    const int* src_cites  = (const int*)d_in[16];
    const int* dst_cites  = (const int*)d_in[17];
    const int* src_wb     = (const int*)d_in[18];
    const int* dst_wb     = (const int*)d_in[19];

    int E = in_sizes[14];
    if (E > EMAX) E = EMAX;

    float *Har, *Hpr, *Qa, *Qp, *Qpc;
    __half *K0, *V0, *Kp, *Vp;
    float *aggPw, *aggPc, *aggP, *aggAc, *aggA, *fW, *fB, *rw;
    int *deg0, *deg1, *deg2, *rp0, *rp1, *rp2, *cur0, *cur1, *cur2, *col0, *col1, *col2;
    int *psum, *pbase;
    cudaGetSymbolAddress((void**)&Har, g_Har);
    cudaGetSymbolAddress((void**)&Hpr, g_Hpr);
    cudaGetSymbolAddress((void**)&K0, g_K0);
    cudaGetSymbolAddress((void**)&V0, g_V0);
    cudaGetSymbolAddress((void**)&Qa, g_Qa);
    cudaGetSymbolAddress((void**)&Kp, g_Kp);
    cudaGetSymbolAddress((void**)&Vp, g_Vp);
    cudaGetSymbolAddress((void**)&Qp, g_Qp);
    cudaGetSymbolAddress((void**)&Qpc, g_Qpc);
    cudaGetSymbolAddress((void**)&aggPw, g_aggPw);
    cudaGetSymbolAddress((void**)&aggPc, g_aggPc);
    cudaGetSymbolAddress((void**)&aggP, g_aggP);
    cudaGetSymbolAddress((void**)&aggAc, g_aggAc);
    cudaGetSymbolAddress((void**)&aggA, g_aggA);
    cudaGetSymbolAddress((void**)&fW, g_fW);
    cudaGetSymbolAddress((void**)&fB, g_fB);
    cudaGetSymbolAddress((void**)&rw, g_rw);
    cudaGetSymbolAddress((void**)&deg0, g_deg0);
    cudaGetSymbolAddress((void**)&deg1, g_deg1);
    cudaGetSymbolAddress((void**)&deg2, g_deg2);
    cudaGetSymbolAddress((void**)&rp0, g_rp0);
    cudaGetSymbolAddress((void**)&rp1, g_rp1);
    cudaGetSymbolAddress((void**)&rp2, g_rp2);
    cudaGetSymbolAddress((void**)&cur0, g_cur0);
    cudaGetSymbolAddress((void**)&cur1, g_cur1);
    cudaGetSymbolAddress((void**)&cur2, g_cur2);
    cudaGetSymbolAddress((void**)&col0, g_col0);
    cudaGetSymbolAddress((void**)&col1, g_col1);
    cudaGetSymbolAddress((void**)&col2, g_col2);
    cudaGetSymbolAddress((void**)&psum, g_psum);
    cudaGetSymbolAddress((void**)&pbase, g_pbase);

    cudaFuncSetAttribute(gemm_out, cudaFuncAttributeMaxDynamicSharedMemorySize, GSMEM);
    cudaFuncSetAttribute(gemm3f, cudaFuncAttributeMaxDynamicSharedMemorySize, GS3);

    float* kwr1 = rw + 0 * 65536;
    float* vwr1 = rw + 1 * 65536;
    float* qwr1 = rw + 2 * 65536;
    float* awr  = rw + 3 * 65536;
    float* fWk0 = fW + 0 * 65536;
    float* fWv0 = fW + 1 * 65536;
    float* fWqa = fW + 2 * 65536;
    float* fBk0 = fB + 0 * 256;
    float* fBv0 = fB + 1 * 256;
    float* fBqa = fB + 2 * 256;

    // 1) fused pre-round (6 regions)
    {
        int n0 = NA * DD / 4, n1 = NP * DD / 4, n2 = 65536 / 4, n3 = 65536 / 4,
            n4 = 65536 / 4, n5 = 131072 / 4;
        int total = n0 + n1 + n2 + n3 + n4 + n5;
        roundcopy_all<<<(total + 255) / 256, 256>>>(
            h_author, Har, n0, h_paper, Hpr, n1,
            k_w + 65536, kwr1, n2, v_w + 65536, vwr1, n3,
            q_w + 65536, qwr1, n4, a_w, awr, n5);
    }

    // 2) fused weight folds
    {
        dim3 g(256, 3);
        fold_all<<<g, 256>>>(k_w, v_w, q_w, k_b, v_b, q_b, rel_att, rel_msg,
                             fWk0, fWv0, fWqa, fBk0, fBv0, fBqa);
    }

    // 3) fused projection GEMM (K/V emitted fp16)
    const int gaB = (NA + 127) / 128, gpB = (NP + 127) / 128;
    {
        dim3 g(gaB + gpB, 2);
        gemm3f<<<g, 256, GS3>>>(gaB, Har, Hpr,
                                fWk0, fWv0, fWqa, kwr1, vwr1, qwr1,
                                fBk0, fBv0, fBqa, k_b + 256, v_b + 256, q_b + 256,
                                K0, V0, Qa, Kp, Vp, Qp, NA, NP);
    }

    // 4) Q transform for cites (fast register/broadcast version)
    {
        dim3 g((NP + 255) / 256, NH);
        bdtrans_q<<<g, 256>>>(Qp, rel_att + 8192, Qpc, NP);
    }

    // 5) CSR builds with wide scan
    zero3<<<(NP + 255) / 256, 256>>>(deg0, deg1, deg2);
    hist3<<<(3 * E + 255) / 256, 256>>>(dst_writes, dst_cites, dst_wb, E, deg0, deg1, deg2);
    scanA<<<NB0 + NB1 + NB2, 512>>>(deg0, deg1, deg2, psum);
    scanB<<<1, 32>>>(psum, pbase);
    scanC<<<NB0 + NB1 + NB2, 512>>>(deg0, deg1, deg2, pbase, rp0, rp1, rp2, cur0, cur1, cur2);
    scatter3<<<(3 * E + 255) / 256, 256>>>(src_writes, dst_writes, src_cites, dst_cites,
                                           src_wb, dst_wb, E, cur0, cur1, cur2, col0, col1, col2);

    // 6) fused attention aggregation (fp16 gathers)
    agg_all<<<((NP + NA) * 32 + 255) / 256, 256>>>(Qp, Qpc, Qa, K0, V0, Kp, Vp,
                                                   rp0, col0, rp1, col1, rp2, col2,
                                                   rel_pri, aggPw, aggPc, aggAc);

    // 7) fused post-agg message transforms (fast version, one launch)
    {
        dim3 g((NP + 255) / 256, 16);
        bdtrans_post<<<g, 256>>>(aggPc, aggPw, rel_msg + 8192, aggP, NP,
                                 aggAc, rel_msg + 2 * 8192, aggA, NA);
    }

    // 8) fused output GEMM
    float* out = (float*)d_out;
    {
        dim3 g(gaB + gpB, 2);
        gemm_out<<<g, 256, GSMEM>>>(gaB, aggA, aggP, awr, awr + 65536, a_b, a_b + 256,
                                    h_author, h_paper, skipv, out, out + (size_t)NA * DD,
                                    NA, NP);
    }
}

// round 14
// speedup vs baseline: 1.4545x; 1.0229x over previous
#include <cuda_runtime.h>
#include <cuda_fp16.h>
#include <math.h>
#include <cstdint>

#define NA 20000
#define NP 50000
#define EMAX 300000
#define DD 256
#define NH 8
#define DKH 32

// ---------------- scratch ----------------
__device__ float g_Har[NA * DD];
__device__ float g_Hpr[NP * DD];
__device__ __half g_K0[NA * DD];
__device__ __half g_V0[NA * DD];
__device__ float g_Qa[NA * DD];
__device__ __half g_Kp[NP * DD];
__device__ __half g_Vp[NP * DD];
__device__ float g_Qp[NP * DD];
__device__ float g_Qpc[NP * DD];
__device__ float g_aggPw[NP * DD];
__device__ float g_aggPc[NP * DD];
__device__ float g_aggP[NP * DD];
__device__ float g_aggAc[NA * DD];
__device__ float g_fW[4 * DD * DD];
__device__ float g_fB[3 * DD];
__device__ float g_rw[4 * DD * DD];
__device__ int g_deg0[NP];
__device__ int g_deg1[NP];
__device__ int g_deg2[NA];
__device__ int g_rp0[NP + 1];
__device__ int g_rp1[NP + 1];
__device__ int g_rp2[NA + 1];
__device__ int g_cur0[NP];
__device__ int g_cur1[NP];
__device__ int g_cur2[NA];
__device__ int g_col0[EMAX];
__device__ int g_col1[EMAX];
__device__ int g_col2[EMAX];
__device__ int g_psum[64];
__device__ int g_pbase[64];

__device__ __forceinline__ float tf32r(float v) {
    uint32_t r;
    asm("cvt.rna.tf32.f32 %0, %1;" : "=r"(r) : "f"(v));
    return __uint_as_float(r);
}

// ---------------- fused round-copy over 6 regions ----------------
__global__ void roundcopy_all(
    const float* __restrict__ s0, float* __restrict__ d0, int n0,
    const float* __restrict__ s1, float* __restrict__ d1, int n1,
    const float* __restrict__ s2, float* __restrict__ d2, int n2,
    const float* __restrict__ s3, float* __restrict__ d3, int n3,
    const float* __restrict__ s4, float* __restrict__ d4, int n4,
    const float* __restrict__ s5, float* __restrict__ d5, int n5) {
    int i = blockIdx.x * blockDim.x + threadIdx.x;
    const float* s;
    float* d;
    if (i < n0) { s = s0; d = d0; }
    else if ((i -= n0) < n1) { s = s1; d = d1; }
    else if ((i -= n1) < n2) { s = s2; d = d2; }
    else if ((i -= n2) < n3) { s = s3; d = d3; }
    else if ((i -= n3) < n4) { s = s4; d = d4; }
    else if ((i -= n4) < n5) { s = s5; d = d5; }
    else return;
    float4 v = ((const float4*)s)[i];
    v.x = tf32r(v.x); v.y = tf32r(v.y); v.z = tf32r(v.z); v.w = tf32r(v.w);
    ((float4*)d)[i] = v;
}

// ---------------- fused weight folds (4 in one launch) ----------------
__global__ void fold_all(const float* __restrict__ k_w, const float* __restrict__ v_w,
                         const float* __restrict__ q_w, const float* __restrict__ a_w,
                         const float* __restrict__ k_b, const float* __restrict__ v_b,
                         const float* __restrict__ q_b,
                         const float* __restrict__ rel_att, const float* __restrict__ rel_msg,
                         float* __restrict__ fWk0, float* __restrict__ fWv0,
                         float* __restrict__ fWqa, float* __restrict__ fWaw,
                         float* __restrict__ fBk0, float* __restrict__ fBv0,
                         float* __restrict__ fBqa) {
    const int which = blockIdx.y;
    int c = blockIdx.x, d = threadIdx.x;
    int h = c >> 5, x = c & 31;
    if (which == 3) {
        // fWaw[d][c] = sum_i rmsg2[h][x][i] * a_w0[d][h*32+i]
        const float* rel = rel_msg + 2 * 8192;
        float s = 0.f;
#pragma unroll
        for (int i = 0; i < 32; i++)
            s += rel[c * 32 + i] * a_w[d * DD + h * 32 + i];
        fWaw[d * DD + c] = tf32r(s);
        return;
    }
    const float *W, *rel, *b;
    float *Wout, *bout;
    if (which == 0) { W = k_w; rel = rel_att; b = k_b; Wout = fWk0; bout = fBk0; }
    else if (which == 1) { W = v_w; rel = rel_msg; b = v_b; Wout = fWv0; bout = fBv0; }
    else { W = q_w; rel = rel_att + 2 * 8192; b = q_b; Wout = fWqa; bout = fBqa; }
    float s = 0.f;
    if (which < 2) {
#pragma unroll
        for (int i = 0; i < 32; i++)
            s += rel[(h * 32 + i) * 32 + x] * W[(h * 32 + i) * DD + d];
    } else {
#pragma unroll
        for (int j = 0; j < 32; j++)
            s += rel[(h * 32 + x) * 32 + j] * W[(h * 32 + j) * DD + d];
    }
    Wout[c * DD + d] = tf32r(s);
    if (d == 0) {
        float sb = 0.f;
        if (which < 2) {
#pragma unroll
            for (int i = 0; i < 32; i++)
                sb += rel[(h * 32 + i) * 32 + x] * b[h * 32 + i];
        } else {
#pragma unroll
            for (int j = 0; j < 32; j++)
                sb += rel[(h * 32 + x) * 32 + j] * b[h * 32 + j];
        }
        bout[c] = sb;
    }
}

// ---------------- SMEM-staged block-diagonal per-head transform (coalesced, pitch 36) ----------------
#define BDP 36

__device__ __forceinline__ void bdt_body(const float* __restrict__ in,
                                         const float* __restrict__ base,
                                         const float* __restrict__ Rh,
                                         float* __restrict__ out,
                                         int N, int h, int transp, int roundit) {
    __shared__ float Ms[1024];
    __shared__ float As[256 * BDP];
    const int t = threadIdx.x;
    const int n0 = blockIdx.x * 256;
    const int rows = (N - n0 < 256) ? (N - n0) : 256;
    for (int k = t; k < 1024; k += 256) {
        int j = k >> 5, i = k & 31;
        Ms[k] = transp ? Rh[j * 32 + i] : Rh[i * 32 + j];
    }
    // coalesced stage-in: 8 lanes cover one 128B row segment
#pragma unroll
    for (int it = 0; it < 8; it++) {
        int idx = t + it * 256;
        int row = idx >> 3, c4 = idx & 7;
        if (row < rows) {
            float4 v = *(const float4*)(in + (size_t)(n0 + row) * DD + h * 32 + c4 * 4);
            *(float4*)&As[row * BDP + c4 * 4] = v;
        }
    }
    __syncthreads();
    float ov[32];
    if (t < rows) {
        float iv[32];
#pragma unroll
        for (int k = 0; k < 8; k++) {
            float4 v = *(const float4*)&As[t * BDP + k * 4];
            iv[4 * k] = v.x; iv[4 * k + 1] = v.y; iv[4 * k + 2] = v.z; iv[4 * k + 3] = v.w;
        }
#pragma unroll
        for (int i = 0; i < 32; i++) ov[i] = 0.f;
#pragma unroll
        for (int j = 0; j < 32; j++) {
#pragma unroll
            for (int i4 = 0; i4 < 8; i4++) {
                float4 m = *(const float4*)&Ms[j * 32 + i4 * 4];
                ov[i4 * 4 + 0] += iv[j] * m.x;
                ov[i4 * 4 + 1] += iv[j] * m.y;
                ov[i4 * 4 + 2] += iv[j] * m.z;
                ov[i4 * 4 + 3] += iv[j] * m.w;
            }
        }
    }
    __syncthreads();
    if (t < rows) {
#pragma unroll
        for (int k = 0; k < 8; k++)
            *(float4*)&As[t * BDP + k * 4] = make_float4(ov[4 * k], ov[4 * k + 1],
                                                         ov[4 * k + 2], ov[4 * k + 3]);
    }
    __syncthreads();
    // coalesced stage-out with fused base add + rounding
#pragma unroll
    for (int it = 0; it < 8; it++) {
        int idx = t + it * 256;
        int row = idx >> 3, c4 = idx & 7;
        if (row < rows) {
            float4 v = *(const float4*)&As[row * BDP + c4 * 4];
            size_t go = (size_t)(n0 + row) * DD + h * 32 + c4 * 4;
            if (base) {
                float4 b = *(const float4*)(base + go);
                v.x += b.x; v.y += b.y; v.z += b.z; v.w += b.w;
            }
            if (roundit) {
                v.x = tf32r(v.x); v.y = tf32r(v.y); v.z = tf32r(v.z); v.w = tf32r(v.w);
            }
            *(float4*)(out + go) = v;
        }
    }
}

__global__ void bdtrans_q(const float* __restrict__ in, const float* __restrict__ R,
                          float* __restrict__ out, int N) {
    bdt_body(in, nullptr, R + blockIdx.y * 1024, out, N, blockIdx.y, 0, 0);
}

__global__ void bdtrans_p(const float* __restrict__ in, const float* __restrict__ base,
                          const float* __restrict__ R, float* __restrict__ out, int N) {
    bdt_body(in, base, R + blockIdx.y * 1024, out, N, blockIdx.y, 1, 1);
}

// ---------------- tf32 mma helpers ----------------
#define SLAB_F (128 * 36)
#define GSMEM (4 * SLAB_F * 4)
#define GS3 (8 * SLAB_F * 4)

__device__ __forceinline__ void mma1688(float c[4], const uint32_t a[4], const uint32_t b[2]) {
    asm volatile(
        "mma.sync.aligned.m16n8k8.row.col.f32.tf32.tf32.f32 "
        "{%0,%1,%2,%3}, {%4,%5,%6,%7}, {%8,%9}, {%0,%1,%2,%3};"
        : "+f"(c[0]), "+f"(c[1]), "+f"(c[2]), "+f"(c[3])
        : "r"(a[0]), "r"(a[1]), "r"(a[2]), "r"(a[3]), "r"(b[0]), "r"(b[1]));
}

// ---------------- fused out-GEMM (authors + papers) ----------------
__global__ __launch_bounds__(256) void gemm_out(
    int gaBlocks,
    const float* __restrict__ Aa, const float* __restrict__ Ap,
    const float* __restrict__ Ba, const float* __restrict__ Bp,
    const float* __restrict__ biasa, const float* __restrict__ biasp,
    const float* __restrict__ resida, const float* __restrict__ residp,
    const float* __restrict__ skipv,
    float* __restrict__ Ca, float* __restrict__ Cp, int Ma, int Mp) {
    extern __shared__ float sm[];
    const int tid = threadIdx.x;
    const bool pp = (int)blockIdx.x >= gaBlocks;
    const int m0 = ((int)blockIdx.x - (pp ? gaBlocks : 0)) * 128;
    const int col0 = blockIdx.y * 128;
    const float* A = pp ? Ap : Aa;
    const float* B = pp ? Bp : Ba;
    const float* bias = pp ? biasp : biasa;
    const float* resid = pp ? residp : resida;
    float* C = pp ? Cp : Ca;
    const int M = pp ? Mp : Ma;
    const int nid = pp ? 1 : 0;

    const int w = tid >> 5, ln = tid & 31;
    const int rowb = (w >> 2) * 64, colb = (w & 3) * 32;
    const int lg = ln >> 2, lt = ln & 3;

    float* const Ab[2] = {sm, sm + SLAB_F};
    float* const Bb[2] = {sm + 2 * SLAB_F, sm + 3 * SLAB_F};

    float c[4][4][4];
#pragma unroll
    for (int mi = 0; mi < 4; mi++)
#pragma unroll
        for (int ni = 0; ni < 4; ni++)
#pragma unroll
            for (int r = 0; r < 4; r++) c[mi][ni][r] = 0.f;

    auto load_slab = [&](int s, int b) {
        const int k0 = s * 32;
        float* As = Ab[b];
        float* Bs = Bb[b];
#pragma unroll
        for (int i = 0; i < 4; i++) {
            int idx = tid + i * 256;
            int row = idx >> 3, kg = idx & 7;
            uint32_t da = (uint32_t)__cvta_generic_to_shared(As + row * 36 + kg * 4);
            const float* ga = A + (size_t)(m0 + row) * DD + k0 + kg * 4;
            int sz = ((m0 + row) < M) ? 16 : 0;
            asm volatile("cp.async.cg.shared.global [%0], [%1], 16, %2;\n" ::"r"(da), "l"(ga), "r"(sz));
            uint32_t db = (uint32_t)__cvta_generic_to_shared(Bs + row * 36 + kg * 4);
            const float* gb = B + (size_t)(col0 + row) * DD + k0 + kg * 4;
            asm volatile("cp.async.cg.shared.global [%0], [%1], 16;\n" ::"r"(db), "l"(gb));
        }
        asm volatile("cp.async.commit_group;\n");
    };

    load_slab(0, 0);
    for (int s = 0; s < 8; s++) {
        int b = s & 1;
        if (s < 7) {
            load_slab(s + 1, b ^ 1);
            asm volatile("cp.async.wait_group 1;\n");
        } else {
            asm volatile("cp.async.wait_group 0;\n");
        }
        __syncthreads();
        const float* As = Ab[b];
        const float* Bs = Bb[b];
#pragma unroll
        for (int ks = 0; ks < 4; ks++) {
            const int kk = ks * 8 + lt;
            uint32_t af[4][4], bf[4][2];
#pragma unroll
            for (int mi = 0; mi < 4; mi++) {
                const float* p = As + (rowb + mi * 16 + lg) * 36 + kk;
                af[mi][0] = __float_as_uint(p[0]);
                af[mi][1] = __float_as_uint(p[8 * 36]);
                af[mi][2] = __float_as_uint(p[4]);
                af[mi][3] = __float_as_uint(p[8 * 36 + 4]);
            }
#pragma unroll
            for (int ni = 0; ni < 4; ni++) {
                const float* p = Bs + (colb + ni * 8 + lg) * 36 + kk;
                bf[ni][0] = __float_as_uint(p[0]);
                bf[ni][1] = __float_as_uint(p[4]);
            }
#pragma unroll
            for (int mi = 0; mi < 4; mi++)
#pragma unroll
                for (int ni = 0; ni < 4; ni++) mma1688(c[mi][ni], af[mi], bf[ni]);
        }
        __syncthreads();
    }

    float sv = skipv[nid];
    float alpha = 1.f / (1.f + __expf(-sv));
    float beta = 1.f - alpha;
#pragma unroll
    for (int mi = 0; mi < 4; mi++) {
#pragma unroll
        for (int half = 0; half < 2; half++) {
            int row = m0 + rowb + mi * 16 + lg + half * 8;
            if (row >= M) continue;
#pragma unroll
            for (int ni = 0; ni < 4; ni++) {
                int cc = col0 + colb + ni * 8 + lt * 2;
                float2 o;
                o.x = c[mi][ni][half * 2 + 0] + bias[cc];
                o.y = c[mi][ni][half * 2 + 1] + bias[cc + 1];
                float2 rv = *(const float2*)(resid + (size_t)row * DD + cc);
                o.x = o.x * alpha + rv.x * beta;
                o.y = o.y * alpha + rv.y * beta;
                *(float2*)(C + (size_t)row * DD + cc) = o;
            }
        }
    }
}

// ---------------- fused 3-B projection GEMM; K/V outputs stored fp16 ----------------
__global__ __launch_bounds__(256, 1) void gemm3f(
    int gaBlocks,
    const float* __restrict__ Aa, const float* __restrict__ Ap,
    const float* __restrict__ Ba0, const float* __restrict__ Ba1, const float* __restrict__ Ba2,
    const float* __restrict__ Bp0, const float* __restrict__ Bp1, const float* __restrict__ Bp2,
    const float* __restrict__ ba0, const float* __restrict__ ba1, const float* __restrict__ ba2,
    const float* __restrict__ bp0, const float* __restrict__ bp1, const float* __restrict__ bp2,
    __half* __restrict__ CaK, __half* __restrict__ CaV, float* __restrict__ CaQ,
    __half* __restrict__ CpK, __half* __restrict__ CpV, float* __restrict__ CpQ,
    int Ma, int Mp) {
    extern __shared__ float sm[];
    const int tid = threadIdx.x;
    const bool pp = (int)blockIdx.x >= gaBlocks;
    const int m0 = ((int)blockIdx.x - (pp ? gaBlocks : 0)) * 128;
    const int col0 = blockIdx.y * 128;
    const float* A = pp ? Ap : Aa;
    const int M = pp ? Mp : Ma;
    const float* const Bv[3] = {pp ? Bp0 : Ba0, pp ? Bp1 : Ba1, pp ? Bp2 : Ba2};
    const float* const biv[3] = {pp ? bp0 : ba0, pp ? bp1 : ba1, pp ? bp2 : ba2};
    __half* const Chv[2] = {pp ? CpK : CaK, pp ? CpV : CaV};
    float* const Cq = pp ? CpQ : CaQ;

    const int w = tid >> 5, ln = tid & 31;
    const int rowb = (w >> 2) * 64, colb = (w & 3) * 32;
    const int lg = ln >> 2, lt = ln & 3;

    float c[3][4][4][4];
#pragma unroll
    for (int b = 0; b < 3; b++)
#pragma unroll
        for (int mi = 0; mi < 4; mi++)
#pragma unroll
            for (int ni = 0; ni < 4; ni++)
#pragma unroll
                for (int r = 0; r < 4; r++) c[b][mi][ni][r] = 0.f;

    auto load_slab = [&](int s, int buf) {
        const int k0 = s * 32;
        float* As = sm + buf * SLAB_F;
#pragma unroll
        for (int i = 0; i < 4; i++) {
            int idx = tid + i * 256;
            int row = idx >> 3, kg = idx & 7;
            uint32_t da = (uint32_t)__cvta_generic_to_shared(As + row * 36 + kg * 4);
            const float* ga = A + (size_t)(m0 + row) * DD + k0 + kg * 4;
            int sz = ((m0 + row) < M) ? 16 : 0;
            asm volatile("cp.async.cg.shared.global [%0], [%1], 16, %2;\n" ::"r"(da), "l"(ga), "r"(sz));
        }
#pragma unroll
        for (int b = 0; b < 3; b++) {
            float* Bs = sm + (2 + b * 2 + buf) * SLAB_F;
#pragma unroll
            for (int i = 0; i < 4; i++) {
                int idx = tid + i * 256;
                int row = idx >> 3, kg = idx & 7;
                uint32_t db = (uint32_t)__cvta_generic_to_shared(Bs + row * 36 + kg * 4);
                const float* gb = Bv[b] + (size_t)(col0 + row) * DD + k0 + kg * 4;
                asm volatile("cp.async.cg.shared.global [%0], [%1], 16;\n" ::"r"(db), "l"(gb));
            }
        }
        asm volatile("cp.async.commit_group;\n");
    };

    load_slab(0, 0);
    for (int s = 0; s < 8; s++) {
        int buf = s & 1;
        if (s < 7) {
            load_slab(s + 1, buf ^ 1);
            asm volatile("cp.async.wait_group 1;\n");
        } else {
            asm volatile("cp.async.wait_group 0;\n");
        }
        __syncthreads();
        const float* As = sm + buf * SLAB_F;
#pragma unroll
        for (int ks = 0; ks < 4; ks++) {
            const int kk = ks * 8 + lt;
            uint32_t af[4][4];
#pragma unroll
            for (int mi = 0; mi < 4; mi++) {
                const float* p = As + (rowb + mi * 16 + lg) * 36 + kk;
                af[mi][0] = __float_as_uint(p[0]);
                af[mi][1] = __float_as_uint(p[8 * 36]);
                af[mi][2] = __float_as_uint(p[4]);
                af[mi][3] = __float_as_uint(p[8 * 36 + 4]);
            }
#pragma unroll
            for (int b = 0; b < 3; b++) {
                const float* Bs = sm + (2 + b * 2 + buf) * SLAB_F;
                uint32_t bf[4][2];
#pragma unroll
                for (int ni = 0; ni < 4; ni++) {
                    const float* p = Bs + (colb + ni * 8 + lg) * 36 + kk;
                    bf[ni][0] = __float_as_uint(p[0]);
                    bf[ni][1] = __float_as_uint(p[4]);
                }
#pragma unroll
                for (int mi = 0; mi < 4; mi++)
#pragma unroll
                    for (int ni = 0; ni < 4; ni++) mma1688(c[b][mi][ni], af[mi], bf[ni]);
            }
        }
        __syncthreads();
    }

#pragma unroll
    for (int b = 0; b < 3; b++) {
#pragma unroll
        for (int mi = 0; mi < 4; mi++) {
#pragma unroll
            for (int half = 0; half < 2; half++) {
                int row = m0 + rowb + mi * 16 + lg + half * 8;
                if (row >= M) continue;
#pragma unroll
                for (int ni = 0; ni < 4; ni++) {
                    int cc = col0 + colb + ni * 8 + lt * 2;
                    float ox = c[b][mi][ni][half * 2 + 0] + biv[b][cc];
                    float oy = c[b][mi][ni][half * 2 + 1] + biv[b][cc + 1];
                    if (b < 2) {
                        *(__half2*)(Chv[b] + (size_t)row * DD + cc) = __floats2half2_rn(ox, oy);
                    } else {
                        *(float2*)(Cq + (size_t)row * DD + cc) = make_float2(ox, oy);
                    }
                }
            }
        }
    }
}

// ---------------- CSR build ----------------
__global__ void zero3(int* d0, int* d1, int* d2) {
    int i = blockIdx.x * blockDim.x + threadIdx.x;
    if (i < NP) { d0[i] = 0; d1[i] = 0; }
    if (i < NA) d2[i] = 0;
}

__global__ void hist3(const int* __restrict__ dw, const int* __restrict__ dc,
                      const int* __restrict__ db, int E,
                      int* d0, int* d1, int* d2) {
    int i = blockIdx.x * blockDim.x + threadIdx.x;
    if (i < E) atomicAdd(&d0[dw[i]], 1);
    else if (i < 2 * E) atomicAdd(&d1[dc[i - E]], 1);
    else if (i < 3 * E) atomicAdd(&d2[db[i - 2 * E]], 1);
}

#define BLKE 2048
#define NB0 25
#define NB1 25
#define NB2 10

__device__ __forceinline__ void seg_of(int b, const int** deg, int* base, int* n, int* lb,
                                       const int* d0, const int* d1, const int* d2) {
    if (b < NB0) { *deg = d0; *lb = b; *n = NP; }
    else if (b < NB0 + NB1) { *deg = d1; *lb = b - NB0; *n = NP; }
    else { *deg = d2; *lb = b - NB0 - NB1; *n = NA; }
    *base = *lb * BLKE;
}

__global__ void scanA(const int* __restrict__ d0, const int* __restrict__ d1,
                      const int* __restrict__ d2, int* __restrict__ psum) {
    __shared__ int sh[512];
    const int* deg; int base, n, lb;
    seg_of(blockIdx.x, &deg, &base, &n, &lb, d0, d1, d2);
    int t = threadIdx.x;
    int s = 0;
#pragma unroll
    for (int k = 0; k < 4; k++) {
        int i = base + t * 4 + k;
        if (i < n && t * 4 + k < BLKE) s += deg[i];
    }
    sh[t] = s;
    __syncthreads();
    for (int off = 256; off; off >>= 1) {
        if (t < off) sh[t] += sh[t + off];
        __syncthreads();
    }
    if (t == 0) psum[blockIdx.x] = sh[0];
}

__global__ void scanB(const int* __restrict__ psum, int* __restrict__ pbase) {
    if (threadIdx.x == 0) {
        int run = 0;
        for (int b = 0; b < NB0 + NB1 + NB2; b++) {
            if (b == 0 || b == NB0 || b == NB0 + NB1) run = 0;
            pbase[b] = run;
            run += psum[b];
        }
    }
}

__global__ void scanC(const int* __restrict__ d0, const int* __restrict__ d1,
                      const int* __restrict__ d2, const int* __restrict__ pbase,
                      int* __restrict__ rp0, int* __restrict__ rp1, int* __restrict__ rp2,
                      int* __restrict__ c0, int* __restrict__ c1, int* __restrict__ c2) {
    __shared__ int sh[512];
    const int* deg; int base, n, lb;
    seg_of(blockIdx.x, &deg, &base, &n, &lb, d0, d1, d2);
    int* rp; int* cur;
    if (blockIdx.x < NB0) { rp = rp0; cur = c0; }
    else if (blockIdx.x < NB0 + NB1) { rp = rp1; cur = c1; }
    else { rp = rp2; cur = c2; }
    int t = threadIdx.x;
    int v[4];
    int loc = 0;
#pragma unroll
    for (int k = 0; k < 4; k++) {
        int i = base + t * 4 + k;
        v[k] = (i < n) ? deg[i] : 0;
        loc += v[k];
    }
    sh[t] = loc;
    __syncthreads();
    for (int off = 1; off < 512; off <<= 1) {
        int x = (t >= off) ? sh[t - off] : 0;
        __syncthreads();
        sh[t] += x;
        __syncthreads();
    }
    int pre = (t ? sh[t - 1] : 0) + pbase[blockIdx.x];
#pragma unroll
    for (int k = 0; k < 4; k++) {
        int i = base + t * 4 + k;
        if (i < n) {
            cur[i] = pre;
            pre += v[k];
            rp[i + 1] = pre;
        }
    }
    if (lb == 0 && t == 0) rp[0] = 0;
}

__global__ void scatter3(const int* __restrict__ sw, const int* __restrict__ dw,
                         const int* __restrict__ sc, const int* __restrict__ dc,
                         const int* __restrict__ sb, const int* __restrict__ db, int E,
                         int* c0, int* c1, int* c2,
                         int* col0, int* col1, int* col2) {
    int i = blockIdx.x * blockDim.x + threadIdx.x;
    if (i < E) { int p = atomicAdd(&c0[dw[i]], 1); col0[p] = sw[i]; }
    else if (i < 2 * E) { int j = i - E; int p = atomicAdd(&c1[dc[j]], 1); col1[p] = sc[j]; }
    else if (i < 3 * E) { int j = i - 2 * E; int p = atomicAdd(&c2[db[j]], 1); col2[p] = sb[j]; }
}

// ---------------- aggregation with fp16 K/V gathers ----------------
__device__ __forceinline__ void csr_attend8h(
    int node, int lane, const int* __restrict__ rp, const int* __restrict__ colv,
    const __half* __restrict__ K, const __half* __restrict__ V,
    const float4 qa, const float4 qb, const float prih, float acc[8]) {
    float s = 0.f;
    float a[8];
#pragma unroll
    for (int j = 0; j < 8; j++) a[j] = 0.f;
    const int off = (lane >> 2) * DKH + (lane & 3) * 8;
    const int beg = rp[node], end = rp[node + 1];
    for (int e = beg; e < end; e++) {
        const int src = colv[e];
        uint4 kq = *(const uint4*)(K + (size_t)src * DD + off);
        const __half2* kh = (const __half2*)&kq;
        float2 k0 = __half22float2(kh[0]);
        float2 k1 = __half22float2(kh[1]);
        float2 k2 = __half22float2(kh[2]);
        float2 k3 = __half22float2(kh[3]);
        float p = qa.x * k0.x + qa.y * k0.y + qa.z * k1.x + qa.w * k1.y +
                  qb.x * k2.x + qb.y * k2.y + qb.z * k3.x + qb.w * k3.y;
        p += __shfl_xor_sync(0xffffffffu, p, 1);
        p += __shfl_xor_sync(0xffffffffu, p, 2);
        float wgt = __expf(p * prih);
        uint4 vq = *(const uint4*)(V + (size_t)src * DD + off);
        const __half2* vh = (const __half2*)&vq;
        float2 v0 = __half22float2(vh[0]);
        float2 v1 = __half22float2(vh[1]);
        float2 v2 = __half22float2(vh[2]);
        float2 v3 = __half22float2(vh[3]);
        s += wgt;
        a[0] += wgt * v0.x; a[1] += wgt * v0.y; a[2] += wgt * v1.x; a[3] += wgt * v1.y;
        a[4] += wgt * v2.x; a[5] += wgt * v2.y; a[6] += wgt * v3.x; a[7] += wgt * v3.y;
    }
    if (s > 0.f) {
        float inv = 1.f / s;
#pragma unroll
        for (int j = 0; j < 8; j++) acc[j] += a[j] * inv;
    }
}

__global__ void agg_all(const float* __restrict__ Qp, const float* __restrict__ Qpc,
                        const float* __restrict__ Qa,
                        const __half* __restrict__ K0, const __half* __restrict__ V0,
                        const __half* __restrict__ Kp, const __half* __restrict__ Vp,
                        const int* __restrict__ rp0, const int* __restrict__ col0,
                        const int* __restrict__ rp1, const int* __restrict__ col1,
                        const int* __restrict__ rp2, const int* __restrict__ col2,
                        const float* __restrict__ rel_pri,
                        float* __restrict__ aggw, float* __restrict__ aggc,
                        float* __restrict__ agga) {
    int w = (blockIdx.x * blockDim.x + threadIdx.x) >> 5;
    int lane = threadIdx.x & 31;
    const float sc = 0.17677669529663687f;
    const int h = lane >> 2;
    const int off = h * DKH + (lane & 3) * 8;
    if (w < NP) {
        const size_t qoff = (size_t)w * DD + off;
        {
            float4 qa = *(const float4*)(Qp + qoff);
            float4 qb = *(const float4*)(Qp + qoff + 4);
            float acc[8];
#pragma unroll
            for (int j = 0; j < 8; j++) acc[j] = 0.f;
            csr_attend8h(w, lane, rp0, col0, K0, V0, qa, qb, rel_pri[h] * sc, acc);
            float* o = aggw + qoff;
            *(float4*)o = make_float4(acc[0], acc[1], acc[2], acc[3]);
            *(float4*)(o + 4) = make_float4(acc[4], acc[5], acc[6], acc[7]);
        }
        {
            float4 qa = *(const float4*)(Qpc + qoff);
            float4 qb = *(const float4*)(Qpc + qoff + 4);
            float acc[8];
#pragma unroll
            for (int j = 0; j < 8; j++) acc[j] = 0.f;
            csr_attend8h(w, lane, rp1, col1, Kp, Vp, qa, qb, rel_pri[NH + h] * sc, acc);
            float* o = aggc + qoff;
            *(float4*)o = make_float4(acc[0], acc[1], acc[2], acc[3]);
            *(float4*)(o + 4) = make_float4(acc[4], acc[5], acc[6], acc[7]);
        }
    } else if (w < NP + NA) {
        int n = w - NP;
        const size_t qoff = (size_t)n * DD + off;
        float4 qa = *(const float4*)(Qa + qoff);
        float4 qb = *(const float4*)(Qa + qoff + 4);
        float acc[8];
#pragma unroll
        for (int j = 0; j < 8; j++) acc[j] = 0.f;
        csr_attend8h(n, lane, rp2, col2, Kp, Vp, qa, qb, rel_pri[2 * NH + h] * sc, acc);
        float* o = agga + qoff;
        *(float4*)o = make_float4(tf32r(acc[0]), tf32r(acc[1]), tf32r(acc[2]), tf32r(acc[3]));
        *(float4*)(o + 4) = make_float4(tf32r(acc[4]), tf32r(acc[5]), tf32r(acc[6]), tf32r(acc[7]));
    }
}

// ---------------- host launch ----------------
extern "C" void kernel_launch(void* const* d_in, const int* in_sizes, int n_in,
                              void* d_out, int out_size) {
    const float* h_author = (const float*)d_in[0];
    const float* h_paper  = (const float*)d_in[1];
    const float* k_w  = (const float*)d_in[2];
    const float* k_b  = (const float*)d_in[3];
    const float* q_w  = (const float*)d_in[4];
    const float* q_b  = (const float*)d_in[5];
    const float* v_w  = (const float*)d_in[6];
    const float* v_b  = (const float*)d_in[7];
    const float* a_w  = (const float*)d_in[8];
    const float* a_b  = (const float*)d_in[9];
    const float* rel_att = (const float*)d_in[10];
    const float* rel_msg = (const float*)d_in[11];
    const float* rel_pri = (const float*)d_in[12];
    const float* skipv   = (const float*)d_in[13];
    const int* src_writes = (const int*)d_in[14];
    const int* dst_writes = (const int*)d_in[15];
    const int* src_cites  = (const int*)d_in[16];
    const int* dst_cites  = (const int*)d_in[17];
    const int* src_wb     = (const int*)d_in[18];
    const int* dst_wb     = (const int*)d_in[19];

    int E = in_sizes[14];
    if (E > EMAX) E = EMAX;

    float *Har, *Hpr, *Qa, *Qp, *Qpc;
    __half *K0, *V0, *Kp, *Vp;
    float *aggPw, *aggPc, *aggP, *aggAc, *fW, *fB, *rw;
    int *deg0, *deg1, *deg2, *rp0, *rp1, *rp2, *cur0, *cur1, *cur2, *col0, *col1, *col2;
    int *psum, *pbase;
    cudaGetSymbolAddress((void**)&Har, g_Har);
    cudaGetSymbolAddress((void**)&Hpr, g_Hpr);
    cudaGetSymbolAddress((void**)&K0, g_K0);
    cudaGetSymbolAddress((void**)&V0, g_V0);
    cudaGetSymbolAddress((void**)&Qa, g_Qa);
    cudaGetSymbolAddress((void**)&Kp, g_Kp);
    cudaGetSymbolAddress((void**)&Vp, g_Vp);
    cudaGetSymbolAddress((void**)&Qp, g_Qp);
    cudaGetSymbolAddress((void**)&Qpc, g_Qpc);
    cudaGetSymbolAddress((void**)&aggPw, g_aggPw);
    cudaGetSymbolAddress((void**)&aggPc, g_aggPc);
    cudaGetSymbolAddress((void**)&aggP, g_aggP);
    cudaGetSymbolAddress((void**)&aggAc, g_aggAc);
    cudaGetSymbolAddress((void**)&fW, g_fW);
    cudaGetSymbolAddress((void**)&fB, g_fB);
    cudaGetSymbolAddress((void**)&rw, g_rw);
    cudaGetSymbolAddress((void**)&deg0, g_deg0);
    cudaGetSymbolAddress((void**)&deg1, g_deg1);
    cudaGetSymbolAddress((void**)&deg2, g_deg2);
    cudaGetSymbolAddress((void**)&rp0, g_rp0);
    cudaGetSymbolAddress((void**)&rp1, g_rp1);
    cudaGetSymbolAddress((void**)&rp2, g_rp2);
    cudaGetSymbolAddress((void**)&cur0, g_cur0);
    cudaGetSymbolAddress((void**)&cur1, g_cur1);
    cudaGetSymbolAddress((void**)&cur2, g_cur2);
    cudaGetSymbolAddress((void**)&col0, g_col0);
    cudaGetSymbolAddress((void**)&col1, g_col1);
    cudaGetSymbolAddress((void**)&col2, g_col2);
    cudaGetSymbolAddress((void**)&psum, g_psum);
    cudaGetSymbolAddress((void**)&pbase, g_pbase);

    cudaFuncSetAttribute(gemm_out, cudaFuncAttributeMaxDynamicSharedMemorySize, GSMEM);
    cudaFuncSetAttribute(gemm3f, cudaFuncAttributeMaxDynamicSharedMemorySize, GS3);

    float* kwr1 = rw + 0 * 65536;
    float* vwr1 = rw + 1 * 65536;
    float* qwr1 = rw + 2 * 65536;
    float* awp  = rw + 3 * 65536;   // rounded paper out-weights
    float* fWk0 = fW + 0 * 65536;
    float* fWv0 = fW + 1 * 65536;
    float* fWqa = fW + 2 * 65536;
    float* fWaw = fW + 3 * 65536;   // rmsg2-folded author out-weights
    float* fBk0 = fB + 0 * 256;
    float* fBv0 = fB + 1 * 256;
    float* fBqa = fB + 2 * 256;

    // 1) fused pre-round (6 regions)
    {
        int n0 = NA * DD / 4, n1 = NP * DD / 4, n2 = 65536 / 4, n3 = 65536 / 4,
            n4 = 65536 / 4, n5 = 65536 / 4;
        int total = n0 + n1 + n2 + n3 + n4 + n5;
        roundcopy_all<<<(total + 255) / 256, 256>>>(
            h_author, Har, n0, h_paper, Hpr, n1,
            k_w + 65536, kwr1, n2, v_w + 65536, vwr1, n3,
            q_w + 65536, qwr1, n4, a_w + 65536, awp, n5);
    }

    // 2) fused weight folds (incl. author out-weight fold with rmsg2)
    {
        dim3 g(256, 4);
        fold_all<<<g, 256>>>(k_w, v_w, q_w, a_w, k_b, v_b, q_b, rel_att, rel_msg,
                             fWk0, fWv0, fWqa, fWaw, fBk0, fBv0, fBqa);
    }

    // 3) fused projection GEMM (K/V emitted fp16)
    const int gaB = (NA + 127) / 128, gpB = (NP + 127) / 128;
    {
        dim3 g(gaB + gpB, 2);
        gemm3f<<<g, 256, GS3>>>(gaB, Har, Hpr,
                                fWk0, fWv0, fWqa, kwr1, vwr1, qwr1,
                                fBk0, fBv0, fBqa, k_b + 256, v_b + 256, q_b + 256,
                                K0, V0, Qa, Kp, Vp, Qp, NA, NP);
    }

    // 4) Q transform for cites (coalesced staged)
    {
        dim3 g((NP + 255) / 256, NH);
        bdtrans_q<<<g, 256>>>(Qp, rel_att + 8192, Qpc, NP);
    }

    // 5) CSR builds with wide scan
    zero3<<<(NP + 255) / 256, 256>>>(deg0, deg1, deg2);
    hist3<<<(3 * E + 255) / 256, 256>>>(dst_writes, dst_cites, dst_wb, E, deg0, deg1, deg2);
    scanA<<<NB0 + NB1 + NB2, 512>>>(deg0, deg1, deg2, psum);
    scanB<<<1, 32>>>(psum, pbase);
    scanC<<<NB0 + NB1 + NB2, 512>>>(deg0, deg1, deg2, pbase, rp0, rp1, rp2, cur0, cur1, cur2);
    scatter3<<<(3 * E + 255) / 256, 256>>>(src_writes, dst_writes, src_cites, dst_cites,
                                           src_wb, dst_wb, E, cur0, cur1, cur2, col0, col1, col2);

    // 6) fused attention aggregation (fp16 gathers; author output tf32-rounded)
    agg_all<<<((NP + NA) * 32 + 255) / 256, 256>>>(Qp, Qpc, Qa, K0, V0, Kp, Vp,
                                                   rp0, col0, rp1, col1, rp2, col2,
                                                   rel_pri, aggPw, aggPc, aggAc);

    // 7) paper post-agg transform only (coalesced staged; author folded into weights)
    {
        dim3 g((NP + 255) / 256, NH);
        bdtrans_p<<<g, 256>>>(aggPc, aggPw, rel_msg + 8192, aggP, NP);
    }

    // 8) fused output GEMM (authors consume aggAc with folded weights)
    float* out = (float*)d_out;
    {
        dim3 g(gaB + gpB, 2);
        gemm_out<<<g, 256, GSMEM>>>(gaB, aggAc, aggP, fWaw, awp, a_b, a_b + 256,
                                    h_author, h_paper, skipv, out, out + (size_t)NA * DD,
                                    NA, NP);
    }
}

// round 15
// speedup vs baseline: 1.8201x; 1.2514x over previous
#include <cuda_runtime.h>
#include <cuda_fp16.h>
#include <math.h>
#include <cstdint>

#define NA 20000
#define NP 50000
#define EMAX 300000
#define DD 256
#define NH 8
#define DKH 32

// ---------------- scratch ----------------
__device__ __half g_Har[NA * DD];
__device__ __half g_Hpr[NP * DD];
__device__ __half g_K0[NA * DD];
__device__ __half g_V0[NA * DD];
__device__ float g_Qa[NA * DD];
__device__ __half g_Kp[NP * DD];
__device__ __half g_Vp[NP * DD];
__device__ float g_Qp[NP * DD];
__device__ float g_Qpc[NP * DD];
__device__ float g_aggPw[NP * DD];
__device__ float g_aggPc[NP * DD];
__device__ __half g_aggP[NP * DD];
__device__ __half g_aggAc[NA * DD];
__device__ __half g_fW[4 * DD * DD];
__device__ float g_fB[3 * DD];
__device__ __half g_rw[4 * DD * DD];
__device__ int g_deg0[NP];
__device__ int g_deg1[NP];
__device__ int g_deg2[NA];
__device__ int g_rp0[NP + 1];
__device__ int g_rp1[NP + 1];
__device__ int g_rp2[NA + 1];
__device__ int g_cur0[NP];
__device__ int g_cur1[NP];
__device__ int g_cur2[NA];
__device__ int g_col0[EMAX];
__device__ int g_col1[EMAX];
__device__ int g_col2[EMAX];
__device__ int g_psum[64];
__device__ int g_pbase[64];

__device__ __forceinline__ float tf32r(float v) {
    uint32_t r;
    asm("cvt.rna.tf32.f32 %0, %1;" : "=r"(r) : "f"(v));
    return __uint_as_float(r);
}

// ---------------- fused float->half copy over 6 regions (counts in 8-elt units) ----------------
__global__ void halfcopy_all(
    const float* __restrict__ s0, __half* __restrict__ d0, int n0,
    const float* __restrict__ s1, __half* __restrict__ d1, int n1,
    const float* __restrict__ s2, __half* __restrict__ d2, int n2,
    const float* __restrict__ s3, __half* __restrict__ d3, int n3,
    const float* __restrict__ s4, __half* __restrict__ d4, int n4,
    const float* __restrict__ s5, __half* __restrict__ d5, int n5) {
    int i = blockIdx.x * blockDim.x + threadIdx.x;
    const float* s;
    __half* d;
    if (i < n0) { s = s0; d = d0; }
    else if ((i -= n0) < n1) { s = s1; d = d1; }
    else if ((i -= n1) < n2) { s = s2; d = d2; }
    else if ((i -= n2) < n3) { s = s3; d = d3; }
    else if ((i -= n3) < n4) { s = s4; d = d4; }
    else if ((i -= n4) < n5) { s = s5; d = d5; }
    else return;
    const float4* ip = (const float4*)(s + (size_t)i * 8);
    float4 v0 = ip[0], v1 = ip[1];
    __half2 h0 = __floats2half2_rn(v0.x, v0.y);
    __half2 h1 = __floats2half2_rn(v0.z, v0.w);
    __half2 h2 = __floats2half2_rn(v1.x, v1.y);
    __half2 h3 = __floats2half2_rn(v1.z, v1.w);
    uint4 o;
    o.x = *(uint32_t*)&h0; o.y = *(uint32_t*)&h1; o.z = *(uint32_t*)&h2; o.w = *(uint32_t*)&h3;
    *(uint4*)(d + (size_t)i * 8) = o;
}

// ---------------- fused weight folds (4 in one launch), half outputs ----------------
__global__ void fold_all(const float* __restrict__ k_w, const float* __restrict__ v_w,
                         const float* __restrict__ q_w, const float* __restrict__ a_w,
                         const float* __restrict__ k_b, const float* __restrict__ v_b,
                         const float* __restrict__ q_b,
                         const float* __restrict__ rel_att, const float* __restrict__ rel_msg,
                         __half* __restrict__ fWk0, __half* __restrict__ fWv0,
                         __half* __restrict__ fWqa, __half* __restrict__ fWaw,
                         float* __restrict__ fBk0, float* __restrict__ fBv0,
                         float* __restrict__ fBqa) {
    const int which = blockIdx.y;
    int c = blockIdx.x, d = threadIdx.x;
    int h = c >> 5, x = c & 31;
    if (which == 3) {
        const float* rel = rel_msg + 2 * 8192;
        float s = 0.f;
#pragma unroll
        for (int i = 0; i < 32; i++)
            s += rel[c * 32 + i] * a_w[d * DD + h * 32 + i];
        fWaw[d * DD + c] = __float2half_rn(s);
        return;
    }
    const float *W, *rel, *b;
    __half* Wout;
    float* bout;
    if (which == 0) { W = k_w; rel = rel_att; b = k_b; Wout = fWk0; bout = fBk0; }
    else if (which == 1) { W = v_w; rel = rel_msg; b = v_b; Wout = fWv0; bout = fBv0; }
    else { W = q_w; rel = rel_att + 2 * 8192; b = q_b; Wout = fWqa; bout = fBqa; }
    float s = 0.f;
    if (which < 2) {
#pragma unroll
        for (int i = 0; i < 32; i++)
            s += rel[(h * 32 + i) * 32 + x] * W[(h * 32 + i) * DD + d];
    } else {
#pragma unroll
        for (int j = 0; j < 32; j++)
            s += rel[(h * 32 + x) * 32 + j] * W[(h * 32 + j) * DD + d];
    }
    Wout[c * DD + d] = __float2half_rn(s);
    if (d == 0) {
        float sb = 0.f;
        if (which < 2) {
#pragma unroll
            for (int i = 0; i < 32; i++)
                sb += rel[(h * 32 + i) * 32 + x] * b[h * 32 + i];
        } else {
#pragma unroll
            for (int j = 0; j < 32; j++)
                sb += rel[(h * 32 + x) * 32 + j] * b[h * 32 + j];
        }
        bout[c] = sb;
    }
}

// ---------------- SMEM-staged block-diagonal transforms (pitch 36, fp32 SMEM) ----------------
#define BDP 36

// Qpc (fp32 out, no base, no round)
__global__ void bdtrans_q(const float* __restrict__ in, const float* __restrict__ R,
                          float* __restrict__ out, int N) {
    __shared__ float Ms[1024];
    __shared__ float As[256 * BDP];
    const float* Rh = R + blockIdx.y * 1024;
    const int h = blockIdx.y;
    const int t = threadIdx.x;
    const int n0 = blockIdx.x * 256;
    const int rows = (N - n0 < 256) ? (N - n0) : 256;
    for (int k = t; k < 1024; k += 256) {
        int j = k >> 5, i = k & 31;
        Ms[k] = Rh[i * 32 + j];
    }
#pragma unroll
    for (int it = 0; it < 8; it++) {
        int idx = t + it * 256;
        int row = idx >> 3, c4 = idx & 7;
        if (row < rows) {
            float4 v = *(const float4*)(in + (size_t)(n0 + row) * DD + h * 32 + c4 * 4);
            *(float4*)&As[row * BDP + c4 * 4] = v;
        }
    }
    __syncthreads();
    float ov[32];
    if (t < rows) {
        float iv[32];
#pragma unroll
        for (int k = 0; k < 8; k++) {
            float4 v = *(const float4*)&As[t * BDP + k * 4];
            iv[4 * k] = v.x; iv[4 * k + 1] = v.y; iv[4 * k + 2] = v.z; iv[4 * k + 3] = v.w;
        }
#pragma unroll
        for (int i = 0; i < 32; i++) ov[i] = 0.f;
#pragma unroll
        for (int j = 0; j < 32; j++) {
#pragma unroll
            for (int i4 = 0; i4 < 8; i4++) {
                float4 m = *(const float4*)&Ms[j * 32 + i4 * 4];
                ov[i4 * 4 + 0] += iv[j] * m.x;
                ov[i4 * 4 + 1] += iv[j] * m.y;
                ov[i4 * 4 + 2] += iv[j] * m.z;
                ov[i4 * 4 + 3] += iv[j] * m.w;
            }
        }
    }
    __syncthreads();
    if (t < rows) {
#pragma unroll
        for (int k = 0; k < 8; k++)
            *(float4*)&As[t * BDP + k * 4] = make_float4(ov[4 * k], ov[4 * k + 1],
                                                         ov[4 * k + 2], ov[4 * k + 3]);
    }
    __syncthreads();
#pragma unroll
    for (int it = 0; it < 8; it++) {
        int idx = t + it * 256;
        int row = idx >> 3, c4 = idx & 7;
        if (row < rows)
            *(float4*)(out + (size_t)(n0 + row) * DD + h * 32 + c4 * 4) =
                *(const float4*)&As[row * BDP + c4 * 4];
    }
}

// paper post transform: out = half( T(in) + base )
__global__ void bdtrans_p(const float* __restrict__ in, const float* __restrict__ base,
                          const float* __restrict__ R, __half* __restrict__ out, int N) {
    __shared__ float Ms[1024];
    __shared__ float As[256 * BDP];
    const float* Rh = R + blockIdx.y * 1024;
    const int h = blockIdx.y;
    const int t = threadIdx.x;
    const int n0 = blockIdx.x * 256;
    const int rows = (N - n0 < 256) ? (N - n0) : 256;
    for (int k = t; k < 1024; k += 256) {
        int j = k >> 5, i = k & 31;
        Ms[k] = Rh[j * 32 + i];  // transp
    }
#pragma unroll
    for (int it = 0; it < 8; it++) {
        int idx = t + it * 256;
        int row = idx >> 3, c4 = idx & 7;
        if (row < rows) {
            float4 v = *(const float4*)(in + (size_t)(n0 + row) * DD + h * 32 + c4 * 4);
            *(float4*)&As[row * BDP + c4 * 4] = v;
        }
    }
    __syncthreads();
    float ov[32];
    if (t < rows) {
        float iv[32];
#pragma unroll
        for (int k = 0; k < 8; k++) {
            float4 v = *(const float4*)&As[t * BDP + k * 4];
            iv[4 * k] = v.x; iv[4 * k + 1] = v.y; iv[4 * k + 2] = v.z; iv[4 * k + 3] = v.w;
        }
#pragma unroll
        for (int i = 0; i < 32; i++) ov[i] = 0.f;
#pragma unroll
        for (int j = 0; j < 32; j++) {
#pragma unroll
            for (int i4 = 0; i4 < 8; i4++) {
                float4 m = *(const float4*)&Ms[j * 32 + i4 * 4];
                ov[i4 * 4 + 0] += iv[j] * m.x;
                ov[i4 * 4 + 1] += iv[j] * m.y;
                ov[i4 * 4 + 2] += iv[j] * m.z;
                ov[i4 * 4 + 3] += iv[j] * m.w;
            }
        }
    }
    __syncthreads();
    if (t < rows) {
#pragma unroll
        for (int k = 0; k < 8; k++)
            *(float4*)&As[t * BDP + k * 4] = make_float4(ov[4 * k], ov[4 * k + 1],
                                                         ov[4 * k + 2], ov[4 * k + 3]);
    }
    __syncthreads();
#pragma unroll
    for (int it = 0; it < 8; it++) {
        int idx = t + it * 256;
        int row = idx >> 3, c4 = idx & 7;
        if (row < rows) {
            float4 v = *(const float4*)&As[row * BDP + c4 * 4];
            size_t go = (size_t)(n0 + row) * DD + h * 32 + c4 * 4;
            float4 b = *(const float4*)(base + go);
            __half2 h0 = __floats2half2_rn(v.x + b.x, v.y + b.y);
            __half2 h1 = __floats2half2_rn(v.z + b.z, v.w + b.w);
            uint2 o;
            o.x = *(uint32_t*)&h0; o.y = *(uint32_t*)&h1;
            *(uint2*)(out + go) = o;
        }
    }
}

// ---------------- fp16 mma helpers ----------------
#define SLABH (128 * 40)            // halfs per slab buffer
#define GSO (4 * SLABH * 2)         // out-GEMM dynamic smem bytes
#define GS3H (8 * SLABH * 2)        // proj-GEMM dynamic smem bytes

__device__ __forceinline__ void mmah(float c[4], const uint32_t a[4], const uint32_t b[2]) {
    asm volatile(
        "mma.sync.aligned.m16n8k16.row.col.f32.f16.f16.f32 "
        "{%0,%1,%2,%3}, {%4,%5,%6,%7}, {%8,%9}, {%0,%1,%2,%3};"
        : "+f"(c[0]), "+f"(c[1]), "+f"(c[2]), "+f"(c[3])
        : "r"(a[0]), "r"(a[1]), "r"(a[2]), "r"(a[3]), "r"(b[0]), "r"(b[1]));
}

// ---------------- fused fp16 out-GEMM (authors + papers) ----------------
__global__ __launch_bounds__(256) void gemm_out(
    int gaBlocks,
    const __half* __restrict__ Aa, const __half* __restrict__ Ap,
    const __half* __restrict__ Ba, const __half* __restrict__ Bp,
    const float* __restrict__ biasa, const float* __restrict__ biasp,
    const float* __restrict__ resida, const float* __restrict__ residp,
    const float* __restrict__ skipv,
    float* __restrict__ Ca, float* __restrict__ Cp, int Ma, int Mp) {
    extern __shared__ __half smh[];
    const int tid = threadIdx.x;
    const bool pp = (int)blockIdx.x >= gaBlocks;
    const int m0 = ((int)blockIdx.x - (pp ? gaBlocks : 0)) * 128;
    const int col0 = blockIdx.y * 128;
    const __half* A = pp ? Ap : Aa;
    const __half* B = pp ? Bp : Ba;
    const float* bias = pp ? biasp : biasa;
    const float* resid = pp ? residp : resida;
    float* C = pp ? Cp : Ca;
    const int M = pp ? Mp : Ma;
    const int nid = pp ? 1 : 0;

    const int w = tid >> 5, ln = tid & 31;
    const int rowb = (w >> 2) * 64, colb = (w & 3) * 32;
    const int lg = ln >> 2, lt = ln & 3;

    __half* const Ab[2] = {smh, smh + SLABH};
    __half* const Bb[2] = {smh + 2 * SLABH, smh + 3 * SLABH};

    float c[4][4][4];
#pragma unroll
    for (int mi = 0; mi < 4; mi++)
#pragma unroll
        for (int ni = 0; ni < 4; ni++)
#pragma unroll
            for (int r = 0; r < 4; r++) c[mi][ni][r] = 0.f;

    auto load_slab = [&](int s, int b) {
        const int k0 = s * 32;
        __half* As = Ab[b];
        __half* Bs = Bb[b];
#pragma unroll
        for (int i = 0; i < 2; i++) {
            int idx = tid + i * 256;
            int row = idx >> 2, kg = idx & 3;
            uint32_t da = (uint32_t)__cvta_generic_to_shared(As + row * 40 + kg * 8);
            const __half* ga = A + (size_t)(m0 + row) * DD + k0 + kg * 8;
            int sz = ((m0 + row) < M) ? 16 : 0;
            asm volatile("cp.async.cg.shared.global [%0], [%1], 16, %2;\n" ::"r"(da), "l"(ga), "r"(sz));
            uint32_t db = (uint32_t)__cvta_generic_to_shared(Bs + row * 40 + kg * 8);
            const __half* gb = B + (size_t)(col0 + row) * DD + k0 + kg * 8;
            asm volatile("cp.async.cg.shared.global [%0], [%1], 16;\n" ::"r"(db), "l"(gb));
        }
        asm volatile("cp.async.commit_group;\n");
    };

    load_slab(0, 0);
    for (int s = 0; s < 8; s++) {
        int b = s & 1;
        if (s < 7) {
            load_slab(s + 1, b ^ 1);
            asm volatile("cp.async.wait_group 1;\n");
        } else {
            asm volatile("cp.async.wait_group 0;\n");
        }
        __syncthreads();
        const __half* As = Ab[b];
        const __half* Bs = Bb[b];
#pragma unroll
        for (int ks = 0; ks < 2; ks++) {
            const int kk = ks * 16 + 2 * lt;
            uint32_t af[4][4], bf[4][2];
#pragma unroll
            for (int mi = 0; mi < 4; mi++) {
                const __half* p = As + (rowb + mi * 16 + lg) * 40 + kk;
                af[mi][0] = *(const uint32_t*)p;
                af[mi][1] = *(const uint32_t*)(p + 8 * 40);
                af[mi][2] = *(const uint32_t*)(p + 8);
                af[mi][3] = *(const uint32_t*)(p + 8 * 40 + 8);
            }
#pragma unroll
            for (int ni = 0; ni < 4; ni++) {
                const __half* p = Bs + (colb + ni * 8 + lg) * 40 + kk;
                bf[ni][0] = *(const uint32_t*)p;
                bf[ni][1] = *(const uint32_t*)(p + 8);
            }
#pragma unroll
            for (int mi = 0; mi < 4; mi++)
#pragma unroll
                for (int ni = 0; ni < 4; ni++) mmah(c[mi][ni], af[mi], bf[ni]);
        }
        __syncthreads();
    }

    float sv = skipv[nid];
    float alpha = 1.f / (1.f + __expf(-sv));
    float beta = 1.f - alpha;
#pragma unroll
    for (int mi = 0; mi < 4; mi++) {
#pragma unroll
        for (int half = 0; half < 2; half++) {
            int row = m0 + rowb + mi * 16 + lg + half * 8;
            if (row >= M) continue;
#pragma unroll
            for (int ni = 0; ni < 4; ni++) {
                int cc = col0 + colb + ni * 8 + lt * 2;
                float2 o;
                o.x = c[mi][ni][half * 2 + 0] + bias[cc];
                o.y = c[mi][ni][half * 2 + 1] + bias[cc + 1];
                float2 rv = *(const float2*)(resid + (size_t)row * DD + cc);
                o.x = o.x * alpha + rv.x * beta;
                o.y = o.y * alpha + rv.y * beta;
                *(float2*)(C + (size_t)row * DD + cc) = o;
            }
        }
    }
}

// ---------------- fused fp16 3-B projection GEMM ----------------
__global__ __launch_bounds__(256, 1) void gemm3h(
    int gaBlocks,
    const __half* __restrict__ Aa, const __half* __restrict__ Ap,
    const __half* __restrict__ Ba0, const __half* __restrict__ Ba1, const __half* __restrict__ Ba2,
    const __half* __restrict__ Bp0, const __half* __restrict__ Bp1, const __half* __restrict__ Bp2,
    const float* __restrict__ ba0, const float* __restrict__ ba1, const float* __restrict__ ba2,
    const float* __restrict__ bp0, const float* __restrict__ bp1, const float* __restrict__ bp2,
    __half* __restrict__ CaK, __half* __restrict__ CaV, float* __restrict__ CaQ,
    __half* __restrict__ CpK, __half* __restrict__ CpV, float* __restrict__ CpQ,
    int Ma, int Mp) {
    extern __shared__ __half smh[];
    const int tid = threadIdx.x;
    const bool pp = (int)blockIdx.x >= gaBlocks;
    const int m0 = ((int)blockIdx.x - (pp ? gaBlocks : 0)) * 128;
    const int col0 = blockIdx.y * 128;
    const __half* A = pp ? Ap : Aa;
    const int M = pp ? Mp : Ma;
    const __half* const Bv[3] = {pp ? Bp0 : Ba0, pp ? Bp1 : Ba1, pp ? Bp2 : Ba2};
    const float* const biv[3] = {pp ? bp0 : ba0, pp ? bp1 : ba1, pp ? bp2 : ba2};
    __half* const Chv[2] = {pp ? CpK : CaK, pp ? CpV : CaV};
    float* const Cq = pp ? CpQ : CaQ;

    const int w = tid >> 5, ln = tid & 31;
    const int rowb = (w >> 2) * 64, colb = (w & 3) * 32;
    const int lg = ln >> 2, lt = ln & 3;

    float c[3][4][4][4];
#pragma unroll
    for (int b = 0; b < 3; b++)
#pragma unroll
        for (int mi = 0; mi < 4; mi++)
#pragma unroll
            for (int ni = 0; ni < 4; ni++)
#pragma unroll
                for (int r = 0; r < 4; r++) c[b][mi][ni][r] = 0.f;

    auto load_slab = [&](int s, int buf) {
        const int k0 = s * 32;
        __half* As = smh + buf * SLABH;
#pragma unroll
        for (int i = 0; i < 2; i++) {
            int idx = tid + i * 256;
            int row = idx >> 2, kg = idx & 3;
            uint32_t da = (uint32_t)__cvta_generic_to_shared(As + row * 40 + kg * 8);
            const __half* ga = A + (size_t)(m0 + row) * DD + k0 + kg * 8;
            int sz = ((m0 + row) < M) ? 16 : 0;
            asm volatile("cp.async.cg.shared.global [%0], [%1], 16, %2;\n" ::"r"(da), "l"(ga), "r"(sz));
        }
#pragma unroll
        for (int b = 0; b < 3; b++) {
            __half* Bs = smh + (2 + b * 2 + buf) * SLABH;
#pragma unroll
            for (int i = 0; i < 2; i++) {
                int idx = tid + i * 256;
                int row = idx >> 2, kg = idx & 3;
                uint32_t db = (uint32_t)__cvta_generic_to_shared(Bs + row * 40 + kg * 8);
                const __half* gb = Bv[b] + (size_t)(col0 + row) * DD + k0 + kg * 8;
                asm volatile("cp.async.cg.shared.global [%0], [%1], 16;\n" ::"r"(db), "l"(gb));
            }
        }
        asm volatile("cp.async.commit_group;\n");
    };

    load_slab(0, 0);
    for (int s = 0; s < 8; s++) {
        int buf = s & 1;
        if (s < 7) {
            load_slab(s + 1, buf ^ 1);
            asm volatile("cp.async.wait_group 1;\n");
        } else {
            asm volatile("cp.async.wait_group 0;\n");
        }
        __syncthreads();
        const __half* As = smh + buf * SLABH;
#pragma unroll
        for (int ks = 0; ks < 2; ks++) {
            const int kk = ks * 16 + 2 * lt;
            uint32_t af[4][4];
#pragma unroll
            for (int mi = 0; mi < 4; mi++) {
                const __half* p = As + (rowb + mi * 16 + lg) * 40 + kk;
                af[mi][0] = *(const uint32_t*)p;
                af[mi][1] = *(const uint32_t*)(p + 8 * 40);
                af[mi][2] = *(const uint32_t*)(p + 8);
                af[mi][3] = *(const uint32_t*)(p + 8 * 40 + 8);
            }
#pragma unroll
            for (int b = 0; b < 3; b++) {
                const __half* Bs = smh + (2 + b * 2 + buf) * SLABH;
                uint32_t bf[4][2];
#pragma unroll
                for (int ni = 0; ni < 4; ni++) {
                    const __half* p = Bs + (colb + ni * 8 + lg) * 40 + kk;
                    bf[ni][0] = *(const uint32_t*)p;
                    bf[ni][1] = *(const uint32_t*)(p + 8);
                }
#pragma unroll
                for (int mi = 0; mi < 4; mi++)
#pragma unroll
                    for (int ni = 0; ni < 4; ni++) mmah(c[b][mi][ni], af[mi], bf[ni]);
            }
        }
        __syncthreads();
    }

#pragma unroll
    for (int b = 0; b < 3; b++) {
#pragma unroll
        for (int mi = 0; mi < 4; mi++) {
#pragma unroll
            for (int half = 0; half < 2; half++) {
                int row = m0 + rowb + mi * 16 + lg + half * 8;
                if (row >= M) continue;
#pragma unroll
                for (int ni = 0; ni < 4; ni++) {
                    int cc = col0 + colb + ni * 8 + lt * 2;
                    float ox = c[b][mi][ni][half * 2 + 0] + biv[b][cc];
                    float oy = c[b][mi][ni][half * 2 + 1] + biv[b][cc + 1];
                    if (b < 2) {
                        *(__half2*)(Chv[b] + (size_t)row * DD + cc) = __floats2half2_rn(ox, oy);
                    } else {
                        *(float2*)(Cq + (size_t)row * DD + cc) = make_float2(ox, oy);
                    }
                }
            }
        }
    }
}

// ---------------- CSR build ----------------
__global__ void zero3(int* d0, int* d1, int* d2) {
    int i = blockIdx.x * blockDim.x + threadIdx.x;
    if (i < NP) { d0[i] = 0; d1[i] = 0; }
    if (i < NA) d2[i] = 0;
}

__global__ void hist3(const int* __restrict__ dw, const int* __restrict__ dc,
                      const int* __restrict__ db, int E,
                      int* d0, int* d1, int* d2) {
    int i = blockIdx.x * blockDim.x + threadIdx.x;
    if (i < E) atomicAdd(&d0[dw[i]], 1);
    else if (i < 2 * E) atomicAdd(&d1[dc[i - E]], 1);
    else if (i < 3 * E) atomicAdd(&d2[db[i - 2 * E]], 1);
}

#define BLKE 2048
#define NB0 25
#define NB1 25
#define NB2 10

__device__ __forceinline__ void seg_of(int b, const int** deg, int* base, int* n, int* lb,
                                       const int* d0, const int* d1, const int* d2) {
    if (b < NB0) { *deg = d0; *lb = b; *n = NP; }
    else if (b < NB0 + NB1) { *deg = d1; *lb = b - NB0; *n = NP; }
    else { *deg = d2; *lb = b - NB0 - NB1; *n = NA; }
    *base = *lb * BLKE;
}

__global__ void scanA(const int* __restrict__ d0, const int* __restrict__ d1,
                      const int* __restrict__ d2, int* __restrict__ psum) {
    __shared__ int sh[512];
    const int* deg; int base, n, lb;
    seg_of(blockIdx.x, &deg, &base, &n, &lb, d0, d1, d2);
    int t = threadIdx.x;
    int s = 0;
#pragma unroll
    for (int k = 0; k < 4; k++) {
        int i = base + t * 4 + k;
        if (i < n && t * 4 + k < BLKE) s += deg[i];
    }
    sh[t] = s;
    __syncthreads();
    for (int off = 256; off; off >>= 1) {
        if (t < off) sh[t] += sh[t + off];
        __syncthreads();
    }
    if (t == 0) psum[blockIdx.x] = sh[0];
}

__global__ void scanB(const int* __restrict__ psum, int* __restrict__ pbase) {
    if (threadIdx.x == 0) {
        int run = 0;
        for (int b = 0; b < NB0 + NB1 + NB2; b++) {
            if (b == 0 || b == NB0 || b == NB0 + NB1) run = 0;
            pbase[b] = run;
            run += psum[b];
        }
    }
}

__global__ void scanC(const int* __restrict__ d0, const int* __restrict__ d1,
                      const int* __restrict__ d2, const int* __restrict__ pbase,
                      int* __restrict__ rp0, int* __restrict__ rp1, int* __restrict__ rp2,
                      int* __restrict__ c0, int* __restrict__ c1, int* __restrict__ c2) {
    __shared__ int sh[512];
    const int* deg; int base, n, lb;
    seg_of(blockIdx.x, &deg, &base, &n, &lb, d0, d1, d2);
    int* rp; int* cur;
    if (blockIdx.x < NB0) { rp = rp0; cur = c0; }
    else if (blockIdx.x < NB0 + NB1) { rp = rp1; cur = c1; }
    else { rp = rp2; cur = c2; }
    int t = threadIdx.x;
    int v[4];
    int loc = 0;
#pragma unroll
    for (int k = 0; k < 4; k++) {
        int i = base + t * 4 + k;
        v[k] = (i < n) ? deg[i] : 0;
        loc += v[k];
    }
    sh[t] = loc;
    __syncthreads();
    for (int off = 1; off < 512; off <<= 1) {
        int x = (t >= off) ? sh[t - off] : 0;
        __syncthreads();
        sh[t] += x;
        __syncthreads();
    }
    int pre = (t ? sh[t - 1] : 0) + pbase[blockIdx.x];
#pragma unroll
    for (int k = 0; k < 4; k++) {
        int i = base + t * 4 + k;
        if (i < n) {
            cur[i] = pre;
            pre += v[k];
            rp[i + 1] = pre;
        }
    }
    if (lb == 0 && t == 0) rp[0] = 0;
}

__global__ void scatter3(const int* __restrict__ sw, const int* __restrict__ dw,
                         const int* __restrict__ sc, const int* __restrict__ dc,
                         const int* __restrict__ sb, const int* __restrict__ db, int E,
                         int* c0, int* c1, int* c2,
                         int* col0, int* col1, int* col2) {
    int i = blockIdx.x * blockDim.x + threadIdx.x;
    if (i < E) { int p = atomicAdd(&c0[dw[i]], 1); col0[p] = sw[i]; }
    else if (i < 2 * E) { int j = i - E; int p = atomicAdd(&c1[dc[j]], 1); col1[p] = sc[j]; }
    else if (i < 3 * E) { int j = i - 2 * E; int p = atomicAdd(&c2[db[j]], 1); col2[p] = sb[j]; }
}

// ---------------- aggregation with fp16 K/V gathers ----------------
__device__ __forceinline__ void csr_attend8h(
    int node, int lane, const int* __restrict__ rp, const int* __restrict__ colv,
    const __half* __restrict__ K, const __half* __restrict__ V,
    const float4 qa, const float4 qb, const float prih, float acc[8]) {
    float s = 0.f;
    float a[8];
#pragma unroll
    for (int j = 0; j < 8; j++) a[j] = 0.f;
    const int off = (lane >> 2) * DKH + (lane & 3) * 8;
    const int beg = rp[node], end = rp[node + 1];
    for (int e = beg; e < end; e++) {
        const int src = colv[e];
        uint4 kq = *(const uint4*)(K + (size_t)src * DD + off);
        const __half2* kh = (const __half2*)&kq;
        float2 k0 = __half22float2(kh[0]);
        float2 k1 = __half22float2(kh[1]);
        float2 k2 = __half22float2(kh[2]);
        float2 k3 = __half22float2(kh[3]);
        float p = qa.x * k0.x + qa.y * k0.y + qa.z * k1.x + qa.w * k1.y +
                  qb.x * k2.x + qb.y * k2.y + qb.z * k3.x + qb.w * k3.y;
        p += __shfl_xor_sync(0xffffffffu, p, 1);
        p += __shfl_xor_sync(0xffffffffu, p, 2);
        float wgt = __expf(p * prih);
        uint4 vq = *(const uint4*)(V + (size_t)src * DD + off);
        const __half2* vh = (const __half2*)&vq;
        float2 v0 = __half22float2(vh[0]);
        float2 v1 = __half22float2(vh[1]);
        float2 v2 = __half22float2(vh[2]);
        float2 v3 = __half22float2(vh[3]);
        s += wgt;
        a[0] += wgt * v0.x; a[1] += wgt * v0.y; a[2] += wgt * v1.x; a[3] += wgt * v1.y;
        a[4] += wgt * v2.x; a[5] += wgt * v2.y; a[6] += wgt * v3.x; a[7] += wgt * v3.y;
    }
    if (s > 0.f) {
        float inv = 1.f / s;
#pragma unroll
        for (int j = 0; j < 8; j++) acc[j] += a[j] * inv;
    }
}

__global__ void agg_all(const float* __restrict__ Qp, const float* __restrict__ Qpc,
                        const float* __restrict__ Qa,
                        const __half* __restrict__ K0, const __half* __restrict__ V0,
                        const __half* __restrict__ Kp, const __half* __restrict__ Vp,
                        const int* __restrict__ rp0, const int* __restrict__ col0,
                        const int* __restrict__ rp1, const int* __restrict__ col1,
                        const int* __restrict__ rp2, const int* __restrict__ col2,
                        const float* __restrict__ rel_pri,
                        float* __restrict__ aggw, float* __restrict__ aggc,
                        __half* __restrict__ agga) {
    int w = (blockIdx.x * blockDim.x + threadIdx.x) >> 5;
    int lane = threadIdx.x & 31;
    const float sc = 0.17677669529663687f;
    const int h = lane >> 2;
    const int off = h * DKH + (lane & 3) * 8;
    if (w < NP) {
        const size_t qoff = (size_t)w * DD + off;
        {
            float4 qa = *(const float4*)(Qp + qoff);
            float4 qb = *(const float4*)(Qp + qoff + 4);
            float acc[8];
#pragma unroll
            for (int j = 0; j < 8; j++) acc[j] = 0.f;
            csr_attend8h(w, lane, rp0, col0, K0, V0, qa, qb, rel_pri[h] * sc, acc);
            float* o = aggw + qoff;
            *(float4*)o = make_float4(acc[0], acc[1], acc[2], acc[3]);
            *(float4*)(o + 4) = make_float4(acc[4], acc[5], acc[6], acc[7]);
        }
        {
            float4 qa = *(const float4*)(Qpc + qoff);
            float4 qb = *(const float4*)(Qpc + qoff + 4);
            float acc[8];
#pragma unroll
            for (int j = 0; j < 8; j++) acc[j] = 0.f;
            csr_attend8h(w, lane, rp1, col1, Kp, Vp, qa, qb, rel_pri[NH + h] * sc, acc);
            float* o = aggc + qoff;
            *(float4*)o = make_float4(acc[0], acc[1], acc[2], acc[3]);
            *(float4*)(o + 4) = make_float4(acc[4], acc[5], acc[6], acc[7]);
        }
    } else if (w < NP + NA) {
        int n = w - NP;
        const size_t qoff = (size_t)n * DD + off;
        float4 qa = *(const float4*)(Qa + qoff);
        float4 qb = *(const float4*)(Qa + qoff + 4);
        float acc[8];
#pragma unroll
        for (int j = 0; j < 8; j++) acc[j] = 0.f;
        csr_attend8h(n, lane, rp2, col2, Kp, Vp, qa, qb, rel_pri[2 * NH + h] * sc, acc);
        __half2 h0 = __floats2half2_rn(acc[0], acc[1]);
        __half2 h1 = __floats2half2_rn(acc[2], acc[3]);
        __half2 h2 = __floats2half2_rn(acc[4], acc[5]);
        __half2 h3 = __floats2half2_rn(acc[6], acc[7]);
        uint4 o;
        o.x = *(uint32_t*)&h0; o.y = *(uint32_t*)&h1; o.z = *(uint32_t*)&h2; o.w = *(uint32_t*)&h3;
        *(uint4*)(agga + qoff) = o;
    }
}

// ---------------- host launch ----------------
extern "C" void kernel_launch(void* const* d_in, const int* in_sizes, int n_in,
                              void* d_out, int out_size) {
    const float* h_author = (const float*)d_in[0];
    const float* h_paper  = (const float*)d_in[1];
    const float* k_w  = (const float*)d_in[2];
    const float* k_b  = (const float*)d_in[3];
    const float* q_w  = (const float*)d_in[4];
    const float* q_b  = (const float*)d_in[5];
    const float* v_w  = (const float*)d_in[6];
    const float* v_b  = (const float*)d_in[7];
    const float* a_w  = (const float*)d_in[8];
    const float* a_b  = (const float*)d_in[9];
    const float* rel_att = (const float*)d_in[10];
    const float* rel_msg = (const float*)d_in[11];
    const float* rel_pri = (const float*)d_in[12];
    const float* skipv   = (const float*)d_in[13];
    const int* src_writes = (const int*)d_in[14];
    const int* dst_writes = (const int*)d_in[15];
    const int* src_cites  = (const int*)d_in[16];
    const int* dst_cites  = (const int*)d_in[17];
    const int* src_wb     = (const int*)d_in[18];
    const int* dst_wb     = (const int*)d_in[19];

    int E = in_sizes[14];
    if (E > EMAX) E = EMAX;

    __half *Har, *Hpr, *K0, *V0, *Kp, *Vp, *aggP, *aggAc, *fW, *rw;
    float *Qa, *Qp, *Qpc, *aggPw, *aggPc, *fB;
    int *deg0, *deg1, *deg2, *rp0, *rp1, *rp2, *cur0, *cur1, *cur2, *col0, *col1, *col2;
    int *psum, *pbase;
    cudaGetSymbolAddress((void**)&Har, g_Har);
    cudaGetSymbolAddress((void**)&Hpr, g_Hpr);
    cudaGetSymbolAddress((void**)&K0, g_K0);
    cudaGetSymbolAddress((void**)&V0, g_V0);
    cudaGetSymbolAddress((void**)&Qa, g_Qa);
    cudaGetSymbolAddress((void**)&Kp, g_Kp);
    cudaGetSymbolAddress((void**)&Vp, g_Vp);
    cudaGetSymbolAddress((void**)&Qp, g_Qp);
    cudaGetSymbolAddress((void**)&Qpc, g_Qpc);
    cudaGetSymbolAddress((void**)&aggPw, g_aggPw);
    cudaGetSymbolAddress((void**)&aggPc, g_aggPc);
    cudaGetSymbolAddress((void**)&aggP, g_aggP);
    cudaGetSymbolAddress((void**)&aggAc, g_aggAc);
    cudaGetSymbolAddress((void**)&fW, g_fW);
    cudaGetSymbolAddress((void**)&fB, g_fB);
    cudaGetSymbolAddress((void**)&rw, g_rw);
    cudaGetSymbolAddress((void**)&deg0, g_deg0);
    cudaGetSymbolAddress((void**)&deg1, g_deg1);
    cudaGetSymbolAddress((void**)&deg2, g_deg2);
    cudaGetSymbolAddress((void**)&rp0, g_rp0);
    cudaGetSymbolAddress((void**)&rp1, g_rp1);
    cudaGetSymbolAddress((void**)&rp2, g_rp2);
    cudaGetSymbolAddress((void**)&cur0, g_cur0);
    cudaGetSymbolAddress((void**)&cur1, g_cur1);
    cudaGetSymbolAddress((void**)&cur2, g_cur2);
    cudaGetSymbolAddress((void**)&col0, g_col0);
    cudaGetSymbolAddress((void**)&col1, g_col1);
    cudaGetSymbolAddress((void**)&col2, g_col2);
    cudaGetSymbolAddress((void**)&psum, g_psum);
    cudaGetSymbolAddress((void**)&pbase, g_pbase);

    cudaFuncSetAttribute(gemm_out, cudaFuncAttributeMaxDynamicSharedMemorySize, GSO);
    cudaFuncSetAttribute(gemm3h, cudaFuncAttributeMaxDynamicSharedMemorySize, GS3H);

    __half* kwr1 = rw + 0 * 65536;
    __half* vwr1 = rw + 1 * 65536;
    __half* qwr1 = rw + 2 * 65536;
    __half* awp  = rw + 3 * 65536;
    __half* fWk0 = fW + 0 * 65536;
    __half* fWv0 = fW + 1 * 65536;
    __half* fWqa = fW + 2 * 65536;
    __half* fWaw = fW + 3 * 65536;
    float* fBk0 = fB + 0 * 256;
    float* fBv0 = fB + 1 * 256;
    float* fBqa = fB + 2 * 256;

    // 1) fused float->half conversions (counts in 8-elt units)
    {
        int n0 = NA * DD / 8, n1 = NP * DD / 8, n2 = 65536 / 8, n3 = 65536 / 8,
            n4 = 65536 / 8, n5 = 65536 / 8;
        int total = n0 + n1 + n2 + n3 + n4 + n5;
        halfcopy_all<<<(total + 255) / 256, 256>>>(
            h_author, Har, n0, h_paper, Hpr, n1,
            k_w + 65536, kwr1, n2, v_w + 65536, vwr1, n3,
            q_w + 65536, qwr1, n4, a_w + 65536, awp, n5);
    }

    // 2) fused weight folds
    {
        dim3 g(256, 4);
        fold_all<<<g, 256>>>(k_w, v_w, q_w, a_w, k_b, v_b, q_b, rel_att, rel_msg,
                             fWk0, fWv0, fWqa, fWaw, fBk0, fBv0, fBqa);
    }

    // 3) fused fp16 projection GEMM
    const int gaB = (NA + 127) / 128, gpB = (NP + 127) / 128;
    {
        dim3 g(gaB + gpB, 2);
        gemm3h<<<g, 256, GS3H>>>(gaB, Har, Hpr,
                                 fWk0, fWv0, fWqa, kwr1, vwr1, qwr1,
                                 fBk0, fBv0, fBqa, k_b + 256, v_b + 256, q_b + 256,
                                 K0, V0, Qa, Kp, Vp, Qp, NA, NP);
    }

    // 4) Q transform for cites
    {
        dim3 g((NP + 255) / 256, NH);
        bdtrans_q<<<g, 256>>>(Qp, rel_att + 8192, Qpc, NP);
    }

    // 5) CSR builds
    zero3<<<(NP + 255) / 256, 256>>>(deg0, deg1, deg2);
    hist3<<<(3 * E + 255) / 256, 256>>>(dst_writes, dst_cites, dst_wb, E, deg0, deg1, deg2);
    scanA<<<NB0 + NB1 + NB2, 512>>>(deg0, deg1, deg2, psum);
    scanB<<<1, 32>>>(psum, pbase);
    scanC<<<NB0 + NB1 + NB2, 512>>>(deg0, deg1, deg2, pbase, rp0, rp1, rp2, cur0, cur1, cur2);
    scatter3<<<(3 * E + 255) / 256, 256>>>(src_writes, dst_writes, src_cites, dst_cites,
                                           src_wb, dst_wb, E, cur0, cur1, cur2, col0, col1, col2);

    // 6) fused aggregation (author output stored fp16)
    agg_all<<<((NP + NA) * 32 + 255) / 256, 256>>>(Qp, Qpc, Qa, K0, V0, Kp, Vp,
                                                   rp0, col0, rp1, col1, rp2, col2,
                                                   rel_pri, aggPw, aggPc, aggAc);

    // 7) paper post-agg transform (half output)
    {
        dim3 g((NP + 255) / 256, NH);
        bdtrans_p<<<g, 256>>>(aggPc, aggPw, rel_msg + 8192, aggP, NP);
    }

    // 8) fused fp16 output GEMM
    float* out = (float*)d_out;
    {
        dim3 g(gaB + gpB, 2);
        gemm_out<<<g, 256, GSO>>>(gaB, aggAc, aggP, fWaw, awp, a_b, a_b + 256,
                                  h_author, h_paper, skipv, out, out + (size_t)NA * DD,
                                  NA, NP);
    }
}

// round 16
// speedup vs baseline: 1.9721x; 1.0835x over previous
#include <cuda_runtime.h>
#include <cuda_fp16.h>
#include <math.h>
#include <cstdint>

#define NA 20000
#define NP 50000
#define EMAX 300000
#define DD 256
#define NH 8
#define DKH 32

// ---------------- scratch ----------------
__device__ __half g_Har[NA * DD];
__device__ __half g_Hpr[NP * DD];
__device__ __half g_K0[NA * DD];
__device__ __half g_V0[NA * DD];
__device__ float g_Qa[NA * DD];
__device__ __half g_Kp[NP * DD];
__device__ __half g_Vp[NP * DD];
__device__ float g_Qp[NP * DD];
__device__ float g_Qpc[NP * DD];
__device__ __half g_aggPw[NP * DD];
__device__ __half g_aggPc[NP * DD];
__device__ __half g_aggAc[NA * DD];
__device__ __half g_fW[6 * DD * DD];
__device__ float g_fB[4 * DD];
__device__ __half g_rw[4 * DD * DD];
__device__ int g_deg0[NP];
__device__ int g_deg1[NP];
__device__ int g_deg2[NA];
__device__ int g_rp0[NP + 1];
__device__ int g_rp1[NP + 1];
__device__ int g_rp2[NA + 1];
__device__ int g_cur0[NP];
__device__ int g_cur1[NP];
__device__ int g_cur2[NA];
__device__ int g_col0[EMAX];
__device__ int g_col1[EMAX];
__device__ int g_col2[EMAX];
__device__ int g_psum[64];
__device__ int g_pbase[64];

// ---------------- fused float->half copy over 6 regions (counts in 8-elt units) ----------------
__global__ void halfcopy_all(
    const float* __restrict__ s0, __half* __restrict__ d0, int n0,
    const float* __restrict__ s1, __half* __restrict__ d1, int n1,
    const float* __restrict__ s2, __half* __restrict__ d2, int n2,
    const float* __restrict__ s3, __half* __restrict__ d3, int n3,
    const float* __restrict__ s4, __half* __restrict__ d4, int n4,
    const float* __restrict__ s5, __half* __restrict__ d5, int n5) {
    int i = blockIdx.x * blockDim.x + threadIdx.x;
    const float* s;
    __half* d;
    if (i < n0) { s = s0; d = d0; }
    else if ((i -= n0) < n1) { s = s1; d = d1; }
    else if ((i -= n1) < n2) { s = s2; d = d2; }
    else if ((i -= n2) < n3) { s = s3; d = d3; }
    else if ((i -= n3) < n4) { s = s4; d = d4; }
    else if ((i -= n4) < n5) { s = s5; d = d5; }
    else return;
    const float4* ip = (const float4*)(s + (size_t)i * 8);
    float4 v0 = ip[0], v1 = ip[1];
    __half2 h0 = __floats2half2_rn(v0.x, v0.y);
    __half2 h1 = __floats2half2_rn(v0.z, v0.w);
    __half2 h2 = __floats2half2_rn(v1.x, v1.y);
    __half2 h3 = __floats2half2_rn(v1.z, v1.w);
    uint4 o;
    o.x = *(uint32_t*)&h0; o.y = *(uint32_t*)&h1; o.z = *(uint32_t*)&h2; o.w = *(uint32_t*)&h3;
    *(uint4*)(d + (size_t)i * 8) = o;
}

// ---------------- fused weight folds (6 in one launch), half outputs ----------------
// 0: K-author (ratt0, K-side)  1: V-author (rmsg0, K-side)  2: Q-author (ratt2, Q-side)
// 3: author out fold (rmsg2, a_w0)  4: Q-cites fold (ratt1, qw1)+bias  5: paper out-c fold (rmsg1, a_w1)
__global__ void fold_all(const float* __restrict__ k_w, const float* __restrict__ v_w,
                         const float* __restrict__ q_w, const float* __restrict__ a_w,
                         const float* __restrict__ k_b, const float* __restrict__ v_b,
                         const float* __restrict__ q_b,
                         const float* __restrict__ rel_att, const float* __restrict__ rel_msg,
                         __half* __restrict__ fWk0, __half* __restrict__ fWv0,
                         __half* __restrict__ fWqa, __half* __restrict__ fWaw,
                         __half* __restrict__ fWqc, __half* __restrict__ fWac,
                         float* __restrict__ fBk0, float* __restrict__ fBv0,
                         float* __restrict__ fBqa, float* __restrict__ fBqc) {
    const int which = blockIdx.y;
    int c = blockIdx.x, d = threadIdx.x;
    int h = c >> 5, x = c & 31;
    if (which == 3 || which == 5) {
        const float* rel = (which == 3) ? rel_msg + 2 * 8192 : rel_msg + 8192;
        const float* W = (which == 3) ? a_w : a_w + 65536;
        __half* Wout = (which == 3) ? fWaw : fWac;
        float s = 0.f;
#pragma unroll
        for (int i = 0; i < 32; i++)
            s += rel[c * 32 + i] * W[d * DD + h * 32 + i];
        Wout[d * DD + c] = __float2half_rn(s);
        return;
    }
    const float *W, *rel, *b;
    __half* Wout;
    float* bout;
    if (which == 0) { W = k_w; rel = rel_att; b = k_b; Wout = fWk0; bout = fBk0; }
    else if (which == 1) { W = v_w; rel = rel_msg; b = v_b; Wout = fWv0; bout = fBv0; }
    else if (which == 2) { W = q_w; rel = rel_att + 2 * 8192; b = q_b; Wout = fWqa; bout = fBqa; }
    else { W = q_w + 65536; rel = rel_att + 8192; b = q_b + 256; Wout = fWqc; bout = fBqc; }
    float s = 0.f;
    if (which < 2) {
#pragma unroll
        for (int i = 0; i < 32; i++)
            s += rel[(h * 32 + i) * 32 + x] * W[(h * 32 + i) * DD + d];
    } else {
#pragma unroll
        for (int j = 0; j < 32; j++)
            s += rel[(h * 32 + x) * 32 + j] * W[(h * 32 + j) * DD + d];
    }
    Wout[c * DD + d] = __float2half_rn(s);
    if (d == 0) {
        float sb = 0.f;
        if (which < 2) {
#pragma unroll
            for (int i = 0; i < 32; i++)
                sb += rel[(h * 32 + i) * 32 + x] * b[h * 32 + i];
        } else {
#pragma unroll
            for (int j = 0; j < 32; j++)
                sb += rel[(h * 32 + x) * 32 + j] * b[h * 32 + j];
        }
        bout[c] = sb;
    }
}

// ---------------- fp16 mma helpers ----------------
#define SLABH (128 * 40)
#define GSO (4 * SLABH * 2)
#define GS3H (8 * SLABH * 2)

__device__ __forceinline__ void mmah(float c[4], const uint32_t a[4], const uint32_t b[2]) {
    asm volatile(
        "mma.sync.aligned.m16n8k16.row.col.f32.f16.f16.f32 "
        "{%0,%1,%2,%3}, {%4,%5,%6,%7}, {%8,%9}, {%0,%1,%2,%3};"
        : "+f"(c[0]), "+f"(c[1]), "+f"(c[2]), "+f"(c[3])
        : "r"(a[0]), "r"(a[1]), "r"(a[2]), "r"(a[3]), "r"(b[0]), "r"(b[1]));
}

// ---------------- fused out-GEMM: authors 8 slabs, papers 16 slabs (split-K two sources) ----------------
__global__ __launch_bounds__(256) void gemm_out(
    int gaBlocks,
    const __half* __restrict__ Aa, const __half* __restrict__ Ba,
    const __half* __restrict__ Ap1, const __half* __restrict__ Bp1,
    const __half* __restrict__ Ap2, const __half* __restrict__ Bp2,
    const float* __restrict__ biasa, const float* __restrict__ biasp,
    const float* __restrict__ resida, const float* __restrict__ residp,
    const float* __restrict__ skipv,
    float* __restrict__ Ca, float* __restrict__ Cp, int Ma, int Mp) {
    extern __shared__ __half smh[];
    const int tid = threadIdx.x;
    const bool pp = (int)blockIdx.x >= gaBlocks;
    const int m0 = ((int)blockIdx.x - (pp ? gaBlocks : 0)) * 128;
    const int col0 = blockIdx.y * 128;
    const float* bias = pp ? biasp : biasa;
    const float* resid = pp ? residp : resida;
    float* C = pp ? Cp : Ca;
    const int M = pp ? Mp : Ma;
    const int nid = pp ? 1 : 0;
    const int ns = pp ? 16 : 8;

    const int w = tid >> 5, ln = tid & 31;
    const int rowb = (w >> 2) * 64, colb = (w & 3) * 32;
    const int lg = ln >> 2, lt = ln & 3;

    __half* const Ab[2] = {smh, smh + SLABH};
    __half* const Bb[2] = {smh + 2 * SLABH, smh + 3 * SLABH};

    float c[4][4][4];
#pragma unroll
    for (int mi = 0; mi < 4; mi++)
#pragma unroll
        for (int ni = 0; ni < 4; ni++)
#pragma unroll
            for (int r = 0; r < 4; r++) c[mi][ni][r] = 0.f;

    auto load_slab = [&](int s, int b) {
        const __half* A;
        const __half* B;
        int k0;
        if (!pp) { A = Aa; B = Ba; k0 = s * 32; }
        else if (s < 8) { A = Ap1; B = Bp1; k0 = s * 32; }
        else { A = Ap2; B = Bp2; k0 = (s - 8) * 32; }
        __half* As = Ab[b];
        __half* Bs = Bb[b];
#pragma unroll
        for (int i = 0; i < 2; i++) {
            int idx = tid + i * 256;
            int row = idx >> 2, kg = idx & 3;
            uint32_t da = (uint32_t)__cvta_generic_to_shared(As + row * 40 + kg * 8);
            const __half* ga = A + (size_t)(m0 + row) * DD + k0 + kg * 8;
            int sz = ((m0 + row) < M) ? 16 : 0;
            asm volatile("cp.async.cg.shared.global [%0], [%1], 16, %2;\n" ::"r"(da), "l"(ga), "r"(sz));
            uint32_t db = (uint32_t)__cvta_generic_to_shared(Bs + row * 40 + kg * 8);
            const __half* gb = B + (size_t)(col0 + row) * DD + k0 + kg * 8;
            asm volatile("cp.async.cg.shared.global [%0], [%1], 16;\n" ::"r"(db), "l"(gb));
        }
        asm volatile("cp.async.commit_group;\n");
    };

    load_slab(0, 0);
    for (int s = 0; s < ns; s++) {
        int b = s & 1;
        if (s < ns - 1) {
            load_slab(s + 1, b ^ 1);
            asm volatile("cp.async.wait_group 1;\n");
        } else {
            asm volatile("cp.async.wait_group 0;\n");
        }
        __syncthreads();
        const __half* As = Ab[b];
        const __half* Bs = Bb[b];
#pragma unroll
        for (int ks = 0; ks < 2; ks++) {
            const int kk = ks * 16 + 2 * lt;
            uint32_t af[4][4], bf[4][2];
#pragma unroll
            for (int mi = 0; mi < 4; mi++) {
                const __half* p = As + (rowb + mi * 16 + lg) * 40 + kk;
                af[mi][0] = *(const uint32_t*)p;
                af[mi][1] = *(const uint32_t*)(p + 8 * 40);
                af[mi][2] = *(const uint32_t*)(p + 8);
                af[mi][3] = *(const uint32_t*)(p + 8 * 40 + 8);
            }
#pragma unroll
            for (int ni = 0; ni < 4; ni++) {
                const __half* p = Bs + (colb + ni * 8 + lg) * 40 + kk;
                bf[ni][0] = *(const uint32_t*)p;
                bf[ni][1] = *(const uint32_t*)(p + 8);
            }
#pragma unroll
            for (int mi = 0; mi < 4; mi++)
#pragma unroll
                for (int ni = 0; ni < 4; ni++) mmah(c[mi][ni], af[mi], bf[ni]);
        }
        __syncthreads();
    }

    float sv = skipv[nid];
    float alpha = 1.f / (1.f + __expf(-sv));
    float beta = 1.f - alpha;
#pragma unroll
    for (int mi = 0; mi < 4; mi++) {
#pragma unroll
        for (int half = 0; half < 2; half++) {
            int row = m0 + rowb + mi * 16 + lg + half * 8;
            if (row >= M) continue;
#pragma unroll
            for (int ni = 0; ni < 4; ni++) {
                int cc = col0 + colb + ni * 8 + lt * 2;
                float2 o;
                o.x = c[mi][ni][half * 2 + 0] + bias[cc];
                o.y = c[mi][ni][half * 2 + 1] + bias[cc + 1];
                float2 rv = *(const float2*)(resid + (size_t)row * DD + cc);
                o.x = o.x * alpha + rv.x * beta;
                o.y = o.y * alpha + rv.y * beta;
                *(float2*)(C + (size_t)row * DD + cc) = o;
            }
        }
    }
}

// ---------------- single-B fp16 GEMM with fp32 output + bias (Qpc) ----------------
__global__ __launch_bounds__(256) void gemmq(
    const __half* __restrict__ A, const __half* __restrict__ B,
    const float* __restrict__ bias, float* __restrict__ C, int M) {
    extern __shared__ __half smh[];
    const int tid = threadIdx.x;
    const int m0 = blockIdx.x * 128;
    const int col0 = blockIdx.y * 128;
    const int w = tid >> 5, ln = tid & 31;
    const int rowb = (w >> 2) * 64, colb = (w & 3) * 32;
    const int lg = ln >> 2, lt = ln & 3;

    __half* const Ab[2] = {smh, smh + SLABH};
    __half* const Bb[2] = {smh + 2 * SLABH, smh + 3 * SLABH};

    float c[4][4][4];
#pragma unroll
    for (int mi = 0; mi < 4; mi++)
#pragma unroll
        for (int ni = 0; ni < 4; ni++)
#pragma unroll
            for (int r = 0; r < 4; r++) c[mi][ni][r] = 0.f;

    auto load_slab = [&](int s, int b) {
        const int k0 = s * 32;
        __half* As = Ab[b];
        __half* Bs = Bb[b];
#pragma unroll
        for (int i = 0; i < 2; i++) {
            int idx = tid + i * 256;
            int row = idx >> 2, kg = idx & 3;
            uint32_t da = (uint32_t)__cvta_generic_to_shared(As + row * 40 + kg * 8);
            const __half* ga = A + (size_t)(m0 + row) * DD + k0 + kg * 8;
            int sz = ((m0 + row) < M) ? 16 : 0;
            asm volatile("cp.async.cg.shared.global [%0], [%1], 16, %2;\n" ::"r"(da), "l"(ga), "r"(sz));
            uint32_t db = (uint32_t)__cvta_generic_to_shared(Bs + row * 40 + kg * 8);
            const __half* gb = B + (size_t)(col0 + row) * DD + k0 + kg * 8;
            asm volatile("cp.async.cg.shared.global [%0], [%1], 16;\n" ::"r"(db), "l"(gb));
        }
        asm volatile("cp.async.commit_group;\n");
    };

    load_slab(0, 0);
    for (int s = 0; s < 8; s++) {
        int b = s & 1;
        if (s < 7) {
            load_slab(s + 1, b ^ 1);
            asm volatile("cp.async.wait_group 1;\n");
        } else {
            asm volatile("cp.async.wait_group 0;\n");
        }
        __syncthreads();
        const __half* As = Ab[b];
        const __half* Bs = Bb[b];
#pragma unroll
        for (int ks = 0; ks < 2; ks++) {
            const int kk = ks * 16 + 2 * lt;
            uint32_t af[4][4], bf[4][2];
#pragma unroll
            for (int mi = 0; mi < 4; mi++) {
                const __half* p = As + (rowb + mi * 16 + lg) * 40 + kk;
                af[mi][0] = *(const uint32_t*)p;
                af[mi][1] = *(const uint32_t*)(p + 8 * 40);
                af[mi][2] = *(const uint32_t*)(p + 8);
                af[mi][3] = *(const uint32_t*)(p + 8 * 40 + 8);
            }
#pragma unroll
            for (int ni = 0; ni < 4; ni++) {
                const __half* p = Bs + (colb + ni * 8 + lg) * 40 + kk;
                bf[ni][0] = *(const uint32_t*)p;
                bf[ni][1] = *(const uint32_t*)(p + 8);
            }
#pragma unroll
            for (int mi = 0; mi < 4; mi++)
#pragma unroll
                for (int ni = 0; ni < 4; ni++) mmah(c[mi][ni], af[mi], bf[ni]);
        }
        __syncthreads();
    }

#pragma unroll
    for (int mi = 0; mi < 4; mi++) {
#pragma unroll
        for (int half = 0; half < 2; half++) {
            int row = m0 + rowb + mi * 16 + lg + half * 8;
            if (row >= M) continue;
#pragma unroll
            for (int ni = 0; ni < 4; ni++) {
                int cc = col0 + colb + ni * 8 + lt * 2;
                float2 o;
                o.x = c[mi][ni][half * 2 + 0] + bias[cc];
                o.y = c[mi][ni][half * 2 + 1] + bias[cc + 1];
                *(float2*)(C + (size_t)row * DD + cc) = o;
            }
        }
    }
}

// ---------------- fused fp16 3-B projection GEMM ----------------
__global__ __launch_bounds__(256, 1) void gemm3h(
    int gaBlocks,
    const __half* __restrict__ Aa, const __half* __restrict__ Ap,
    const __half* __restrict__ Ba0, const __half* __restrict__ Ba1, const __half* __restrict__ Ba2,
    const __half* __restrict__ Bp0, const __half* __restrict__ Bp1, const __half* __restrict__ Bp2,
    const float* __restrict__ ba0, const float* __restrict__ ba1, const float* __restrict__ ba2,
    const float* __restrict__ bp0, const float* __restrict__ bp1, const float* __restrict__ bp2,
    __half* __restrict__ CaK, __half* __restrict__ CaV, float* __restrict__ CaQ,
    __half* __restrict__ CpK, __half* __restrict__ CpV, float* __restrict__ CpQ,
    int Ma, int Mp) {
    extern __shared__ __half smh[];
    const int tid = threadIdx.x;
    const bool pp = (int)blockIdx.x >= gaBlocks;
    const int m0 = ((int)blockIdx.x - (pp ? gaBlocks : 0)) * 128;
    const int col0 = blockIdx.y * 128;
    const __half* A = pp ? Ap : Aa;
    const int M = pp ? Mp : Ma;
    const __half* const Bv[3] = {pp ? Bp0 : Ba0, pp ? Bp1 : Ba1, pp ? Bp2 : Ba2};
    const float* const biv[3] = {pp ? bp0 : ba0, pp ? bp1 : ba1, pp ? bp2 : ba2};
    __half* const Chv[2] = {pp ? CpK : CaK, pp ? CpV : CaV};
    float* const Cq = pp ? CpQ : CaQ;

    const int w = tid >> 5, ln = tid & 31;
    const int rowb = (w >> 2) * 64, colb = (w & 3) * 32;
    const int lg = ln >> 2, lt = ln & 3;

    float c[3][4][4][4];
#pragma unroll
    for (int b = 0; b < 3; b++)
#pragma unroll
        for (int mi = 0; mi < 4; mi++)
#pragma unroll
            for (int ni = 0; ni < 4; ni++)
#pragma unroll
                for (int r = 0; r < 4; r++) c[b][mi][ni][r] = 0.f;

    auto load_slab = [&](int s, int buf) {
        const int k0 = s * 32;
        __half* As = smh + buf * SLABH;
#pragma unroll
        for (int i = 0; i < 2; i++) {
            int idx = tid + i * 256;
            int row = idx >> 2, kg = idx & 3;
            uint32_t da = (uint32_t)__cvta_generic_to_shared(As + row * 40 + kg * 8);
            const __half* ga = A + (size_t)(m0 + row) * DD + k0 + kg * 8;
            int sz = ((m0 + row) < M) ? 16 : 0;
            asm volatile("cp.async.cg.shared.global [%0], [%1], 16, %2;\n" ::"r"(da), "l"(ga), "r"(sz));
        }
#pragma unroll
        for (int b = 0; b < 3; b++) {
            __half* Bs = smh + (2 + b * 2 + buf) * SLABH;
#pragma unroll
            for (int i = 0; i < 2; i++) {
                int idx = tid + i * 256;
                int row = idx >> 2, kg = idx & 3;
                uint32_t db = (uint32_t)__cvta_generic_to_shared(Bs + row * 40 + kg * 8);
                const __half* gb = Bv[b] + (size_t)(col0 + row) * DD + k0 + kg * 8;
                asm volatile("cp.async.cg.shared.global [%0], [%1], 16;\n" ::"r"(db), "l"(gb));
            }
        }
        asm volatile("cp.async.commit_group;\n");
    };

    load_slab(0, 0);
    for (int s = 0; s < 8; s++) {
        int buf = s & 1;
        if (s < 7) {
            load_slab(s + 1, buf ^ 1);
            asm volatile("cp.async.wait_group 1;\n");
        } else {
            asm volatile("cp.async.wait_group 0;\n");
        }
        __syncthreads();
        const __half* As = smh + buf * SLABH;
#pragma unroll
        for (int ks = 0; ks < 2; ks++) {
            const int kk = ks * 16 + 2 * lt;
            uint32_t af[4][4];
#pragma unroll
            for (int mi = 0; mi < 4; mi++) {
                const __half* p = As + (rowb + mi * 16 + lg) * 40 + kk;
                af[mi][0] = *(const uint32_t*)p;
                af[mi][1] = *(const uint32_t*)(p + 8 * 40);
                af[mi][2] = *(const uint32_t*)(p + 8);
                af[mi][3] = *(const uint32_t*)(p + 8 * 40 + 8);
            }
#pragma unroll
            for (int b = 0; b < 3; b++) {
                const __half* Bs = smh + (2 + b * 2 + buf) * SLABH;
                uint32_t bf[4][2];
#pragma unroll
                for (int ni = 0; ni < 4; ni++) {
                    const __half* p = Bs + (colb + ni * 8 + lg) * 40 + kk;
                    bf[ni][0] = *(const uint32_t*)p;
                    bf[ni][1] = *(const uint32_t*)(p + 8);
                }
#pragma unroll
                for (int mi = 0; mi < 4; mi++)
#pragma unroll
                    for (int ni = 0; ni < 4; ni++) mmah(c[b][mi][ni], af[mi], bf[ni]);
            }
        }
        __syncthreads();
    }

#pragma unroll
    for (int b = 0; b < 3; b++) {
#pragma unroll
        for (int mi = 0; mi < 4; mi++) {
#pragma unroll
            for (int half = 0; half < 2; half++) {
                int row = m0 + rowb + mi * 16 + lg + half * 8;
                if (row >= M) continue;
#pragma unroll
                for (int ni = 0; ni < 4; ni++) {
                    int cc = col0 + colb + ni * 8 + lt * 2;
                    float ox = c[b][mi][ni][half * 2 + 0] + biv[b][cc];
                    float oy = c[b][mi][ni][half * 2 + 1] + biv[b][cc + 1];
                    if (b < 2) {
                        *(__half2*)(Chv[b] + (size_t)row * DD + cc) = __floats2half2_rn(ox, oy);
                    } else {
                        *(float2*)(Cq + (size_t)row * DD + cc) = make_float2(ox, oy);
                    }
                }
            }
        }
    }
}

// ---------------- CSR build ----------------
__global__ void zero3(int* d0, int* d1, int* d2) {
    int i = blockIdx.x * blockDim.x + threadIdx.x;
    if (i < NP) { d0[i] = 0; d1[i] = 0; }
    if (i < NA) d2[i] = 0;
}

__global__ void hist3(const int* __restrict__ dw, const int* __restrict__ dc,
                      const int* __restrict__ db, int E,
                      int* d0, int* d1, int* d2) {
    int i = blockIdx.x * blockDim.x + threadIdx.x;
    if (i < E) atomicAdd(&d0[dw[i]], 1);
    else if (i < 2 * E) atomicAdd(&d1[dc[i - E]], 1);
    else if (i < 3 * E) atomicAdd(&d2[db[i - 2 * E]], 1);
}

#define BLKE 2048
#define NB0 25
#define NB1 25
#define NB2 10

__device__ __forceinline__ void seg_of(int b, const int** deg, int* base, int* n, int* lb,
                                       const int* d0, const int* d1, const int* d2) {
    if (b < NB0) { *deg = d0; *lb = b; *n = NP; }
    else if (b < NB0 + NB1) { *deg = d1; *lb = b - NB0; *n = NP; }
    else { *deg = d2; *lb = b - NB0 - NB1; *n = NA; }
    *base = *lb * BLKE;
}

__global__ void scanA(const int* __restrict__ d0, const int* __restrict__ d1,
                      const int* __restrict__ d2, int* __restrict__ psum) {
    __shared__ int sh[512];
    const int* deg; int base, n, lb;
    seg_of(blockIdx.x, &deg, &base, &n, &lb, d0, d1, d2);
    int t = threadIdx.x;
    int s = 0;
#pragma unroll
    for (int k = 0; k < 4; k++) {
        int i = base + t * 4 + k;
        if (i < n && t * 4 + k < BLKE) s += deg[i];
    }
    sh[t] = s;
    __syncthreads();
    for (int off = 256; off; off >>= 1) {
        if (t < off) sh[t] += sh[t + off];
        __syncthreads();
    }
    if (t == 0) psum[blockIdx.x] = sh[0];
}

__global__ void scanB(const int* __restrict__ psum, int* __restrict__ pbase) {
    if (threadIdx.x == 0) {
        int run = 0;
        for (int b = 0; b < NB0 + NB1 + NB2; b++) {
            if (b == 0 || b == NB0 || b == NB0 + NB1) run = 0;
            pbase[b] = run;
            run += psum[b];
        }
    }
}

__global__ void scanC(const int* __restrict__ d0, const int* __restrict__ d1,
                      const int* __restrict__ d2, const int* __restrict__ pbase,
                      int* __restrict__ rp0, int* __restrict__ rp1, int* __restrict__ rp2,
                      int* __restrict__ c0, int* __restrict__ c1, int* __restrict__ c2) {
    __shared__ int sh[512];
    const int* deg; int base, n, lb;
    seg_of(blockIdx.x, &deg, &base, &n, &lb, d0, d1, d2);
    int* rp; int* cur;
    if (blockIdx.x < NB0) { rp = rp0; cur = c0; }
    else if (blockIdx.x < NB0 + NB1) { rp = rp1; cur = c1; }
    else { rp = rp2; cur = c2; }
    int t = threadIdx.x;
    int v[4];
    int loc = 0;
#pragma unroll
    for (int k = 0; k < 4; k++) {
        int i = base + t * 4 + k;
        v[k] = (i < n) ? deg[i] : 0;
        loc += v[k];
    }
    sh[t] = loc;
    __syncthreads();
    for (int off = 1; off < 512; off <<= 1) {
        int x = (t >= off) ? sh[t - off] : 0;
        __syncthreads();
        sh[t] += x;
        __syncthreads();
    }
    int pre = (t ? sh[t - 1] : 0) + pbase[blockIdx.x];
#pragma unroll
    for (int k = 0; k < 4; k++) {
        int i = base + t * 4 + k;
        if (i < n) {
            cur[i] = pre;
            pre += v[k];
            rp[i + 1] = pre;
        }
    }
    if (lb == 0 && t == 0) rp[0] = 0;
}

__global__ void scatter3(const int* __restrict__ sw, const int* __restrict__ dw,
                         const int* __restrict__ sc, const int* __restrict__ dc,
                         const int* __restrict__ sb, const int* __restrict__ db, int E,
                         int* c0, int* c1, int* c2,
                         int* col0, int* col1, int* col2) {
    int i = blockIdx.x * blockDim.x + threadIdx.x;
    if (i < E) { int p = atomicAdd(&c0[dw[i]], 1); col0[p] = sw[i]; }
    else if (i < 2 * E) { int j = i - E; int p = atomicAdd(&c1[dc[j]], 1); col1[p] = sc[j]; }
    else if (i < 3 * E) { int j = i - 2 * E; int p = atomicAdd(&c2[db[j]], 1); col2[p] = sb[j]; }
}

// ---------------- aggregation with fp16 K/V gathers; all outputs fp16 ----------------
__device__ __forceinline__ void csr_attend8h(
    int node, int lane, const int* __restrict__ rp, const int* __restrict__ colv,
    const __half* __restrict__ K, const __half* __restrict__ V,
    const float4 qa, const float4 qb, const float prih, float acc[8]) {
    float s = 0.f;
    float a[8];
#pragma unroll
    for (int j = 0; j < 8; j++) a[j] = 0.f;
    const int off = (lane >> 2) * DKH + (lane & 3) * 8;
    const int beg = rp[node], end = rp[node + 1];
    for (int e = beg; e < end; e++) {
        const int src = colv[e];
        uint4 kq = *(const uint4*)(K + (size_t)src * DD + off);
        const __half2* kh = (const __half2*)&kq;
        float2 k0 = __half22float2(kh[0]);
        float2 k1 = __half22float2(kh[1]);
        float2 k2 = __half22float2(kh[2]);
        float2 k3 = __half22float2(kh[3]);
        float p = qa.x * k0.x + qa.y * k0.y + qa.z * k1.x + qa.w * k1.y +
                  qb.x * k2.x + qb.y * k2.y + qb.z * k3.x + qb.w * k3.y;
        p += __shfl_xor_sync(0xffffffffu, p, 1);
        p += __shfl_xor_sync(0xffffffffu, p, 2);
        float wgt = __expf(p * prih);
        uint4 vq = *(const uint4*)(V + (size_t)src * DD + off);
        const __half2* vh = (const __half2*)&vq;
        float2 v0 = __half22float2(vh[0]);
        float2 v1 = __half22float2(vh[1]);
        float2 v2 = __half22float2(vh[2]);
        float2 v3 = __half22float2(vh[3]);
        s += wgt;
        a[0] += wgt * v0.x; a[1] += wgt * v0.y; a[2] += wgt * v1.x; a[3] += wgt * v1.y;
        a[4] += wgt * v2.x; a[5] += wgt * v2.y; a[6] += wgt * v3.x; a[7] += wgt * v3.y;
    }
    if (s > 0.f) {
        float inv = 1.f / s;
#pragma unroll
        for (int j = 0; j < 8; j++) acc[j] += a[j] * inv;
    }
}

__device__ __forceinline__ void store_h8(__half* dst, const float acc[8]) {
    __half2 h0 = __floats2half2_rn(acc[0], acc[1]);
    __half2 h1 = __floats2half2_rn(acc[2], acc[3]);
    __half2 h2 = __floats2half2_rn(acc[4], acc[5]);
    __half2 h3 = __floats2half2_rn(acc[6], acc[7]);
    uint4 o;
    o.x = *(uint32_t*)&h0; o.y = *(uint32_t*)&h1; o.z = *(uint32_t*)&h2; o.w = *(uint32_t*)&h3;
    *(uint4*)dst = o;
}

__global__ void agg_all(const float* __restrict__ Qp, const float* __restrict__ Qpc,
                        const float* __restrict__ Qa,
                        const __half* __restrict__ K0, const __half* __restrict__ V0,
                        const __half* __restrict__ Kp, const __half* __restrict__ Vp,
                        const int* __restrict__ rp0, const int* __restrict__ col0,
                        const int* __restrict__ rp1, const int* __restrict__ col1,
                        const int* __restrict__ rp2, const int* __restrict__ col2,
                        const float* __restrict__ rel_pri,
                        __half* __restrict__ aggw, __half* __restrict__ aggc,
                        __half* __restrict__ agga) {
    int w = (blockIdx.x * blockDim.x + threadIdx.x) >> 5;
    int lane = threadIdx.x & 31;
    const float sc = 0.17677669529663687f;
    const int h = lane >> 2;
    const int off = h * DKH + (lane & 3) * 8;
    if (w < NP) {
        const size_t qoff = (size_t)w * DD + off;
        {
            float4 qa = *(const float4*)(Qp + qoff);
            float4 qb = *(const float4*)(Qp + qoff + 4);
            float acc[8];
#pragma unroll
            for (int j = 0; j < 8; j++) acc[j] = 0.f;
            csr_attend8h(w, lane, rp0, col0, K0, V0, qa, qb, rel_pri[h] * sc, acc);
            store_h8(aggw + qoff, acc);
        }
        {
            float4 qa = *(const float4*)(Qpc + qoff);
            float4 qb = *(const float4*)(Qpc + qoff + 4);
            float acc[8];
#pragma unroll
            for (int j = 0; j < 8; j++) acc[j] = 0.f;
            csr_attend8h(w, lane, rp1, col1, Kp, Vp, qa, qb, rel_pri[NH + h] * sc, acc);
            store_h8(aggc + qoff, acc);
        }
    } else if (w < NP + NA) {
        int n = w - NP;
        const size_t qoff = (size_t)n * DD + off;
        float4 qa = *(const float4*)(Qa + qoff);
        float4 qb = *(const float4*)(Qa + qoff + 4);
        float acc[8];
#pragma unroll
        for (int j = 0; j < 8; j++) acc[j] = 0.f;
        csr_attend8h(n, lane, rp2, col2, Kp, Vp, qa, qb, rel_pri[2 * NH + h] * sc, acc);
        store_h8(agga + qoff, acc);
    }
}

// ---------------- host launch ----------------
extern "C" void kernel_launch(void* const* d_in, const int* in_sizes, int n_in,
                              void* d_out, int out_size) {
    const float* h_author = (const float*)d_in[0];
    const float* h_paper  = (const float*)d_in[1];
    const float* k_w  = (const float*)d_in[2];
    const float* k_b  = (const float*)d_in[3];
    const float* q_w  = (const float*)d_in[4];
    const float* q_b  = (const float*)d_in[5];
    const float* v_w  = (const float*)d_in[6];
    const float* v_b  = (const float*)d_in[7];
    const float* a_w  = (const float*)d_in[8];
    const float* a_b  = (const float*)d_in[9];
    const float* rel_att = (const float*)d_in[10];
    const float* rel_msg = (const float*)d_in[11];
    const float* rel_pri = (const float*)d_in[12];
    const float* skipv   = (const float*)d_in[13];
    const int* src_writes = (const int*)d_in[14];
    const int* dst_writes = (const int*)d_in[15];
    const int* src_cites  = (const int*)d_in[16];
    const int* dst_cites  = (const int*)d_in[17];
    const int* src_wb     = (const int*)d_in[18];
    const int* dst_wb     = (const int*)d_in[19];

    int E = in_sizes[14];
    if (E > EMAX) E = EMAX;

    __half *Har, *Hpr, *K0, *V0, *Kp, *Vp, *aggPw, *aggPc, *aggAc, *fW, *rw;
    float *Qa, *Qp, *Qpc, *fB;
    int *deg0, *deg1, *deg2, *rp0, *rp1, *rp2, *cur0, *cur1, *cur2, *col0, *col1, *col2;
    int *psum, *pbase;
    cudaGetSymbolAddress((void**)&Har, g_Har);
    cudaGetSymbolAddress((void**)&Hpr, g_Hpr);
    cudaGetSymbolAddress((void**)&K0, g_K0);
    cudaGetSymbolAddress((void**)&V0, g_V0);
    cudaGetSymbolAddress((void**)&Qa, g_Qa);
    cudaGetSymbolAddress((void**)&Kp, g_Kp);
    cudaGetSymbolAddress((void**)&Vp, g_Vp);
    cudaGetSymbolAddress((void**)&Qp, g_Qp);
    cudaGetSymbolAddress((void**)&Qpc, g_Qpc);
    cudaGetSymbolAddress((void**)&aggPw, g_aggPw);
    cudaGetSymbolAddress((void**)&aggPc, g_aggPc);
    cudaGetSymbolAddress((void**)&aggAc, g_aggAc);
    cudaGetSymbolAddress((void**)&fW, g_fW);
    cudaGetSymbolAddress((void**)&fB, g_fB);
    cudaGetSymbolAddress((void**)&rw, g_rw);
    cudaGetSymbolAddress((void**)&deg0, g_deg0);
    cudaGetSymbolAddress((void**)&deg1, g_deg1);
    cudaGetSymbolAddress((void**)&deg2, g_deg2);
    cudaGetSymbolAddress((void**)&rp0, g_rp0);
    cudaGetSymbolAddress((void**)&rp1, g_rp1);
    cudaGetSymbolAddress((void**)&rp2, g_rp2);
    cudaGetSymbolAddress((void**)&cur0, g_cur0);
    cudaGetSymbolAddress((void**)&cur1, g_cur1);
    cudaGetSymbolAddress((void**)&cur2, g_cur2);
    cudaGetSymbolAddress((void**)&col0, g_col0);
    cudaGetSymbolAddress((void**)&col1, g_col1);
    cudaGetSymbolAddress((void**)&col2, g_col2);
    cudaGetSymbolAddress((void**)&psum, g_psum);
    cudaGetSymbolAddress((void**)&pbase, g_pbase);

    cudaFuncSetAttribute(gemm_out, cudaFuncAttributeMaxDynamicSharedMemorySize, GSO);
    cudaFuncSetAttribute(gemmq, cudaFuncAttributeMaxDynamicSharedMemorySize, GSO);
    cudaFuncSetAttribute(gemm3h, cudaFuncAttributeMaxDynamicSharedMemorySize, GS3H);

    __half* kwr1 = rw + 0 * 65536;
    __half* vwr1 = rw + 1 * 65536;
    __half* qwr1 = rw + 2 * 65536;
    __half* awp  = rw + 3 * 65536;
    __half* fWk0 = fW + 0 * 65536;
    __half* fWv0 = fW + 1 * 65536;
    __half* fWqa = fW + 2 * 65536;
    __half* fWaw = fW + 3 * 65536;
    __half* fWqc = fW + 4 * 65536;
    __half* fWac = fW + 5 * 65536;
    float* fBk0 = fB + 0 * 256;
    float* fBv0 = fB + 1 * 256;
    float* fBqa = fB + 2 * 256;
    float* fBqc = fB + 3 * 256;

    // 1) fused float->half conversions
    {
        int n0 = NA * DD / 8, n1 = NP * DD / 8, n2 = 65536 / 8, n3 = 65536 / 8,
            n4 = 65536 / 8, n5 = 65536 / 8;
        int total = n0 + n1 + n2 + n3 + n4 + n5;
        halfcopy_all<<<(total + 255) / 256, 256>>>(
            h_author, Har, n0, h_paper, Hpr, n1,
            k_w + 65536, kwr1, n2, v_w + 65536, vwr1, n3,
            q_w + 65536, qwr1, n4, a_w + 65536, awp, n5);
    }

    // 2) fused weight folds (6 variants)
    {
        dim3 g(256, 6);
        fold_all<<<g, 256>>>(k_w, v_w, q_w, a_w, k_b, v_b, q_b, rel_att, rel_msg,
                             fWk0, fWv0, fWqa, fWaw, fWqc, fWac,
                             fBk0, fBv0, fBqa, fBqc);
    }

    // 3) fused fp16 projection GEMM
    const int gaB = (NA + 127) / 128, gpB = (NP + 127) / 128;
    {
        dim3 g(gaB + gpB, 2);
        gemm3h<<<g, 256, GS3H>>>(gaB, Har, Hpr,
                                 fWk0, fWv0, fWqa, kwr1, vwr1, qwr1,
                                 fBk0, fBv0, fBqa, k_b + 256, v_b + 256, q_b + 256,
                                 K0, V0, Qa, Kp, Vp, Qp, NA, NP);
    }

    // 4) Qpc via folded-weight GEMM (replaces bdtrans_q)
    {
        dim3 g(gpB, 2);
        gemmq<<<g, 256, GSO>>>(Hpr, fWqc, fBqc, Qpc, NP);
    }

    // 5) CSR builds
    zero3<<<(NP + 255) / 256, 256>>>(deg0, deg1, deg2);
    hist3<<<(3 * E + 255) / 256, 256>>>(dst_writes, dst_cites, dst_wb, E, deg0, deg1, deg2);
    scanA<<<NB0 + NB1 + NB2, 512>>>(deg0, deg1, deg2, psum);
    scanB<<<1, 32>>>(psum, pbase);
    scanC<<<NB0 + NB1 + NB2, 512>>>(deg0, deg1, deg2, pbase, rp0, rp1, rp2, cur0, cur1, cur2);
    scatter3<<<(3 * E + 255) / 256, 256>>>(src_writes, dst_writes, src_cites, dst_cites,
                                           src_wb, dst_wb, E, cur0, cur1, cur2, col0, col1, col2);

    // 6) fused aggregation (all outputs fp16)
    agg_all<<<((NP + NA) * 32 + 255) / 256, 256>>>(Qp, Qpc, Qa, K0, V0, Kp, Vp,
                                                   rp0, col0, rp1, col1, rp2, col2,
                                                   rel_pri, aggPw, aggPc, aggAc);

    // 7) fused output GEMM: authors 8 slabs; papers 16 slabs (aggPw@awp + aggPc@fWac)
    float* out = (float*)d_out;
    {
        dim3 g(gaB + gpB, 2);
        gemm_out<<<g, 256, GSO>>>(gaB, aggAc, fWaw, aggPw, awp, aggPc, fWac,
                                  a_b, a_b + 256, h_author, h_paper, skipv,
                                  out, out + (size_t)NA * DD, NA, NP);
    }
}